// round 11
// baseline (speedup 1.0000x reference)
#include <cuda_runtime.h>
#include <cuda_bf16.h>
#include <cstdint>
#include <cstddef>

#define N_ 20000
#define E_ 640000
#define MB (1048576ull)

// ---------------- scratch layout ----------------
static const size_t O_CSR  = 0;                // int[2E] 5.12MB
static const size_t O_CNT  = 6*MB;
static const size_t O_OFF  = 7*MB;
static const size_t O_CUR  = 8*MB;
static const size_t O_XB   = 9*MB;             // bf16[20000*512] hi|lo, 20.5MB
static const size_t O_H1   = 30*MB;            // fp32[20000*256] 20.5MB
static const size_t O_S1S  = 51*MB;            // fp32[2*N*8]
static const size_t O_S1D  = 53*MB;
static const size_t O_H1C  = 55*MB;            // fp32[N*128] 10.2MB
static const size_t O_S2S  = 66*MB;
static const size_t O_S2D  = 68*MB;
static const size_t O_WS   = 70*MB;            // fp32[2048]
static const size_t O_WD   = 70*MB + 16384;
static const size_t O_BC   = 70*MB + 32768;
static const size_t O_WT1  = 71*MB;            // bf16[256*512]  [whi|wlo]
static const size_t O_WT2  = 72*MB;            // bf16[64*4096]  [whi|wlo]
static const size_t O_AGGB = 73*MB;            // bf16[20000*4096] hi|lo, 164MB
static const size_t O_SRC  = 73*MB;            // int[2E] temp (dead before AGGB)
static const size_t O_DST  = 79*MB;            // int[2E] temp
static const size_t O_H2P  = 238*MB;           // fp32[4 * N*64] split-K parts
static const size_t SCRATCH_BYTES = 262*MB;

__device__ __align__(1024) unsigned char g_scratch[SCRATCH_BYTES];

__device__ __forceinline__ float eluf(float x) { return x > 0.f ? x : expm1f(x); }
__device__ __forceinline__ float lrelu(float x) { return x > 0.f ? x : 0.2f * x; }

__device__ __forceinline__ void hl_split(float x, uint16_t& h, uint16_t& l) {
    __nv_bfloat16 hb = __float2bfloat16(x);
    h = __bfloat16_as_ushort(hb);
    l = __bfloat16_as_ushort(__float2bfloat16(x - __bfloat162float(hb)));
}

__device__ __forceinline__ void cpa16(uint32_t dst, const void* src, int szbytes) {
    asm volatile("cp.async.cg.shared.global [%0], [%1], 16, %2;"
                 :: "r"(dst), "l"(src), "r"(szbytes));
}

__device__ __forceinline__ void ldsm4(uint32_t* r, uint32_t addr) {
    asm volatile("ldmatrix.sync.aligned.m8n8.x4.shared.b16 {%0,%1,%2,%3}, [%4];"
                 : "=r"(r[0]), "=r"(r[1]), "=r"(r[2]), "=r"(r[3]) : "r"(addr));
}

// packed f32x2 helpers
__device__ __forceinline__ uint64_t pk2(float x, float y) {
    uint64_t r;
    asm("mov.b64 %0, {%1, %2};" : "=l"(r) : "f"(x), "f"(y));
    return r;
}
__device__ __forceinline__ void upk2(uint64_t v, float& x, float& y) {
    asm("mov.b64 {%0, %1}, %2;" : "=f"(x), "=f"(y) : "l"(v));
}
__device__ __forceinline__ uint64_t fma2(uint64_t a, uint64_t b, uint64_t c) {
    uint64_t d;
    asm("fma.rn.f32x2 %0, %1, %2, %3;" : "=l"(d) : "l"(a), "l"(b), "l"(c));
    return d;
}
__device__ __forceinline__ uint64_t add2(uint64_t a, uint64_t b) {
    uint64_t d;
    asm("add.rn.f32x2 %0, %1, %2;" : "=l"(d) : "l"(a), "l"(b));
    return d;
}

// ================= pipelined mma.sync bf16 GEMM (128x64 tiles) =================
template<int HA, int LDA, int LDB>
__global__ void __launch_bounds__(256) k_mmagemm(
    const uint16_t* __restrict__ A, const uint16_t* __restrict__ B,
    float* __restrict__ C, int nrows, int ldc, size_t zstride)
{
    extern __shared__ uint16_t sh[];
    uint16_t* Asm = sh;
    uint16_t* Bsm = sh + 2 * 9216;
    int tid = threadIdx.x;
    int wm = tid >> 5, lane = tid & 31;
    int g = lane >> 2, t4 = lane & 3;
    int rowBase = blockIdx.x * 128;
    int colBase = blockIdx.y * 64;
    int span = (2 * HA) / gridDim.z;
    int itBeg = blockIdx.z * span, itEnd = itBeg + span;
    C += (size_t)blockIdx.z * zstride;

    float c[8][4];
#pragma unroll
    for (int i = 0; i < 8; i++)
#pragma unroll
        for (int j = 0; j < 4; j++) c[i][j] = 0.f;

    uint32_t aBase = (uint32_t)__cvta_generic_to_shared(Asm);
    uint32_t bBase = (uint32_t)__cvta_generic_to_shared(Bsm);

    auto issue = [&](int it, int buf) {
#pragma unroll
        for (int i = 0; i < 4; i++) {
            int s = i * 256 + tid;
            int row = s >> 3, k8 = s & 7;
            int gr = rowBase + row;
            const uint16_t* src = A + (size_t)gr * LDA + it * 64 + k8 * 8;
            cpa16(aBase + (buf * 9216 + row * 72 + k8 * 8) * 2, src, (gr < nrows) ? 16 : 0);
        }
        bool ph1 = it < HA;
        int b0 = ph1 ? it * 64 : (it - HA) * 64;
#pragma unroll
        for (int i = 0; i < 2; i++) {
            int s = i * 256 + tid;
            int row = s >> 3, k8 = s & 7;
            cpa16(bBase + (buf * 9216 + row * 72 + k8 * 8) * 2,
                  B + (size_t)(colBase + row) * LDB + b0 + k8 * 8, 16);
        }
        if (ph1) {
            int b1 = (HA + it) * 64;
#pragma unroll
            for (int i = 0; i < 2; i++) {
                int s = i * 256 + tid;
                int row = s >> 3, k8 = s & 7;
                cpa16(bBase + (buf * 9216 + 4608 + row * 72 + k8 * 8) * 2,
                      B + (size_t)(colBase + row) * LDB + b1 + k8 * 8, 16);
            }
        }
        asm volatile("cp.async.commit_group;" ::: "memory");
    };

    issue(itBeg, 0);
    for (int it = itBeg; it < itEnd; it++) {
        int buf = (it - itBeg) & 1;
        if (it + 1 < itEnd) {
            issue(it + 1, buf ^ 1);
            asm volatile("cp.async.wait_group 1;" ::: "memory");
        } else {
            asm volatile("cp.async.wait_group 0;" ::: "memory");
        }
        __syncthreads();
        bool ph1 = it < HA;
#pragma unroll
        for (int ks = 0; ks < 4; ks++) {
            int k0 = ks * 16;
            uint32_t ar[4];
            {
                int row = wm * 16 + (lane & 15);
                int col = k0 + 8 * (lane >> 4);
                ldsm4(ar, aBase + (buf * 9216 + row * 72 + col) * 2);
            }
#pragma unroll
            for (int bt = 0; bt < 2; bt++) {
                if (bt == 1 && !ph1) break;
                uint32_t br[16];
#pragma unroll
                for (int j = 0; j < 4; j++) {
                    int n = j * 16 + 8 * (lane >> 4) + (lane & 7);
                    int col = k0 + 8 * ((lane >> 3) & 1);
                    ldsm4(br + 4 * j, bBase + (buf * 9216 + bt * 4608 + n * 72 + col) * 2);
                }
#pragma unroll
                for (int nf = 0; nf < 8; nf++) {
                    uint32_t b0 = br[4 * (nf >> 1) + 2 * (nf & 1)];
                    uint32_t b1 = br[4 * (nf >> 1) + 2 * (nf & 1) + 1];
                    asm volatile(
                        "mma.sync.aligned.m16n8k16.row.col.f32.bf16.bf16.f32 "
                        "{%0,%1,%2,%3}, {%4,%5,%6,%7}, {%8,%9}, {%0,%1,%2,%3};"
                        : "+f"(c[nf][0]), "+f"(c[nf][1]), "+f"(c[nf][2]), "+f"(c[nf][3])
                        : "r"(ar[0]), "r"(ar[1]), "r"(ar[2]), "r"(ar[3]), "r"(b0), "r"(b1));
                }
            }
        }
        __syncthreads();
    }
    int r0 = rowBase + wm * 16 + g;
    int r1 = r0 + 8;
#pragma unroll
    for (int nf = 0; nf < 8; nf++) {
        int col = colBase + nf * 8 + 2 * t4;
        if (r0 < nrows) *(float2*)(C + (size_t)r0 * ldc + col) = make_float2(c[nf][0], c[nf][1]);
        if (r1 < nrows) *(float2*)(C + (size_t)r1 * ldc + col) = make_float2(c[nf][2], c[nf][3]);
    }
}

// ================= prep (also zeroes cnt) =================
__global__ void k_prep(const float* __restrict__ W2, const float* __restrict__ a2s,
                       const float* __restrict__ a2d, const float* __restrict__ b2,
                       const float* __restrict__ W1,
                       uint16_t* __restrict__ Wt1, uint16_t* __restrict__ Wt2,
                       float* __restrict__ ws, float* __restrict__ wd, float* __restrict__ bc,
                       int* __restrict__ cnt)
{
    int i = blockIdx.x * blockDim.x + threadIdx.x;
    if (i < 131072) {
        int n = i & 63, k = i >> 6;
        int t = k >> 10, r = k & 1023, h = r >> 7, cc = r & 127;
        float wv = W2[t * 65536 + cc * 512 + h * 64 + n] * 0.0625f;
        uint16_t hh, ll; hl_split(wv, hh, ll);
        uint16_t* p = Wt2 + (size_t)n * 4096 + k;
        p[0] = hh; p[2048] = ll;
    } else if (i < 196608) {
        int j = i - 131072;
        int np = j & 255, k = j >> 8;
        int t = np >> 7, n = np & 127;
        float wv = W1[t * 32768 + k * 128 + n];
        uint16_t hh, ll; hl_split(wv, hh, ll);
        uint16_t* p = Wt1 + (size_t)np * 512 + k;
        p[0] = hh; p[256] = ll;
    } else if (i < 198656) {
        int j = i - 196608;
        int t = j >> 10, r = j & 1023, h = r >> 7, cc = r & 127;
        const float* wrow = W2 + t * 65536 + cc * 512 + h * 64;
        const float* av = a2s + t * 512 + h * 64;
        float acc = 0.f;
        for (int o = 0; o < 64; o++) acc += wrow[o] * av[o];
        ws[j] = acc;
    } else if (i < 200704) {
        int j = i - 198656;
        int t = j >> 10, r = j & 1023, h = r >> 7, cc = r & 127;
        const float* wrow = W2 + t * 65536 + cc * 512 + h * 64;
        const float* av = a2d + t * 512 + h * 64;
        float acc = 0.f;
        for (int o = 0; o < 64; o++) acc += wrow[o] * av[o];
        wd[j] = acc;
    } else if (i < 200768) {
        int o = i - 200704;
        bc[o] = 0.5f * (b2[o] + b2[64 + o]);
    } else if (i < 240768) {
        cnt[i - 200768] = 0;
    }
}

// ================= graph preprocessing =================
__global__ void k_cvt(const void* pa, const void* pb, int* src, int* dst, int* cnt) {
    int t = blockIdx.y;
    const void* p = t ? pb : pa;
    unsigned ov = ((const unsigned*)p)[1 + 2 * (threadIdx.x & 31)];
    int is64 = __all_sync(0xffffffffu, ov == 0u);
    int i = blockIdx.x * blockDim.x + threadIdx.x;
    if (i >= E_) return;
    int s, d;
    if (is64) {
        const long long* q = (const long long*)p;
        s = (int)q[i]; d = (int)q[E_ + i];
    } else {
        const int* q = (const int*)p;
        s = q[i]; d = q[E_ + i];
    }
    src[t * E_ + i] = s;
    dst[t * E_ + i] = d;
    atomicAdd(&cnt[t * N_ + d], 1);
}

__global__ void k_cvtx(const float* __restrict__ x, uint16_t* __restrict__ xb) {
    int i = blockIdx.x * blockDim.x + threadIdx.x;
    if (i >= N_ * 64) return;
    int row = i >> 6, k4 = (i & 63) << 2;
    float4 v = ((const float4*)x)[i];
    uint16_t h0, l0, h1, l1, h2, l2, h3, l3;
    hl_split(v.x, h0, l0); hl_split(v.y, h1, l1);
    hl_split(v.z, h2, l2); hl_split(v.w, h3, l3);
    uint2 hi, lo;
    hi.x = (uint32_t)h0 | ((uint32_t)h1 << 16);
    hi.y = (uint32_t)h2 | ((uint32_t)h3 << 16);
    lo.x = (uint32_t)l0 | ((uint32_t)l1 << 16);
    lo.y = (uint32_t)l2 | ((uint32_t)l3 << 16);
    *(uint2*)(xb + (size_t)row * 512 + k4) = hi;
    *(uint2*)(xb + (size_t)row * 512 + 256 + k4) = lo;
}

__global__ void k_scan(const int* __restrict__ cnt, int* __restrict__ offs, int* __restrict__ cur)
{
    int t = blockIdx.x;
    const int4* c4 = (const int4*)(cnt + t * N_);
    int4* o4 = (int4*)(offs + t * N_);
    int4* q4 = (int4*)(cur + t * N_);
    __shared__ int wsum[32];
    __shared__ int sbase;
    int tid = threadIdx.x, lane = tid & 31, w = tid >> 5;
    if (tid == 0) sbase = 0;
    __syncthreads();
    const int N4 = N_ / 4;
    for (int i0 = 0; i0 < N4; i0 += 1024) {
        int i = i0 + tid;
        int4 c = make_int4(0, 0, 0, 0);
        if (i < N4) c = c4[i];
        int s = c.x + c.y + c.z + c.w;
        int x = s;
#pragma unroll
        for (int ofs = 1; ofs < 32; ofs <<= 1) {
            int y = __shfl_up_sync(0xffffffffu, x, ofs);
            if (lane >= ofs) x += y;
        }
        if (lane == 31) wsum[w] = x;
        __syncthreads();
        if (w == 0) {
            int v = wsum[lane];
#pragma unroll
            for (int ofs = 1; ofs < 32; ofs <<= 1) {
                int y = __shfl_up_sync(0xffffffffu, v, ofs);
                if (lane >= ofs) v += y;
            }
            wsum[lane] = v;
        }
        __syncthreads();
        int excl = sbase + (w ? wsum[w - 1] : 0) + x - s;
        if (i < N4) {
            int4 r;
            r.x = excl; r.y = excl + c.x; r.z = r.y + c.y; r.w = r.z + c.z;
            o4[i] = r; q4[i] = r;
        }
        __syncthreads();
        if (tid == 0) sbase += wsum[31];
        __syncthreads();
    }
}

__global__ void k_scatter(const int* __restrict__ src, const int* __restrict__ dst,
                          int* __restrict__ cur, int* __restrict__ csr)
{
    int i = blockIdx.x * blockDim.x + threadIdx.x;
    if (i >= 2 * E_) return;
    int t = (i >= E_) ? 1 : 0;
    int e = i - t * E_;
    int s = src[t * E_ + e], d = dst[t * E_ + e];
    int pos = atomicAdd(&cur[t * N_ + d], 1);
    csr[(size_t)t * E_ + pos] = s;
}

// ---------------- layer-1 scores ----------------
__global__ void k_scores1(const float* __restrict__ h1,
                          const float* __restrict__ a_src, const float* __restrict__ a_dst,
                          float* __restrict__ ss, float* __restrict__ sd)
{
    int node = blockIdx.x * 8 + (threadIdx.x >> 5);
    int lane = threadIdx.x & 31;
    int t = blockIdx.y;
    if (node >= N_) return;
    const float* hr = h1 + (size_t)node * 256 + t * 128;
    float4 v = *(const float4*)(hr + lane * 4);
    float4 w = *(const float4*)(a_src + t * 128 + lane * 4);
    float4 u = *(const float4*)(a_dst + t * 128 + lane * 4);
    float ps = v.x * w.x + v.y * w.y + v.z * w.z + v.w * w.w;
    float pd = v.x * u.x + v.y * u.y + v.z * u.z + v.w * u.w;
    ps += __shfl_xor_sync(0xffffffffu, ps, 1);
    ps += __shfl_xor_sync(0xffffffffu, ps, 2);
    pd += __shfl_xor_sync(0xffffffffu, pd, 1);
    pd += __shfl_xor_sync(0xffffffffu, pd, 2);
    if ((lane & 3) == 0) {
        ss[t * N_ * 8 + node * 8 + (lane >> 2)] = ps;
        sd[t * N_ * 8 + node * 8 + (lane >> 2)] = pd;
    }
}

// ---------------- layer-1 GAT: warp per (dst, type, half), fused scores2 ----------------
// Block = 8 warps = 2 dst nodes x 2 types x 2 edge-halves. N_ even -> no guards.
__global__ void __launch_bounds__(256) k_gat1(
    const int* __restrict__ offs, const int* __restrict__ cnt, const int* __restrict__ csr,
    const float* __restrict__ s1s, const float* __restrict__ s1d,
    const float* __restrict__ h1, const float* __restrict__ b1,
    float* __restrict__ h1c,
    const float* __restrict__ ws, const float* __restrict__ wd,
    float* __restrict__ s2s, float* __restrict__ s2d)
{
    __shared__ float sa[8][256];
    __shared__ float4 pacc[8][32];
    __shared__ float pz[8][32];
    int w = threadIdx.x >> 5, lane = threadIdx.x & 31;
    int d = blockIdx.x * 2 + (w >> 2);
    int sub = w & 3, t = sub >> 1, hf = sub & 1;
    int hd = lane >> 2;
    float4 acc = make_float4(0.f, 0.f, 0.f, 0.f);
    float zp = 0.f;
    {
        int beg = offs[t * N_ + d], n = cnt[t * N_ + d];
        int nh = n >> 1;
        int lo = hf ? nh : 0, hiE = hf ? n : nh;
        const float* ss = s1s + (size_t)t * N_ * 8;
        const float4* sdp = (const float4*)(s1d + ((size_t)t * N_ + d) * 8);
        float4 sd0 = sdp[0], sd1 = sdp[1];
        float sdv[8] = {sd0.x, sd0.y, sd0.z, sd0.w, sd1.x, sd1.y, sd1.z, sd1.w};
        const int* cs = csr + (size_t)t * E_ + beg;
        for (int c0 = lo; c0 < hiE; c0 += 32) {
            int m = hiE - c0; if (m > 32) m = 32;
            int sL = 0;
            if (lane < m) {
                sL = cs[c0 + lane];
                float4 a0 = *(const float4*)(ss + (size_t)sL * 8);
                float4 a1 = *(const float4*)(ss + (size_t)sL * 8 + 4);
                float4 e0, e1;
                e0.x = __expf(lrelu(a0.x + sdv[0]));
                e0.y = __expf(lrelu(a0.y + sdv[1]));
                e0.z = __expf(lrelu(a0.z + sdv[2]));
                e0.w = __expf(lrelu(a0.w + sdv[3]));
                e1.x = __expf(lrelu(a1.x + sdv[4]));
                e1.y = __expf(lrelu(a1.y + sdv[5]));
                e1.z = __expf(lrelu(a1.z + sdv[6]));
                e1.w = __expf(lrelu(a1.w + sdv[7]));
                *(float4*)&sa[w][lane * 8] = e0;
                *(float4*)&sa[w][lane * 8 + 4] = e1;
            }
            __syncwarp();
#pragma unroll
            for (int j = 0; j < 32; j++) {
                if (j < m) {
                    int sj = __shfl_sync(0xffffffffu, sL, j);
                    float a = sa[w][j * 8 + hd];
                    zp += a;
                    float4 v = *(const float4*)(h1 + (size_t)sj * 256 + t * 128 + lane * 4);
                    acc.x = fmaf(a, v.x, acc.x);
                    acc.y = fmaf(a, v.y, acc.y);
                    acc.z = fmaf(a, v.z, acc.z);
                    acc.w = fmaf(a, v.w, acc.w);
                }
            }
            __syncwarp();
        }
    }
    pacc[w][lane] = acc;
    pz[w][lane] = zp;
    __syncthreads();
    if (sub == 0) {
        float4 a00 = pacc[w][lane],     a01 = pacc[w + 1][lane];
        float4 a10 = pacc[w + 2][lane], a11 = pacc[w + 3][lane];
        float z0 = pz[w][lane] + pz[w + 1][lane];
        float z1 = pz[w + 2][lane] + pz[w + 3][lane];
        float i0 = (z0 > 0.f) ? 1.f / z0 : 0.f;
        float i1 = (z1 > 0.f) ? 1.f / z1 : 0.f;
        float4 bb0 = *(const float4*)(b1 + lane * 4);
        float4 bb1 = *(const float4*)(b1 + 128 + lane * 4);
        float4 r;
        r.x = eluf(0.5f * ((a00.x + a01.x) * i0 + (a10.x + a11.x) * i1 + bb0.x + bb1.x));
        r.y = eluf(0.5f * ((a00.y + a01.y) * i0 + (a10.y + a11.y) * i1 + bb0.y + bb1.y));
        r.z = eluf(0.5f * ((a00.z + a01.z) * i0 + (a10.z + a11.z) * i1 + bb0.z + bb1.z));
        r.w = eluf(0.5f * ((a00.w + a01.w) * i0 + (a10.w + a11.w) * i1 + bb0.w + bb1.w));
        *(float4*)(h1c + (size_t)d * 128 + lane * 4) = r;
        // fused layer-2 scores
#pragma unroll
        for (int c = 0; c < 16; c++) {
            float4 wv = *(const float4*)(ws + c * 128 + lane * 4);
            float p = r.x * wv.x + r.y * wv.y + r.z * wv.z + r.w * wv.w;
            p += __shfl_xor_sync(0xffffffffu, p, 16);
            p += __shfl_xor_sync(0xffffffffu, p, 8);
            p += __shfl_xor_sync(0xffffffffu, p, 4);
            p += __shfl_xor_sync(0xffffffffu, p, 2);
            p += __shfl_xor_sync(0xffffffffu, p, 1);
            float4 uv = *(const float4*)(wd + c * 128 + lane * 4);
            float q = r.x * uv.x + r.y * uv.y + r.z * uv.z + r.w * uv.w;
            q += __shfl_xor_sync(0xffffffffu, q, 16);
            q += __shfl_xor_sync(0xffffffffu, q, 8);
            q += __shfl_xor_sync(0xffffffffu, q, 4);
            q += __shfl_xor_sync(0xffffffffu, q, 2);
            q += __shfl_xor_sync(0xffffffffu, q, 1);
            if (lane == 0) {
                s2s[(c >> 3) * N_ * 8 + d * 8 + (c & 7)] = p;
                s2d[(c >> 3) * N_ * 8 + d * 8 + (c & 7)] = q;
            }
        }
    }
}

// ---------------- layer-2 aggregate: warp per (dst, type, half), packed f32x2 ----------------
__global__ void __launch_bounds__(256) k_gat2(
    const int* __restrict__ offs, const int* __restrict__ cnt, const int* __restrict__ csr,
    const float* __restrict__ s2s, const float* __restrict__ s2d,
    const float* __restrict__ h1c, uint16_t* __restrict__ aggb)
{
    __shared__ float sa[8][256];
    __shared__ uint64_t pacc[4][32][16];
    __shared__ uint64_t pz[4][4];
    int w = threadIdx.x >> 5, lane = threadIdx.x & 31;
    int d = blockIdx.x * 2 + (w >> 2);
    int sub = w & 3, t = sub >> 1, hf = sub & 1;
    uint64_t z2[4];
#pragma unroll
    for (int k = 0; k < 4; k++) z2[k] = pk2(0.f, 0.f);
    uint64_t acc2[4][4];
#pragma unroll
    for (int cc = 0; cc < 4; cc++)
#pragma unroll
        for (int hp = 0; hp < 4; hp++) acc2[cc][hp] = pk2(0.f, 0.f);
    {
        int beg = offs[t * N_ + d], n = cnt[t * N_ + d];
        int nh = n >> 1;
        int lo = hf ? nh : 0, hiE = hf ? n : nh;
        const float* ss = s2s + (size_t)t * N_ * 8;
        const float4* sdp = (const float4*)(s2d + ((size_t)t * N_ + d) * 8);
        float4 sd0 = sdp[0], sd1 = sdp[1];
        float sdv[8] = {sd0.x, sd0.y, sd0.z, sd0.w, sd1.x, sd1.y, sd1.z, sd1.w};
        const int* cs = csr + (size_t)t * E_ + beg;
        for (int c0 = lo; c0 < hiE; c0 += 32) {
            int m = hiE - c0; if (m > 32) m = 32;
            int sL = 0;
            if (lane < m) {
                sL = cs[c0 + lane];
                float4 a0 = *(const float4*)(ss + (size_t)sL * 8);
                float4 a1 = *(const float4*)(ss + (size_t)sL * 8 + 4);
                float4 e0, e1;
                e0.x = __expf(lrelu(a0.x + sdv[0]));
                e0.y = __expf(lrelu(a0.y + sdv[1]));
                e0.z = __expf(lrelu(a0.z + sdv[2]));
                e0.w = __expf(lrelu(a0.w + sdv[3]));
                e1.x = __expf(lrelu(a1.x + sdv[4]));
                e1.y = __expf(lrelu(a1.y + sdv[5]));
                e1.z = __expf(lrelu(a1.z + sdv[6]));
                e1.w = __expf(lrelu(a1.w + sdv[7]));
                *(float4*)&sa[w][lane * 8] = e0;
                *(float4*)&sa[w][lane * 8 + 4] = e1;
            }
            __syncwarp();
#pragma unroll
            for (int j = 0; j < 32; j++) {
                if (j < m) {
                    int sj = __shfl_sync(0xffffffffu, sL, j);
                    uint64_t a01 = *(const uint64_t*)&sa[w][j * 8];
                    uint64_t a23 = *(const uint64_t*)&sa[w][j * 8 + 2];
                    uint64_t a45 = *(const uint64_t*)&sa[w][j * 8 + 4];
                    uint64_t a67 = *(const uint64_t*)&sa[w][j * 8 + 6];
                    z2[0] = add2(z2[0], a01);
                    z2[1] = add2(z2[1], a23);
                    z2[2] = add2(z2[2], a45);
                    z2[3] = add2(z2[3], a67);
                    float4 v = *(const float4*)(h1c + (size_t)sj * 128 + lane * 4);
                    uint64_t vb[4];
                    vb[0] = pk2(v.x, v.x); vb[1] = pk2(v.y, v.y);
                    vb[2] = pk2(v.z, v.z); vb[3] = pk2(v.w, v.w);
#pragma unroll
                    for (int cc = 0; cc < 4; cc++) {
                        acc2[cc][0] = fma2(a01, vb[cc], acc2[cc][0]);
                        acc2[cc][1] = fma2(a23, vb[cc], acc2[cc][1]);
                        acc2[cc][2] = fma2(a45, vb[cc], acc2[cc][2]);
                        acc2[cc][3] = fma2(a67, vb[cc], acc2[cc][3]);
                    }
                }
            }
            __syncwarp();
        }
    }
    if (hf) {
        int slot = w >> 1;
#pragma unroll
        for (int cc = 0; cc < 4; cc++)
#pragma unroll
            for (int hp = 0; hp < 4; hp++)
                pacc[slot][lane][cc * 4 + hp] = acc2[cc][hp];
        if (lane == 0) {
#pragma unroll
            for (int k = 0; k < 4; k++) pz[slot][k] = z2[k];
        }
    }
    __syncthreads();
    if (!hf) {
        int slot = w >> 1;
#pragma unroll
        for (int cc = 0; cc < 4; cc++)
#pragma unroll
            for (int hp = 0; hp < 4; hp++)
                acc2[cc][hp] = add2(acc2[cc][hp], pacc[slot][lane][cc * 4 + hp]);
#pragma unroll
        for (int k = 0; k < 4; k++) z2[k] = add2(z2[k], pz[slot][k]);
        float z8[8];
#pragma unroll
        for (int hp = 0; hp < 4; hp++) upk2(z2[hp], z8[2 * hp], z8[2 * hp + 1]);
#pragma unroll
        for (int h = 0; h < 8; h++) {
            float inv = (z8[h] > 0.f) ? 1.f / z8[h] : 0.f;
            float ax, ay, az, aw, dummy;
            int hp = h >> 1;
            if ((h & 1) == 0) {
                upk2(acc2[0][hp], ax, dummy);
                upk2(acc2[1][hp], ay, dummy);
                upk2(acc2[2][hp], az, dummy);
                upk2(acc2[3][hp], aw, dummy);
            } else {
                upk2(acc2[0][hp], dummy, ax);
                upk2(acc2[1][hp], dummy, ay);
                upk2(acc2[2][hp], dummy, az);
                upk2(acc2[3][hp], dummy, aw);
            }
            ax *= inv; ay *= inv; az *= inv; aw *= inv;
            uint16_t h0, l0, h1v, l1, h2, l2, h3, l3;
            hl_split(ax, h0, l0); hl_split(ay, h1v, l1);
            hl_split(az, h2, l2); hl_split(aw, h3, l3);
            uint2 hi, lo;
            hi.x = (uint32_t)h0 | ((uint32_t)h1v << 16);
            hi.y = (uint32_t)h2 | ((uint32_t)h3 << 16);
            lo.x = (uint32_t)l0 | ((uint32_t)l1 << 16);
            lo.y = (uint32_t)l2 | ((uint32_t)l3 << 16);
            int k = t * 1024 + h * 128 + lane * 4;
            *(uint2*)(aggb + (size_t)d * 4096 + k) = hi;
            *(uint2*)(aggb + (size_t)d * 4096 + 2048 + k) = lo;
        }
    }
}

// ---------------- classifier ----------------
__global__ void k_classifier(const float* __restrict__ h, const float* __restrict__ bc,
                             const float* __restrict__ Wc1, const float* __restrict__ bc1,
                             const float* __restrict__ Wc2, const float* __restrict__ bc2,
                             float* __restrict__ out)
{
    int wid = (blockIdx.x * blockDim.x + threadIdx.x) >> 5;
    int lane = threadIdx.x & 31;
    if (wid >= N_) return;
    const float* hr0 = h + (size_t)wid * 64;
    const float* hr1 = hr0 + (size_t)N_ * 64;
    const float* hr2 = hr1 + (size_t)N_ * 64;
    const float* hr3 = hr2 + (size_t)N_ * 64;
    float acc = bc1[lane];
#pragma unroll
    for (int c = 0; c < 64; c++) {
        float hv = eluf(__ldg(hr0 + c) + __ldg(hr1 + c) + __ldg(hr2 + c) + __ldg(hr3 + c)
                        + __ldg(bc + c));
        acc = fmaf(hv, Wc1[c * 32 + lane], acc);
    }
    acc = fmaxf(acc, 0.f);
    float p0 = acc * Wc2[lane * 2];
    float p1 = acc * Wc2[lane * 2 + 1];
#pragma unroll
    for (int o = 16; o >= 1; o >>= 1) {
        p0 += __shfl_xor_sync(0xffffffffu, p0, o);
        p1 += __shfl_xor_sync(0xffffffffu, p1, o);
    }
    if (lane == 0) {
        out[wid * 2 + 0] = p0 + bc2[0];
        out[wid * 2 + 1] = p1 + bc2[1];
    }
}

// ---------------- launch ----------------
extern "C" void kernel_launch(void* const* d_in, const int* in_sizes, int n_in,
                              void* d_out, int out_size)
{
    const float* x    = (const float*)d_in[0];
    const void*  eia  = d_in[1];
    const void*  eib  = d_in[2];
    const float* W1   = (const float*)d_in[3];
    const float* a1s  = (const float*)d_in[4];
    const float* a1d  = (const float*)d_in[5];
    const float* b1   = (const float*)d_in[6];
    const float* W2   = (const float*)d_in[7];
    const float* a2s  = (const float*)d_in[8];
    const float* a2d  = (const float*)d_in[9];
    const float* b2   = (const float*)d_in[10];
    const float* Wc1  = (const float*)d_in[11];
    const float* bc1  = (const float*)d_in[12];
    const float* Wc2  = (const float*)d_in[13];
    const float* bc2  = (const float*)d_in[14];
    float* out = (float*)d_out;

    void* basev = nullptr;
    cudaGetSymbolAddress(&basev, g_scratch);
    unsigned char* base = (unsigned char*)basev;

    int*      p_csr  = (int*)(base + O_CSR);
    int*      p_cnt  = (int*)(base + O_CNT);
    int*      p_off  = (int*)(base + O_OFF);
    int*      p_cur  = (int*)(base + O_CUR);
    uint16_t* p_xb   = (uint16_t*)(base + O_XB);
    float*    p_h1   = (float*)(base + O_H1);
    float*    p_s1s  = (float*)(base + O_S1S);
    float*    p_s1d  = (float*)(base + O_S1D);
    float*    p_h1c  = (float*)(base + O_H1C);
    float*    p_s2s  = (float*)(base + O_S2S);
    float*    p_s2d  = (float*)(base + O_S2D);
    float*    p_ws   = (float*)(base + O_WS);
    float*    p_wd   = (float*)(base + O_WD);
    float*    p_bc   = (float*)(base + O_BC);
    uint16_t* p_wt1  = (uint16_t*)(base + O_WT1);
    uint16_t* p_wt2  = (uint16_t*)(base + O_WT2);
    uint16_t* p_aggb = (uint16_t*)(base + O_AGGB);
    int*      p_src  = (int*)(base + O_SRC);
    int*      p_dst  = (int*)(base + O_DST);
    float*    p_h2p  = (float*)(base + O_H2P);

    cudaFuncSetAttribute(k_mmagemm<4, 512, 512>,
                         cudaFuncAttributeMaxDynamicSharedMemorySize, 73728);
    cudaFuncSetAttribute(k_mmagemm<32, 4096, 4096>,
                         cudaFuncAttributeMaxDynamicSharedMemorySize, 73728);

    // 1-3: prep (zeros cnt), cvt (+histogram), cvtx
    k_prep<<<(240768 + 255) / 256, 256>>>(W2, a2s, a2d, b2, W1, p_wt1, p_wt2,
                                          p_ws, p_wd, p_bc, p_cnt);
    k_cvt<<<dim3((E_ + 255) / 256, 2), 256>>>(eia, eib, p_src, p_dst, p_cnt);
    k_cvtx<<<(N_ * 64 + 255) / 256, 256>>>(x, p_xb);

    // 4: layer-1 GEMM
    k_mmagemm<4, 512, 512><<<dim3(157, 4, 1), 256, 73728>>>(p_xb, p_wt1, p_h1, N_, 256, 0);

    // 5-6: finish CSR
    k_scan<<<2, 1024>>>(p_cnt, p_off, p_cur);
    k_scatter<<<(2 * E_ + 255) / 256, 256>>>(p_src, p_dst, p_cur, p_csr);

    // 7-9: scores -> gat1 (h1c + layer-2 scores) -> gat2   (2 nodes per block)
    k_scores1<<<dim3((N_ + 7) / 8, 2), 256>>>(p_h1, a1s, a1d, p_s1s, p_s1d);
    k_gat1<<<N_ / 2, 256>>>(p_off, p_cnt, p_csr, p_s1s, p_s1d, p_h1, b1,
                            p_h1c, p_ws, p_wd, p_s2s, p_s2d);
    k_gat2<<<N_ / 2, 256>>>(p_off, p_cnt, p_csr, p_s2s, p_s2d, p_h1c, p_aggb);

    // 10: layer-2 GEMM, split-K=4
    k_mmagemm<32, 4096, 4096><<<dim3(157, 1, 4), 256, 73728>>>(
        p_aggb, p_wt2, p_h2p, N_, 64, (size_t)N_ * 64);

    // 11: classifier
    k_classifier<<<(N_ * 32 + 255) / 256, 256>>>(p_h2p, p_bc, Wc1, bc1, Wc2, bc2, out);
}

// round 12
// speedup vs baseline: 1.1207x; 1.1207x over previous
#include <cuda_runtime.h>
#include <cuda_bf16.h>
#include <cstdint>
#include <cstddef>

#define N_ 20000
#define E_ 640000
#define MB (1048576ull)

// ---------------- scratch layout ----------------
static const size_t O_CSR  = 0;                // int[2E] 5.12MB
static const size_t O_CNT  = 6*MB;
static const size_t O_OFF  = 7*MB;
static const size_t O_CUR  = 8*MB;
static const size_t O_XB   = 9*MB;             // bf16[20000*512] hi|lo, 20.5MB
static const size_t O_H1   = 30*MB;            // fp32[20000*256] 20.5MB
static const size_t O_S1S  = 51*MB;            // fp32[2*N*8]
static const size_t O_S1D  = 53*MB;
static const size_t O_H1C  = 55*MB;            // fp32[N*128] 10.2MB
static const size_t O_S2S  = 66*MB;
static const size_t O_S2D  = 68*MB;
static const size_t O_WS   = 70*MB;            // fp32[2048]
static const size_t O_WD   = 70*MB + 16384;
static const size_t O_BC   = 70*MB + 32768;
static const size_t O_WT1  = 71*MB;            // bf16[256*512]  [whi|wlo]
static const size_t O_WT2  = 72*MB;            // bf16[64*4096]  [whi|wlo]
static const size_t O_AGGB = 73*MB;            // bf16[20000*4096] hi|lo, 164MB
static const size_t O_H2P  = 238*MB;           // fp32[8 * N*64] split-K parts, 41MB
static const size_t SCRATCH_BYTES = 280*MB;

__device__ __align__(1024) unsigned char g_scratch[SCRATCH_BYTES];

__device__ __forceinline__ float eluf(float x) { return x > 0.f ? x : expm1f(x); }
__device__ __forceinline__ float lrelu(float x) { return x > 0.f ? x : 0.2f * x; }

__device__ __forceinline__ void hl_split(float x, uint16_t& h, uint16_t& l) {
    __nv_bfloat16 hb = __float2bfloat16(x);
    h = __bfloat16_as_ushort(hb);
    l = __bfloat16_as_ushort(__float2bfloat16(x - __bfloat162float(hb)));
}

__device__ __forceinline__ void cpa16(uint32_t dst, const void* src, int szbytes) {
    asm volatile("cp.async.cg.shared.global [%0], [%1], 16, %2;"
                 :: "r"(dst), "l"(src), "r"(szbytes));
}

__device__ __forceinline__ void ldsm4(uint32_t* r, uint32_t addr) {
    asm volatile("ldmatrix.sync.aligned.m8n8.x4.shared.b16 {%0,%1,%2,%3}, [%4];"
                 : "=r"(r[0]), "=r"(r[1]), "=r"(r[2]), "=r"(r[3]) : "r"(addr));
}

// packed f32x2 helpers
__device__ __forceinline__ uint64_t pk2(float x, float y) {
    uint64_t r;
    asm("mov.b64 %0, {%1, %2};" : "=l"(r) : "f"(x), "f"(y));
    return r;
}
__device__ __forceinline__ void upk2(uint64_t v, float& x, float& y) {
    asm("mov.b64 {%0, %1}, %2;" : "=f"(x), "=f"(y) : "l"(v));
}
__device__ __forceinline__ uint64_t fma2(uint64_t a, uint64_t b, uint64_t c) {
    uint64_t d;
    asm("fma.rn.f32x2 %0, %1, %2, %3;" : "=l"(d) : "l"(a), "l"(b), "l"(c));
    return d;
}
__device__ __forceinline__ uint64_t add2(uint64_t a, uint64_t b) {
    uint64_t d;
    asm("add.rn.f32x2 %0, %1, %2;" : "=l"(d) : "l"(a), "l"(b));
    return d;
}

// ================= pipelined mma.sync bf16 GEMM (128x64 tiles) =================
template<int HA, int LDA, int LDB>
__global__ void __launch_bounds__(256) k_mmagemm(
    const uint16_t* __restrict__ A, const uint16_t* __restrict__ B,
    float* __restrict__ C, int nrows, int ldc, size_t zstride)
{
    extern __shared__ uint16_t sh[];
    uint16_t* Asm = sh;
    uint16_t* Bsm = sh + 2 * 9216;
    int tid = threadIdx.x;
    int wm = tid >> 5, lane = tid & 31;
    int g = lane >> 2, t4 = lane & 3;
    int rowBase = blockIdx.x * 128;
    int colBase = blockIdx.y * 64;
    int span = (2 * HA) / gridDim.z;
    int itBeg = blockIdx.z * span, itEnd = itBeg + span;
    C += (size_t)blockIdx.z * zstride;

    float c[8][4];
#pragma unroll
    for (int i = 0; i < 8; i++)
#pragma unroll
        for (int j = 0; j < 4; j++) c[i][j] = 0.f;

    uint32_t aBase = (uint32_t)__cvta_generic_to_shared(Asm);
    uint32_t bBase = (uint32_t)__cvta_generic_to_shared(Bsm);

    auto issue = [&](int it, int buf) {
#pragma unroll
        for (int i = 0; i < 4; i++) {
            int s = i * 256 + tid;
            int row = s >> 3, k8 = s & 7;
            int gr = rowBase + row;
            const uint16_t* src = A + (size_t)gr * LDA + it * 64 + k8 * 8;
            cpa16(aBase + (buf * 9216 + row * 72 + k8 * 8) * 2, src, (gr < nrows) ? 16 : 0);
        }
        bool ph1 = it < HA;
        int b0 = ph1 ? it * 64 : (it - HA) * 64;
#pragma unroll
        for (int i = 0; i < 2; i++) {
            int s = i * 256 + tid;
            int row = s >> 3, k8 = s & 7;
            cpa16(bBase + (buf * 9216 + row * 72 + k8 * 8) * 2,
                  B + (size_t)(colBase + row) * LDB + b0 + k8 * 8, 16);
        }
        if (ph1) {
            int b1 = (HA + it) * 64;
#pragma unroll
            for (int i = 0; i < 2; i++) {
                int s = i * 256 + tid;
                int row = s >> 3, k8 = s & 7;
                cpa16(bBase + (buf * 9216 + 4608 + row * 72 + k8 * 8) * 2,
                      B + (size_t)(colBase + row) * LDB + b1 + k8 * 8, 16);
            }
        }
        asm volatile("cp.async.commit_group;" ::: "memory");
    };

    issue(itBeg, 0);
    for (int it = itBeg; it < itEnd; it++) {
        int buf = (it - itBeg) & 1;
        if (it + 1 < itEnd) {
            issue(it + 1, buf ^ 1);
            asm volatile("cp.async.wait_group 1;" ::: "memory");
        } else {
            asm volatile("cp.async.wait_group 0;" ::: "memory");
        }
        __syncthreads();
        bool ph1 = it < HA;
#pragma unroll
        for (int ks = 0; ks < 4; ks++) {
            int k0 = ks * 16;
            uint32_t ar[4];
            {
                int row = wm * 16 + (lane & 15);
                int col = k0 + 8 * (lane >> 4);
                ldsm4(ar, aBase + (buf * 9216 + row * 72 + col) * 2);
            }
#pragma unroll
            for (int bt = 0; bt < 2; bt++) {
                if (bt == 1 && !ph1) break;
                uint32_t br[16];
#pragma unroll
                for (int j = 0; j < 4; j++) {
                    int n = j * 16 + 8 * (lane >> 4) + (lane & 7);
                    int col = k0 + 8 * ((lane >> 3) & 1);
                    ldsm4(br + 4 * j, bBase + (buf * 9216 + bt * 4608 + n * 72 + col) * 2);
                }
#pragma unroll
                for (int nf = 0; nf < 8; nf++) {
                    uint32_t b0 = br[4 * (nf >> 1) + 2 * (nf & 1)];
                    uint32_t b1 = br[4 * (nf >> 1) + 2 * (nf & 1) + 1];
                    asm volatile(
                        "mma.sync.aligned.m16n8k16.row.col.f32.bf16.bf16.f32 "
                        "{%0,%1,%2,%3}, {%4,%5,%6,%7}, {%8,%9}, {%0,%1,%2,%3};"
                        : "+f"(c[nf][0]), "+f"(c[nf][1]), "+f"(c[nf][2]), "+f"(c[nf][3])
                        : "r"(ar[0]), "r"(ar[1]), "r"(ar[2]), "r"(ar[3]), "r"(b0), "r"(b1));
                }
            }
        }
        __syncthreads();
    }
    int r0 = rowBase + wm * 16 + g;
    int r1 = r0 + 8;
#pragma unroll
    for (int nf = 0; nf < 8; nf++) {
        int col = colBase + nf * 8 + 2 * t4;
        if (r0 < nrows) *(float2*)(C + (size_t)r0 * ldc + col) = make_float2(c[nf][0], c[nf][1]);
        if (r1 < nrows) *(float2*)(C + (size_t)r1 * ldc + col) = make_float2(c[nf][2], c[nf][3]);
    }
}

// ================= prep (also zeroes cnt) =================
__global__ void k_prep(const float* __restrict__ W2, const float* __restrict__ a2s,
                       const float* __restrict__ a2d, const float* __restrict__ b2,
                       const float* __restrict__ W1,
                       uint16_t* __restrict__ Wt1, uint16_t* __restrict__ Wt2,
                       float* __restrict__ ws, float* __restrict__ wd, float* __restrict__ bc,
                       int* __restrict__ cnt)
{
    int i = blockIdx.x * blockDim.x + threadIdx.x;
    if (i < 131072) {
        int n = i & 63, k = i >> 6;
        int t = k >> 10, r = k & 1023, h = r >> 7, cc = r & 127;
        float wv = W2[t * 65536 + cc * 512 + h * 64 + n] * 0.0625f;
        uint16_t hh, ll; hl_split(wv, hh, ll);
        uint16_t* p = Wt2 + (size_t)n * 4096 + k;
        p[0] = hh; p[2048] = ll;
    } else if (i < 196608) {
        int j = i - 131072;
        int np = j & 255, k = j >> 8;
        int t = np >> 7, n = np & 127;
        float wv = W1[t * 32768 + k * 128 + n];
        uint16_t hh, ll; hl_split(wv, hh, ll);
        uint16_t* p = Wt1 + (size_t)np * 512 + k;
        p[0] = hh; p[256] = ll;
    } else if (i < 198656) {
        int j = i - 196608;
        int t = j >> 10, r = j & 1023, h = r >> 7, cc = r & 127;
        const float* wrow = W2 + t * 65536 + cc * 512 + h * 64;
        const float* av = a2s + t * 512 + h * 64;
        float acc = 0.f;
        for (int o = 0; o < 64; o++) acc += wrow[o] * av[o];
        ws[j] = acc;
    } else if (i < 200704) {
        int j = i - 198656;
        int t = j >> 10, r = j & 1023, h = r >> 7, cc = r & 127;
        const float* wrow = W2 + t * 65536 + cc * 512 + h * 64;
        const float* av = a2d + t * 512 + h * 64;
        float acc = 0.f;
        for (int o = 0; o < 64; o++) acc += wrow[o] * av[o];
        wd[j] = acc;
    } else if (i < 200768) {
        int o = i - 200704;
        bc[o] = 0.5f * (b2[o] + b2[64 + o]);
    } else if (i < 240768) {
        cnt[i - 200768] = 0;
    }
}

// ================= graph preprocessing: histogram only ================= 
__global__ void k_cvt(const void* pa, const void* pb, int* cnt) {
    int t = blockIdx.y;
    const void* p = t ? pb : pa;
    unsigned ov = ((const unsigned*)p)[1 + 2 * (threadIdx.x & 31)];
    int is64 = __all_sync(0xffffffffu, ov == 0u);
    int i = blockIdx.x * blockDim.x + threadIdx.x;
    if (i >= E_) return;
    int d;
    if (is64) d = (int)((const long long*)p)[E_ + i];
    else      d = ((const int*)p)[E_ + i];
    atomicAdd(&cnt[t * N_ + d], 1);
}

__global__ void k_cvtx(const float* __restrict__ x, uint16_t* __restrict__ xb) {
    int i = blockIdx.x * blockDim.x + threadIdx.x;
    if (i >= N_ * 64) return;
    int row = i >> 6, k4 = (i & 63) << 2;
    float4 v = ((const float4*)x)[i];
    uint16_t h0, l0, h1, l1, h2, l2, h3, l3;
    hl_split(v.x, h0, l0); hl_split(v.y, h1, l1);
    hl_split(v.z, h2, l2); hl_split(v.w, h3, l3);
    uint2 hi, lo;
    hi.x = (uint32_t)h0 | ((uint32_t)h1 << 16);
    hi.y = (uint32_t)h2 | ((uint32_t)h3 << 16);
    lo.x = (uint32_t)l0 | ((uint32_t)l1 << 16);
    lo.y = (uint32_t)l2 | ((uint32_t)l3 << 16);
    *(uint2*)(xb + (size_t)row * 512 + k4) = hi;
    *(uint2*)(xb + (size_t)row * 512 + 256 + k4) = lo;
}

__global__ void k_scan(const int* __restrict__ cnt, int* __restrict__ offs, int* __restrict__ cur)
{
    int t = blockIdx.x;
    const int4* c4 = (const int4*)(cnt + t * N_);
    int4* o4 = (int4*)(offs + t * N_);
    int4* q4 = (int4*)(cur + t * N_);
    __shared__ int wsum[32];
    __shared__ int sbase;
    int tid = threadIdx.x, lane = tid & 31, w = tid >> 5;
    if (tid == 0) sbase = 0;
    __syncthreads();
    const int N4 = N_ / 4;
    for (int i0 = 0; i0 < N4; i0 += 1024) {
        int i = i0 + tid;
        int4 c = make_int4(0, 0, 0, 0);
        if (i < N4) c = c4[i];
        int s = c.x + c.y + c.z + c.w;
        int x = s;
#pragma unroll
        for (int ofs = 1; ofs < 32; ofs <<= 1) {
            int y = __shfl_up_sync(0xffffffffu, x, ofs);
            if (lane >= ofs) x += y;
        }
        if (lane == 31) wsum[w] = x;
        __syncthreads();
        if (w == 0) {
            int v = wsum[lane];
#pragma unroll
            for (int ofs = 1; ofs < 32; ofs <<= 1) {
                int y = __shfl_up_sync(0xffffffffu, v, ofs);
                if (lane >= ofs) v += y;
            }
            wsum[lane] = v;
        }
        __syncthreads();
        int excl = sbase + (w ? wsum[w - 1] : 0) + x - s;
        if (i < N4) {
            int4 r;
            r.x = excl; r.y = excl + c.x; r.z = r.y + c.y; r.w = r.z + c.z;
            o4[i] = r; q4[i] = r;
        }
        __syncthreads();
        if (tid == 0) sbase += wsum[31];
        __syncthreads();
    }
}

// scatter reading original inputs (dtype re-detected per warp)
__global__ void k_scatter(const void* pa, const void* pb,
                          int* __restrict__ cur, int* __restrict__ csr)
{
    int t = blockIdx.y;
    const void* p = t ? pb : pa;
    unsigned ov = ((const unsigned*)p)[1 + 2 * (threadIdx.x & 31)];
    int is64 = __all_sync(0xffffffffu, ov == 0u);
    int i = blockIdx.x * blockDim.x + threadIdx.x;
    if (i >= E_) return;
    int s, d;
    if (is64) {
        const long long* q = (const long long*)p;
        s = (int)q[i]; d = (int)q[E_ + i];
    } else {
        const int* q = (const int*)p;
        s = q[i]; d = q[E_ + i];
    }
    int pos = atomicAdd(&cur[t * N_ + d], 1);
    csr[(size_t)t * E_ + pos] = s;
}

// ---------------- layer-1 scores ----------------
__global__ void k_scores1(const float* __restrict__ h1,
                          const float* __restrict__ a_src, const float* __restrict__ a_dst,
                          float* __restrict__ ss, float* __restrict__ sd)
{
    int node = blockIdx.x * 8 + (threadIdx.x >> 5);
    int lane = threadIdx.x & 31;
    int t = blockIdx.y;
    if (node >= N_) return;
    const float* hr = h1 + (size_t)node * 256 + t * 128;
    float4 v = *(const float4*)(hr + lane * 4);
    float4 w = *(const float4*)(a_src + t * 128 + lane * 4);
    float4 u = *(const float4*)(a_dst + t * 128 + lane * 4);
    float ps = v.x * w.x + v.y * w.y + v.z * w.z + v.w * w.w;
    float pd = v.x * u.x + v.y * u.y + v.z * u.z + v.w * u.w;
    ps += __shfl_xor_sync(0xffffffffu, ps, 1);
    ps += __shfl_xor_sync(0xffffffffu, ps, 2);
    pd += __shfl_xor_sync(0xffffffffu, pd, 1);
    pd += __shfl_xor_sync(0xffffffffu, pd, 2);
    if ((lane & 3) == 0) {
        ss[t * N_ * 8 + node * 8 + (lane >> 2)] = ps;
        sd[t * N_ * 8 + node * 8 + (lane >> 2)] = pd;
    }
}

// ---------------- layer-1 GAT: warp per (dst,type), single pass, fused scores2 ----------------
__global__ void __launch_bounds__(256) k_gat1(
    const int* __restrict__ offs, const int* __restrict__ cnt, const int* __restrict__ csr,
    const float* __restrict__ s1s, const float* __restrict__ s1d,
    const float* __restrict__ h1, const float* __restrict__ b1,
    float* __restrict__ h1c,
    const float* __restrict__ ws, const float* __restrict__ wd,
    float* __restrict__ s2s, float* __restrict__ s2d)
{
    __shared__ float sa[8][256];
    __shared__ float4 accs[8][32];
    int w = threadIdx.x >> 5, lane = threadIdx.x & 31;
    int d = blockIdx.x * 4 + (w >> 1);
    int t = w & 1;
    int hd = lane >> 2;
    float4 acc = make_float4(0.f, 0.f, 0.f, 0.f);
    if (d < N_) {
        int beg = offs[t * N_ + d], n = cnt[t * N_ + d];
        const float* ss = s1s + (size_t)t * N_ * 8;
        const float4* sdp = (const float4*)(s1d + ((size_t)t * N_ + d) * 8);
        float4 sd0 = sdp[0], sd1 = sdp[1];
        float sdv[8] = {sd0.x, sd0.y, sd0.z, sd0.w, sd1.x, sd1.y, sd1.z, sd1.w};
        const int* cs = csr + (size_t)t * E_ + beg;
        float zp = 0.f;
        for (int c0 = 0; c0 < n; c0 += 32) {
            int m = n - c0; if (m > 32) m = 32;
            int sL = 0;
            if (lane < m) {
                sL = cs[c0 + lane];
                float4 a0 = *(const float4*)(ss + (size_t)sL * 8);
                float4 a1 = *(const float4*)(ss + (size_t)sL * 8 + 4);
                float4 e0, e1;
                e0.x = __expf(lrelu(a0.x + sdv[0]));
                e0.y = __expf(lrelu(a0.y + sdv[1]));
                e0.z = __expf(lrelu(a0.z + sdv[2]));
                e0.w = __expf(lrelu(a0.w + sdv[3]));
                e1.x = __expf(lrelu(a1.x + sdv[4]));
                e1.y = __expf(lrelu(a1.y + sdv[5]));
                e1.z = __expf(lrelu(a1.z + sdv[6]));
                e1.w = __expf(lrelu(a1.w + sdv[7]));
                *(float4*)&sa[w][lane * 8] = e0;
                *(float4*)&sa[w][lane * 8 + 4] = e1;
            }
            __syncwarp();
#pragma unroll
            for (int j = 0; j < 32; j++) {
                if (j < m) {
                    int sj = __shfl_sync(0xffffffffu, sL, j);
                    float a = sa[w][j * 8 + hd];
                    zp += a;
                    float4 v = *(const float4*)(h1 + (size_t)sj * 256 + t * 128 + lane * 4);
                    acc.x = fmaf(a, v.x, acc.x);
                    acc.y = fmaf(a, v.y, acc.y);
                    acc.z = fmaf(a, v.z, acc.z);
                    acc.w = fmaf(a, v.w, acc.w);
                }
            }
            __syncwarp();
        }
        float inv = (zp > 0.f) ? 1.f / zp : 0.f;
        acc.x *= inv; acc.y *= inv; acc.z *= inv; acc.w *= inv;
    }
    accs[w][lane] = acc;
    __syncthreads();
    if (t == 0 && d < N_) {
        float4 a0 = accs[w][lane], a1 = accs[w + 1][lane];
        float4 bb0 = *(const float4*)(b1 + lane * 4);
        float4 bb1 = *(const float4*)(b1 + 128 + lane * 4);
        float4 r;
        r.x = eluf(0.5f * (a0.x + a1.x + bb0.x + bb1.x));
        r.y = eluf(0.5f * (a0.y + a1.y + bb0.y + bb1.y));
        r.z = eluf(0.5f * (a0.z + a1.z + bb0.z + bb1.z));
        r.w = eluf(0.5f * (a0.w + a1.w + bb0.w + bb1.w));
        *(float4*)(h1c + (size_t)d * 128 + lane * 4) = r;
#pragma unroll
        for (int c = 0; c < 16; c++) {
            float4 wv = *(const float4*)(ws + c * 128 + lane * 4);
            float p = r.x * wv.x + r.y * wv.y + r.z * wv.z + r.w * wv.w;
            p += __shfl_xor_sync(0xffffffffu, p, 16);
            p += __shfl_xor_sync(0xffffffffu, p, 8);
            p += __shfl_xor_sync(0xffffffffu, p, 4);
            p += __shfl_xor_sync(0xffffffffu, p, 2);
            p += __shfl_xor_sync(0xffffffffu, p, 1);
            float4 uv = *(const float4*)(wd + c * 128 + lane * 4);
            float q = r.x * uv.x + r.y * uv.y + r.z * uv.z + r.w * uv.w;
            q += __shfl_xor_sync(0xffffffffu, q, 16);
            q += __shfl_xor_sync(0xffffffffu, q, 8);
            q += __shfl_xor_sync(0xffffffffu, q, 4);
            q += __shfl_xor_sync(0xffffffffu, q, 2);
            q += __shfl_xor_sync(0xffffffffu, q, 1);
            if (lane == 0) {
                s2s[(c >> 3) * N_ * 8 + d * 8 + (c & 7)] = p;
                s2d[(c >> 3) * N_ * 8 + d * 8 + (c & 7)] = q;
            }
        }
    }
}

// ---------------- layer-2 aggregate: warp per (dst,type), packed f32x2 ----------------
__global__ void __launch_bounds__(256) k_gat2(
    const int* __restrict__ offs, const int* __restrict__ cnt, const int* __restrict__ csr,
    const float* __restrict__ s2s, const float* __restrict__ s2d,
    const float* __restrict__ h1c, uint16_t* __restrict__ aggb)
{
    __shared__ float sa[8][256];
    int w = threadIdx.x >> 5, lane = threadIdx.x & 31;
    int d = blockIdx.x * 4 + (w >> 1);
    int t = w & 1;
    if (d >= N_) return;
    int beg = offs[t * N_ + d], n = cnt[t * N_ + d];
    const float* ss = s2s + (size_t)t * N_ * 8;
    const float4* sdp = (const float4*)(s2d + ((size_t)t * N_ + d) * 8);
    float4 sd0 = sdp[0], sd1 = sdp[1];
    float sdv[8] = {sd0.x, sd0.y, sd0.z, sd0.w, sd1.x, sd1.y, sd1.z, sd1.w};
    const int* cs = csr + (size_t)t * E_ + beg;
    uint64_t z2[4];
#pragma unroll
    for (int k = 0; k < 4; k++) z2[k] = pk2(0.f, 0.f);
    uint64_t acc2[4][4];
#pragma unroll
    for (int cc = 0; cc < 4; cc++)
#pragma unroll
        for (int hp = 0; hp < 4; hp++) acc2[cc][hp] = pk2(0.f, 0.f);

    for (int c0 = 0; c0 < n; c0 += 32) {
        int m = n - c0; if (m > 32) m = 32;
        int sL = 0;
        if (lane < m) {
            sL = cs[c0 + lane];
            float4 a0 = *(const float4*)(ss + (size_t)sL * 8);
            float4 a1 = *(const float4*)(ss + (size_t)sL * 8 + 4);
            float4 e0, e1;
            e0.x = __expf(lrelu(a0.x + sdv[0]));
            e0.y = __expf(lrelu(a0.y + sdv[1]));
            e0.z = __expf(lrelu(a0.z + sdv[2]));
            e0.w = __expf(lrelu(a0.w + sdv[3]));
            e1.x = __expf(lrelu(a1.x + sdv[4]));
            e1.y = __expf(lrelu(a1.y + sdv[5]));
            e1.z = __expf(lrelu(a1.z + sdv[6]));
            e1.w = __expf(lrelu(a1.w + sdv[7]));
            *(float4*)&sa[w][lane * 8] = e0;
            *(float4*)&sa[w][lane * 8 + 4] = e1;
        }
        __syncwarp();
#pragma unroll
        for (int j = 0; j < 32; j++) {
            if (j < m) {
                int sj = __shfl_sync(0xffffffffu, sL, j);
                uint64_t a01 = *(const uint64_t*)&sa[w][j * 8];
                uint64_t a23 = *(const uint64_t*)&sa[w][j * 8 + 2];
                uint64_t a45 = *(const uint64_t*)&sa[w][j * 8 + 4];
                uint64_t a67 = *(const uint64_t*)&sa[w][j * 8 + 6];
                z2[0] = add2(z2[0], a01);
                z2[1] = add2(z2[1], a23);
                z2[2] = add2(z2[2], a45);
                z2[3] = add2(z2[3], a67);
                float4 v = *(const float4*)(h1c + (size_t)sj * 128 + lane * 4);
                uint64_t vb[4];
                vb[0] = pk2(v.x, v.x); vb[1] = pk2(v.y, v.y);
                vb[2] = pk2(v.z, v.z); vb[3] = pk2(v.w, v.w);
#pragma unroll
                for (int cc = 0; cc < 4; cc++) {
                    acc2[cc][0] = fma2(a01, vb[cc], acc2[cc][0]);
                    acc2[cc][1] = fma2(a23, vb[cc], acc2[cc][1]);
                    acc2[cc][2] = fma2(a45, vb[cc], acc2[cc][2]);
                    acc2[cc][3] = fma2(a67, vb[cc], acc2[cc][3]);
                }
            }
        }
        __syncwarp();
    }
    float z8[8];
#pragma unroll
    for (int hp = 0; hp < 4; hp++) upk2(z2[hp], z8[2 * hp], z8[2 * hp + 1]);
#pragma unroll
    for (int h = 0; h < 8; h++) {
        float inv = (z8[h] > 0.f) ? 1.f / z8[h] : 0.f;
        float ax, ay, az, aw, dummy;
        int hp = h >> 1;
        if ((h & 1) == 0) {
            upk2(acc2[0][hp], ax, dummy);
            upk2(acc2[1][hp], ay, dummy);
            upk2(acc2[2][hp], az, dummy);
            upk2(acc2[3][hp], aw, dummy);
        } else {
            upk2(acc2[0][hp], dummy, ax);
            upk2(acc2[1][hp], dummy, ay);
            upk2(acc2[2][hp], dummy, az);
            upk2(acc2[3][hp], dummy, aw);
        }
        ax *= inv; ay *= inv; az *= inv; aw *= inv;
        uint16_t h0, l0, h1v, l1, h2, l2, h3, l3;
        hl_split(ax, h0, l0); hl_split(ay, h1v, l1);
        hl_split(az, h2, l2); hl_split(aw, h3, l3);
        uint2 hi, lo;
        hi.x = (uint32_t)h0 | ((uint32_t)h1v << 16);
        hi.y = (uint32_t)h2 | ((uint32_t)h3 << 16);
        lo.x = (uint32_t)l0 | ((uint32_t)l1 << 16);
        lo.y = (uint32_t)l2 | ((uint32_t)l3 << 16);
        int k = t * 1024 + h * 128 + lane * 4;
        *(uint2*)(aggb + (size_t)d * 4096 + k) = hi;
        *(uint2*)(aggb + (size_t)d * 4096 + 2048 + k) = lo;
    }
}

// ---------------- classifier (sums 8 split-K parts, bias + ELU fused) ----------------
__global__ void k_classifier(const float* __restrict__ h, const float* __restrict__ bc,
                             const float* __restrict__ Wc1, const float* __restrict__ bc1,
                             const float* __restrict__ Wc2, const float* __restrict__ bc2,
                             float* __restrict__ out)
{
    int wid = (blockIdx.x * blockDim.x + threadIdx.x) >> 5;
    int lane = threadIdx.x & 31;
    if (wid >= N_) return;
    float acc = bc1[lane];
#pragma unroll
    for (int c = 0; c < 64; c++) {
        float s = __ldg(bc + c);
#pragma unroll
        for (int z = 0; z < 8; z++)
            s += __ldg(h + (size_t)z * N_ * 64 + (size_t)wid * 64 + c);
        acc = fmaf(eluf(s), Wc1[c * 32 + lane], acc);
    }
    acc = fmaxf(acc, 0.f);
    float p0 = acc * Wc2[lane * 2];
    float p1 = acc * Wc2[lane * 2 + 1];
#pragma unroll
    for (int o = 16; o >= 1; o >>= 1) {
        p0 += __shfl_xor_sync(0xffffffffu, p0, o);
        p1 += __shfl_xor_sync(0xffffffffu, p1, o);
    }
    if (lane == 0) {
        out[wid * 2 + 0] = p0 + bc2[0];
        out[wid * 2 + 1] = p1 + bc2[1];
    }
}

// ---------------- launch ----------------
extern "C" void kernel_launch(void* const* d_in, const int* in_sizes, int n_in,
                              void* d_out, int out_size)
{
    const float* x    = (const float*)d_in[0];
    const void*  eia  = d_in[1];
    const void*  eib  = d_in[2];
    const float* W1   = (const float*)d_in[3];
    const float* a1s  = (const float*)d_in[4];
    const float* a1d  = (const float*)d_in[5];
    const float* b1   = (const float*)d_in[6];
    const float* W2   = (const float*)d_in[7];
    const float* a2s  = (const float*)d_in[8];
    const float* a2d  = (const float*)d_in[9];
    const float* b2   = (const float*)d_in[10];
    const float* Wc1  = (const float*)d_in[11];
    const float* bc1  = (const float*)d_in[12];
    const float* Wc2  = (const float*)d_in[13];
    const float* bc2  = (const float*)d_in[14];
    float* out = (float*)d_out;

    void* basev = nullptr;
    cudaGetSymbolAddress(&basev, g_scratch);
    unsigned char* base = (unsigned char*)basev;

    int*      p_csr  = (int*)(base + O_CSR);
    int*      p_cnt  = (int*)(base + O_CNT);
    int*      p_off  = (int*)(base + O_OFF);
    int*      p_cur  = (int*)(base + O_CUR);
    uint16_t* p_xb   = (uint16_t*)(base + O_XB);
    float*    p_h1   = (float*)(base + O_H1);
    float*    p_s1s  = (float*)(base + O_S1S);
    float*    p_s1d  = (float*)(base + O_S1D);
    float*    p_h1c  = (float*)(base + O_H1C);
    float*    p_s2s  = (float*)(base + O_S2S);
    float*    p_s2d  = (float*)(base + O_S2D);
    float*    p_ws   = (float*)(base + O_WS);
    float*    p_wd   = (float*)(base + O_WD);
    float*    p_bc   = (float*)(base + O_BC);
    uint16_t* p_wt1  = (uint16_t*)(base + O_WT1);
    uint16_t* p_wt2  = (uint16_t*)(base + O_WT2);
    uint16_t* p_aggb = (uint16_t*)(base + O_AGGB);
    float*    p_h2p  = (float*)(base + O_H2P);

    cudaFuncSetAttribute(k_mmagemm<4, 512, 512>,
                         cudaFuncAttributeMaxDynamicSharedMemorySize, 73728);
    cudaFuncSetAttribute(k_mmagemm<32, 4096, 4096>,
                         cudaFuncAttributeMaxDynamicSharedMemorySize, 73728);

    // 1-3: prep (zeros cnt), cvt (histogram only), cvtx
    k_prep<<<(240768 + 255) / 256, 256>>>(W2, a2s, a2d, b2, W1, p_wt1, p_wt2,
                                          p_ws, p_wd, p_bc, p_cnt);
    k_cvt<<<dim3((E_ + 255) / 256, 2), 256>>>(eia, eib, p_cnt);
    k_cvtx<<<(N_ * 64 + 255) / 256, 256>>>(x, p_xb);

    // 4: layer-1 GEMM
    k_mmagemm<4, 512, 512><<<dim3(157, 4, 1), 256, 73728>>>(p_xb, p_wt1, p_h1, N_, 256, 0);

    // 5-6: finish CSR (scatter reads original inputs)
    k_scan<<<2, 1024>>>(p_cnt, p_off, p_cur);
    k_scatter<<<dim3((E_ + 255) / 256, 2), 256>>>(eia, eib, p_cur, p_csr);

    // 7-9: scores -> gat1 (h1c + layer-2 scores) -> gat2
    k_scores1<<<dim3((N_ + 7) / 8, 2), 256>>>(p_h1, a1s, a1d, p_s1s, p_s1d);
    k_gat1<<<(N_ + 3) / 4, 256>>>(p_off, p_cnt, p_csr, p_s1s, p_s1d, p_h1, b1,
                                  p_h1c, p_ws, p_wd, p_s2s, p_s2d);
    k_gat2<<<(N_ + 3) / 4, 256>>>(p_off, p_cnt, p_csr, p_s2s, p_s2d, p_h1c, p_aggb);

    // 10: layer-2 GEMM, split-K=8
    k_mmagemm<32, 4096, 4096><<<dim3(157, 1, 8), 256, 73728>>>(
        p_aggb, p_wt2, p_h2p, N_, 64, (size_t)N_ * 64);

    // 11: classifier
    k_classifier<<<(N_ * 32 + 255) / 256, 256>>>(p_h2p, p_bc, Wc1, bc1, Wc2, bc2, out);
}

// round 13
// speedup vs baseline: 1.1309x; 1.0091x over previous
#include <cuda_runtime.h>
#include <cuda_bf16.h>
#include <cstdint>
#include <cstddef>

#define N_ 20000
#define E_ 640000
#define MB (1048576ull)

// ---------------- scratch layout (R10) ----------------
static const size_t O_CSR  = 0;
static const size_t O_CNT  = 6*MB;
static const size_t O_OFF  = 7*MB;
static const size_t O_CUR  = 8*MB;
static const size_t O_XB   = 9*MB;
static const size_t O_H1   = 30*MB;
static const size_t O_S1S  = 51*MB;
static const size_t O_S1D  = 53*MB;
static const size_t O_H1C  = 55*MB;
static const size_t O_S2S  = 66*MB;
static const size_t O_S2D  = 68*MB;
static const size_t O_WS   = 70*MB;
static const size_t O_WD   = 70*MB + 16384;
static const size_t O_BC   = 70*MB + 32768;
static const size_t O_WT1  = 71*MB;
static const size_t O_WT2  = 72*MB;
static const size_t O_AGGB = 73*MB;
static const size_t O_SRC  = 73*MB;            // temp, dead before AGGB
static const size_t O_DST  = 79*MB;            // temp
static const size_t O_H2P  = 238*MB;           // fp32[4 * N*64]
static const size_t SCRATCH_BYTES = 262*MB;

__device__ __align__(1024) unsigned char g_scratch[SCRATCH_BYTES];

__device__ __forceinline__ float eluf(float x) { return x > 0.f ? x : expm1f(x); }
__device__ __forceinline__ float lrelu(float x) { return x > 0.f ? x : 0.2f * x; }

__device__ __forceinline__ void hl_split(float x, uint16_t& h, uint16_t& l) {
    __nv_bfloat16 hb = __float2bfloat16(x);
    h = __bfloat16_as_ushort(hb);
    l = __bfloat16_as_ushort(__float2bfloat16(x - __bfloat162float(hb)));
}

__device__ __forceinline__ void cpa16(uint32_t dst, const void* src, int szbytes) {
    asm volatile("cp.async.cg.shared.global [%0], [%1], 16, %2;"
                 :: "r"(dst), "l"(src), "r"(szbytes));
}

__device__ __forceinline__ void ldsm4(uint32_t* r, uint32_t addr) {
    asm volatile("ldmatrix.sync.aligned.m8n8.x4.shared.b16 {%0,%1,%2,%3}, [%4];"
                 : "=r"(r[0]), "=r"(r[1]), "=r"(r[2]), "=r"(r[3]) : "r"(addr));
}

__device__ __forceinline__ uint64_t pk2(float x, float y) {
    uint64_t r;
    asm("mov.b64 %0, {%1, %2};" : "=l"(r) : "f"(x), "f"(y));
    return r;
}
__device__ __forceinline__ void upk2(uint64_t v, float& x, float& y) {
    asm("mov.b64 {%0, %1}, %2;" : "=f"(x), "=f"(y) : "l"(v));
}
__device__ __forceinline__ uint64_t fma2(uint64_t a, uint64_t b, uint64_t c) {
    uint64_t d;
    asm("fma.rn.f32x2 %0, %1, %2, %3;" : "=l"(d) : "l"(a), "l"(b), "l"(c));
    return d;
}
__device__ __forceinline__ uint64_t add2(uint64_t a, uint64_t b) {
    uint64_t d;
    asm("add.rn.f32x2 %0, %1, %2;" : "=l"(d) : "l"(a), "l"(b));
    return d;
}

// ================= pipelined mma.sync bf16 GEMM (128x64 tiles) =================
template<int HA, int LDA, int LDB>
__global__ void __launch_bounds__(256) k_mmagemm(
    const uint16_t* __restrict__ A, const uint16_t* __restrict__ B,
    float* __restrict__ C, int nrows, int ldc, size_t zstride)
{
    extern __shared__ uint16_t sh[];
    uint16_t* Asm = sh;
    uint16_t* Bsm = sh + 2 * 9216;
    int tid = threadIdx.x;
    int wm = tid >> 5, lane = tid & 31;
    int g = lane >> 2, t4 = lane & 3;
    int rowBase = blockIdx.x * 128;
    int colBase = blockIdx.y * 64;
    int span = (2 * HA) / gridDim.z;
    int itBeg = blockIdx.z * span, itEnd = itBeg + span;
    C += (size_t)blockIdx.z * zstride;

    float c[8][4];
#pragma unroll
    for (int i = 0; i < 8; i++)
#pragma unroll
        for (int j = 0; j < 4; j++) c[i][j] = 0.f;

    uint32_t aBase = (uint32_t)__cvta_generic_to_shared(Asm);
    uint32_t bBase = (uint32_t)__cvta_generic_to_shared(Bsm);

    auto issue = [&](int it, int buf) {
#pragma unroll
        for (int i = 0; i < 4; i++) {
            int s = i * 256 + tid;
            int row = s >> 3, k8 = s & 7;
            int gr = rowBase + row;
            const uint16_t* src = A + (size_t)gr * LDA + it * 64 + k8 * 8;
            cpa16(aBase + (buf * 9216 + row * 72 + k8 * 8) * 2, src, (gr < nrows) ? 16 : 0);
        }
        bool ph1 = it < HA;
        int b0 = ph1 ? it * 64 : (it - HA) * 64;
#pragma unroll
        for (int i = 0; i < 2; i++) {
            int s = i * 256 + tid;
            int row = s >> 3, k8 = s & 7;
            cpa16(bBase + (buf * 9216 + row * 72 + k8 * 8) * 2,
                  B + (size_t)(colBase + row) * LDB + b0 + k8 * 8, 16);
        }
        if (ph1) {
            int b1 = (HA + it) * 64;
#pragma unroll
            for (int i = 0; i < 2; i++) {
                int s = i * 256 + tid;
                int row = s >> 3, k8 = s & 7;
                cpa16(bBase + (buf * 9216 + 4608 + row * 72 + k8 * 8) * 2,
                      B + (size_t)(colBase + row) * LDB + b1 + k8 * 8, 16);
            }
        }
        asm volatile("cp.async.commit_group;" ::: "memory");
    };

    issue(itBeg, 0);
    for (int it = itBeg; it < itEnd; it++) {
        int buf = (it - itBeg) & 1;
        if (it + 1 < itEnd) {
            issue(it + 1, buf ^ 1);
            asm volatile("cp.async.wait_group 1;" ::: "memory");
        } else {
            asm volatile("cp.async.wait_group 0;" ::: "memory");
        }
        __syncthreads();
        bool ph1 = it < HA;
#pragma unroll
        for (int ks = 0; ks < 4; ks++) {
            int k0 = ks * 16;
            uint32_t ar[4];
            {
                int row = wm * 16 + (lane & 15);
                int col = k0 + 8 * (lane >> 4);
                ldsm4(ar, aBase + (buf * 9216 + row * 72 + col) * 2);
            }
#pragma unroll
            for (int bt = 0; bt < 2; bt++) {
                if (bt == 1 && !ph1) break;
                uint32_t br[16];
#pragma unroll
                for (int j = 0; j < 4; j++) {
                    int n = j * 16 + 8 * (lane >> 4) + (lane & 7);
                    int col = k0 + 8 * ((lane >> 3) & 1);
                    ldsm4(br + 4 * j, bBase + (buf * 9216 + bt * 4608 + n * 72 + col) * 2);
                }
#pragma unroll
                for (int nf = 0; nf < 8; nf++) {
                    uint32_t b0 = br[4 * (nf >> 1) + 2 * (nf & 1)];
                    uint32_t b1 = br[4 * (nf >> 1) + 2 * (nf & 1) + 1];
                    asm volatile(
                        "mma.sync.aligned.m16n8k16.row.col.f32.bf16.bf16.f32 "
                        "{%0,%1,%2,%3}, {%4,%5,%6,%7}, {%8,%9}, {%0,%1,%2,%3};"
                        : "+f"(c[nf][0]), "+f"(c[nf][1]), "+f"(c[nf][2]), "+f"(c[nf][3])
                        : "r"(ar[0]), "r"(ar[1]), "r"(ar[2]), "r"(ar[3]), "r"(b0), "r"(b1));
                }
            }
        }
        __syncthreads();
    }
    int r0 = rowBase + wm * 16 + g;
    int r1 = r0 + 8;
#pragma unroll
    for (int nf = 0; nf < 8; nf++) {
        int col = colBase + nf * 8 + 2 * t4;
        if (r0 < nrows) *(float2*)(C + (size_t)r0 * ldc + col) = make_float2(c[nf][0], c[nf][1]);
        if (r1 < nrows) *(float2*)(C + (size_t)r1 * ldc + col) = make_float2(c[nf][2], c[nf][3]);
    }
}

// ================= prep (also zeroes cnt) =================
__global__ void k_prep(const float* __restrict__ W2, const float* __restrict__ a2s,
                       const float* __restrict__ a2d, const float* __restrict__ b2,
                       const float* __restrict__ W1,
                       uint16_t* __restrict__ Wt1, uint16_t* __restrict__ Wt2,
                       float* __restrict__ ws, float* __restrict__ wd, float* __restrict__ bc,
                       int* __restrict__ cnt)
{
    int i = blockIdx.x * blockDim.x + threadIdx.x;
    if (i < 131072) {
        int n = i & 63, k = i >> 6;
        int t = k >> 10, r = k & 1023, h = r >> 7, cc = r & 127;
        float wv = W2[t * 65536 + cc * 512 + h * 64 + n] * 0.0625f;
        uint16_t hh, ll; hl_split(wv, hh, ll);
        uint16_t* p = Wt2 + (size_t)n * 4096 + k;
        p[0] = hh; p[2048] = ll;
    } else if (i < 196608) {
        int j = i - 131072;
        int np = j & 255, k = j >> 8;
        int t = np >> 7, n = np & 127;
        float wv = W1[t * 32768 + k * 128 + n];
        uint16_t hh, ll; hl_split(wv, hh, ll);
        uint16_t* p = Wt1 + (size_t)np * 512 + k;
        p[0] = hh; p[256] = ll;
    } else if (i < 198656) {
        int j = i - 196608;
        int t = j >> 10, r = j & 1023, h = r >> 7, cc = r & 127;
        const float* wrow = W2 + t * 65536 + cc * 512 + h * 64;
        const float* av = a2s + t * 512 + h * 64;
        float acc = 0.f;
        for (int o = 0; o < 64; o++) acc += wrow[o] * av[o];
        ws[j] = acc;
    } else if (i < 200704) {
        int j = i - 198656;
        int t = j >> 10, r = j & 1023, h = r >> 7, cc = r & 127;
        const float* wrow = W2 + t * 65536 + cc * 512 + h * 64;
        const float* av = a2d + t * 512 + h * 64;
        float acc = 0.f;
        for (int o = 0; o < 64; o++) acc += wrow[o] * av[o];
        wd[j] = acc;
    } else if (i < 200768) {
        int o = i - 200704;
        bc[o] = 0.5f * (b2[o] + b2[64 + o]);
    } else if (i < 240768) {
        cnt[i - 200768] = 0;
    }
}

// ================= graph preprocessing (staged, R10) =================
__global__ void k_cvt(const void* pa, const void* pb, int* src, int* dst, int* cnt) {
    int t = blockIdx.y;
    const void* p = t ? pb : pa;
    unsigned ov = ((const unsigned*)p)[1 + 2 * (threadIdx.x & 31)];
    int is64 = __all_sync(0xffffffffu, ov == 0u);
    int i = blockIdx.x * blockDim.x + threadIdx.x;
    if (i >= E_) return;
    int s, d;
    if (is64) {
        const long long* q = (const long long*)p;
        s = (int)q[i]; d = (int)q[E_ + i];
    } else {
        const int* q = (const int*)p;
        s = q[i]; d = q[E_ + i];
    }
    src[t * E_ + i] = s;
    dst[t * E_ + i] = d;
    atomicAdd(&cnt[t * N_ + d], 1);
}

__global__ void k_cvtx(const float* __restrict__ x, uint16_t* __restrict__ xb) {
    int i = blockIdx.x * blockDim.x + threadIdx.x;
    if (i >= N_ * 64) return;
    int row = i >> 6, k4 = (i & 63) << 2;
    float4 v = ((const float4*)x)[i];
    uint16_t h0, l0, h1, l1, h2, l2, h3, l3;
    hl_split(v.x, h0, l0); hl_split(v.y, h1, l1);
    hl_split(v.z, h2, l2); hl_split(v.w, h3, l3);
    uint2 hi, lo;
    hi.x = (uint32_t)h0 | ((uint32_t)h1 << 16);
    hi.y = (uint32_t)h2 | ((uint32_t)h3 << 16);
    lo.x = (uint32_t)l0 | ((uint32_t)l1 << 16);
    lo.y = (uint32_t)l2 | ((uint32_t)l3 << 16);
    *(uint2*)(xb + (size_t)row * 512 + k4) = hi;
    *(uint2*)(xb + (size_t)row * 512 + 256 + k4) = lo;
}

__global__ void k_scan(const int* __restrict__ cnt, int* __restrict__ offs, int* __restrict__ cur)
{
    int t = blockIdx.x;
    const int4* c4 = (const int4*)(cnt + t * N_);
    int4* o4 = (int4*)(offs + t * N_);
    int4* q4 = (int4*)(cur + t * N_);
    __shared__ int wsum[32];
    __shared__ int sbase;
    int tid = threadIdx.x, lane = tid & 31, w = tid >> 5;
    if (tid == 0) sbase = 0;
    __syncthreads();
    const int N4 = N_ / 4;
    for (int i0 = 0; i0 < N4; i0 += 1024) {
        int i = i0 + tid;
        int4 c = make_int4(0, 0, 0, 0);
        if (i < N4) c = c4[i];
        int s = c.x + c.y + c.z + c.w;
        int x = s;
#pragma unroll
        for (int ofs = 1; ofs < 32; ofs <<= 1) {
            int y = __shfl_up_sync(0xffffffffu, x, ofs);
            if (lane >= ofs) x += y;
        }
        if (lane == 31) wsum[w] = x;
        __syncthreads();
        if (w == 0) {
            int v = wsum[lane];
#pragma unroll
            for (int ofs = 1; ofs < 32; ofs <<= 1) {
                int y = __shfl_up_sync(0xffffffffu, v, ofs);
                if (lane >= ofs) v += y;
            }
            wsum[lane] = v;
        }
        __syncthreads();
        int excl = sbase + (w ? wsum[w - 1] : 0) + x - s;
        if (i < N4) {
            int4 r;
            r.x = excl; r.y = excl + c.x; r.z = r.y + c.y; r.w = r.z + c.z;
            o4[i] = r; q4[i] = r;
        }
        __syncthreads();
        if (tid == 0) sbase += wsum[31];
        __syncthreads();
    }
}

__global__ void k_scatter(const int* __restrict__ src, const int* __restrict__ dst,
                          int* __restrict__ cur, int* __restrict__ csr)
{
    int i = blockIdx.x * blockDim.x + threadIdx.x;
    if (i >= 2 * E_) return;
    int t = (i >= E_) ? 1 : 0;
    int e = i - t * E_;
    int s = src[t * E_ + e], d = dst[t * E_ + e];
    int pos = atomicAdd(&cur[t * N_ + d], 1);
    csr[(size_t)t * E_ + pos] = s;
}

// ---------------- layer-1 scores ----------------
__global__ void k_scores1(const float* __restrict__ h1,
                          const float* __restrict__ a_src, const float* __restrict__ a_dst,
                          float* __restrict__ ss, float* __restrict__ sd)
{
    int node = blockIdx.x * 8 + (threadIdx.x >> 5);
    int lane = threadIdx.x & 31;
    int t = blockIdx.y;
    if (node >= N_) return;
    const float* hr = h1 + (size_t)node * 256 + t * 128;
    float4 v = *(const float4*)(hr + lane * 4);
    float4 w = *(const float4*)(a_src + t * 128 + lane * 4);
    float4 u = *(const float4*)(a_dst + t * 128 + lane * 4);
    float ps = v.x * w.x + v.y * w.y + v.z * w.z + v.w * w.w;
    float pd = v.x * u.x + v.y * u.y + v.z * u.z + v.w * u.w;
    ps += __shfl_xor_sync(0xffffffffu, ps, 1);
    ps += __shfl_xor_sync(0xffffffffu, ps, 2);
    pd += __shfl_xor_sync(0xffffffffu, pd, 1);
    pd += __shfl_xor_sync(0xffffffffu, pd, 2);
    if ((lane & 3) == 0) {
        ss[t * N_ * 8 + node * 8 + (lane >> 2)] = ps;
        sd[t * N_ * 8 + node * 8 + (lane >> 2)] = pd;
    }
}

// ---------------- layer-1 GAT: warp per (dst,type), prefetched staging, fused scores2 ----------------
__global__ void __launch_bounds__(256) k_gat1(
    const int* __restrict__ offs, const int* __restrict__ cnt, const int* __restrict__ csr,
    const float* __restrict__ s1s, const float* __restrict__ s1d,
    const float* __restrict__ h1, const float* __restrict__ b1,
    float* __restrict__ h1c,
    const float* __restrict__ ws, const float* __restrict__ wd,
    float* __restrict__ s2s, float* __restrict__ s2d)
{
    __shared__ float sa[8][256];
    __shared__ float4 accs[8][32];
    int w = threadIdx.x >> 5, lane = threadIdx.x & 31;
    int d = blockIdx.x * 4 + (w >> 1);
    int t = w & 1;
    int hd = lane >> 2;
    float4 acc = make_float4(0.f, 0.f, 0.f, 0.f);
    if (d < N_) {
        int beg = offs[t * N_ + d], n = cnt[t * N_ + d];
        const float* ss = s1s + (size_t)t * N_ * 8;
        const float4* sdp = (const float4*)(s1d + ((size_t)t * N_ + d) * 8);
        float4 sd0 = sdp[0], sd1 = sdp[1];
        float sdv[8] = {sd0.x, sd0.y, sd0.z, sd0.w, sd1.x, sd1.y, sd1.z, sd1.w};
        const int* cs = csr + (size_t)t * E_ + beg;
        float zp = 0.f;
        // prefetch chunk 0
        int m = n < 32 ? n : 32;
        int sL = 0; float4 pa0, pa1;
        if (lane < m) {
            sL = cs[lane];
            pa0 = *(const float4*)(ss + (size_t)sL * 8);
            pa1 = *(const float4*)(ss + (size_t)sL * 8 + 4);
        }
        for (int c0 = 0; c0 < n; c0 += 32) {
            if (lane < m) {
                float4 e0, e1;
                e0.x = __expf(lrelu(pa0.x + sdv[0]));
                e0.y = __expf(lrelu(pa0.y + sdv[1]));
                e0.z = __expf(lrelu(pa0.z + sdv[2]));
                e0.w = __expf(lrelu(pa0.w + sdv[3]));
                e1.x = __expf(lrelu(pa1.x + sdv[4]));
                e1.y = __expf(lrelu(pa1.y + sdv[5]));
                e1.z = __expf(lrelu(pa1.z + sdv[6]));
                e1.w = __expf(lrelu(pa1.w + sdv[7]));
                *(float4*)&sa[w][lane * 8] = e0;
                *(float4*)&sa[w][lane * 8 + 4] = e1;
            }
            __syncwarp();
            // prefetch next chunk (overlaps inner loop below)
            int c1 = c0 + 32;
            int m2 = n - c1; if (m2 > 32) m2 = 32;
            int sL2 = 0; float4 na0 = pa0, na1 = pa1;
            if (c1 < n && lane < m2) {
                sL2 = cs[c1 + lane];
                na0 = *(const float4*)(ss + (size_t)sL2 * 8);
                na1 = *(const float4*)(ss + (size_t)sL2 * 8 + 4);
            }
#pragma unroll
            for (int j = 0; j < 32; j++) {
                if (j < m) {
                    int sj = __shfl_sync(0xffffffffu, sL, j);
                    float a = sa[w][j * 8 + hd];
                    zp += a;
                    float4 v = *(const float4*)(h1 + (size_t)sj * 256 + t * 128 + lane * 4);
                    acc.x = fmaf(a, v.x, acc.x);
                    acc.y = fmaf(a, v.y, acc.y);
                    acc.z = fmaf(a, v.z, acc.z);
                    acc.w = fmaf(a, v.w, acc.w);
                }
            }
            __syncwarp();
            m = m2; sL = sL2; pa0 = na0; pa1 = na1;
        }
        float inv = (zp > 0.f) ? 1.f / zp : 0.f;
        acc.x *= inv; acc.y *= inv; acc.z *= inv; acc.w *= inv;
    }
    accs[w][lane] = acc;
    __syncthreads();
    if (t == 0 && d < N_) {
        float4 a0 = accs[w][lane], a1 = accs[w + 1][lane];
        float4 bb0 = *(const float4*)(b1 + lane * 4);
        float4 bb1 = *(const float4*)(b1 + 128 + lane * 4);
        float4 r;
        r.x = eluf(0.5f * (a0.x + a1.x + bb0.x + bb1.x));
        r.y = eluf(0.5f * (a0.y + a1.y + bb0.y + bb1.y));
        r.z = eluf(0.5f * (a0.z + a1.z + bb0.z + bb1.z));
        r.w = eluf(0.5f * (a0.w + a1.w + bb0.w + bb1.w));
        *(float4*)(h1c + (size_t)d * 128 + lane * 4) = r;
#pragma unroll
        for (int c = 0; c < 16; c++) {
            float4 wv = *(const float4*)(ws + c * 128 + lane * 4);
            float p = r.x * wv.x + r.y * wv.y + r.z * wv.z + r.w * wv.w;
            p += __shfl_xor_sync(0xffffffffu, p, 16);
            p += __shfl_xor_sync(0xffffffffu, p, 8);
            p += __shfl_xor_sync(0xffffffffu, p, 4);
            p += __shfl_xor_sync(0xffffffffu, p, 2);
            p += __shfl_xor_sync(0xffffffffu, p, 1);
            float4 uv = *(const float4*)(wd + c * 128 + lane * 4);
            float q = r.x * uv.x + r.y * uv.y + r.z * uv.z + r.w * uv.w;
            q += __shfl_xor_sync(0xffffffffu, q, 16);
            q += __shfl_xor_sync(0xffffffffu, q, 8);
            q += __shfl_xor_sync(0xffffffffu, q, 4);
            q += __shfl_xor_sync(0xffffffffu, q, 2);
            q += __shfl_xor_sync(0xffffffffu, q, 1);
            if (lane == 0) {
                s2s[(c >> 3) * N_ * 8 + d * 8 + (c & 7)] = p;
                s2d[(c >> 3) * N_ * 8 + d * 8 + (c & 7)] = q;
            }
        }
    }
}

// ---------------- layer-2 aggregate: warp per (dst,type), prefetched staging, f32x2 ----------------
__global__ void __launch_bounds__(256) k_gat2(
    const int* __restrict__ offs, const int* __restrict__ cnt, const int* __restrict__ csr,
    const float* __restrict__ s2s, const float* __restrict__ s2d,
    const float* __restrict__ h1c, uint16_t* __restrict__ aggb)
{
    __shared__ float sa[8][256];
    int w = threadIdx.x >> 5, lane = threadIdx.x & 31;
    int d = blockIdx.x * 4 + (w >> 1);
    int t = w & 1;
    if (d >= N_) return;
    int beg = offs[t * N_ + d], n = cnt[t * N_ + d];
    const float* ss = s2s + (size_t)t * N_ * 8;
    const float4* sdp = (const float4*)(s2d + ((size_t)t * N_ + d) * 8);
    float4 sd0 = sdp[0], sd1 = sdp[1];
    float sdv[8] = {sd0.x, sd0.y, sd0.z, sd0.w, sd1.x, sd1.y, sd1.z, sd1.w};
    const int* cs = csr + (size_t)t * E_ + beg;
    uint64_t z2[4];
#pragma unroll
    for (int k = 0; k < 4; k++) z2[k] = pk2(0.f, 0.f);
    uint64_t acc2[4][4];
#pragma unroll
    for (int cc = 0; cc < 4; cc++)
#pragma unroll
        for (int hp = 0; hp < 4; hp++) acc2[cc][hp] = pk2(0.f, 0.f);

    // prefetch chunk 0
    int m = n < 32 ? n : 32;
    int sL = 0; float4 pa0, pa1;
    if (lane < m) {
        sL = cs[lane];
        pa0 = *(const float4*)(ss + (size_t)sL * 8);
        pa1 = *(const float4*)(ss + (size_t)sL * 8 + 4);
    }
    for (int c0 = 0; c0 < n; c0 += 32) {
        if (lane < m) {
            float4 e0, e1;
            e0.x = __expf(lrelu(pa0.x + sdv[0]));
            e0.y = __expf(lrelu(pa0.y + sdv[1]));
            e0.z = __expf(lrelu(pa0.z + sdv[2]));
            e0.w = __expf(lrelu(pa0.w + sdv[3]));
            e1.x = __expf(lrelu(pa1.x + sdv[4]));
            e1.y = __expf(lrelu(pa1.y + sdv[5]));
            e1.z = __expf(lrelu(pa1.z + sdv[6]));
            e1.w = __expf(lrelu(pa1.w + sdv[7]));
            *(float4*)&sa[w][lane * 8] = e0;
            *(float4*)&sa[w][lane * 8 + 4] = e1;
        }
        __syncwarp();
        // prefetch next chunk
        int c1 = c0 + 32;
        int m2 = n - c1; if (m2 > 32) m2 = 32;
        int sL2 = 0; float4 na0 = pa0, na1 = pa1;
        if (c1 < n && lane < m2) {
            sL2 = cs[c1 + lane];
            na0 = *(const float4*)(ss + (size_t)sL2 * 8);
            na1 = *(const float4*)(ss + (size_t)sL2 * 8 + 4);
        }
#pragma unroll
        for (int j = 0; j < 32; j++) {
            if (j < m) {
                int sj = __shfl_sync(0xffffffffu, sL, j);
                uint64_t a01 = *(const uint64_t*)&sa[w][j * 8];
                uint64_t a23 = *(const uint64_t*)&sa[w][j * 8 + 2];
                uint64_t a45 = *(const uint64_t*)&sa[w][j * 8 + 4];
                uint64_t a67 = *(const uint64_t*)&sa[w][j * 8 + 6];
                z2[0] = add2(z2[0], a01);
                z2[1] = add2(z2[1], a23);
                z2[2] = add2(z2[2], a45);
                z2[3] = add2(z2[3], a67);
                float4 v = *(const float4*)(h1c + (size_t)sj * 128 + lane * 4);
                uint64_t vb[4];
                vb[0] = pk2(v.x, v.x); vb[1] = pk2(v.y, v.y);
                vb[2] = pk2(v.z, v.z); vb[3] = pk2(v.w, v.w);
#pragma unroll
                for (int cc = 0; cc < 4; cc++) {
                    acc2[cc][0] = fma2(a01, vb[cc], acc2[cc][0]);
                    acc2[cc][1] = fma2(a23, vb[cc], acc2[cc][1]);
                    acc2[cc][2] = fma2(a45, vb[cc], acc2[cc][2]);
                    acc2[cc][3] = fma2(a67, vb[cc], acc2[cc][3]);
                }
            }
        }
        __syncwarp();
        m = m2; sL = sL2; pa0 = na0; pa1 = na1;
    }
    float z8[8];
#pragma unroll
    for (int hp = 0; hp < 4; hp++) upk2(z2[hp], z8[2 * hp], z8[2 * hp + 1]);
#pragma unroll
    for (int h = 0; h < 8; h++) {
        float inv = (z8[h] > 0.f) ? 1.f / z8[h] : 0.f;
        float ax, ay, az, aw, dummy;
        int hp = h >> 1;
        if ((h & 1) == 0) {
            upk2(acc2[0][hp], ax, dummy);
            upk2(acc2[1][hp], ay, dummy);
            upk2(acc2[2][hp], az, dummy);
            upk2(acc2[3][hp], aw, dummy);
        } else {
            upk2(acc2[0][hp], dummy, ax);
            upk2(acc2[1][hp], dummy, ay);
            upk2(acc2[2][hp], dummy, az);
            upk2(acc2[3][hp], dummy, aw);
        }
        ax *= inv; ay *= inv; az *= inv; aw *= inv;
        uint16_t h0, l0, h1v, l1, h2, l2, h3, l3;
        hl_split(ax, h0, l0); hl_split(ay, h1v, l1);
        hl_split(az, h2, l2); hl_split(aw, h3, l3);
        uint2 hi, lo;
        hi.x = (uint32_t)h0 | ((uint32_t)h1v << 16);
        hi.y = (uint32_t)h2 | ((uint32_t)h3 << 16);
        lo.x = (uint32_t)l0 | ((uint32_t)l1 << 16);
        lo.y = (uint32_t)l2 | ((uint32_t)l3 << 16);
        int k = t * 1024 + h * 128 + lane * 4;
        *(uint2*)(aggb + (size_t)d * 4096 + k) = hi;
        *(uint2*)(aggb + (size_t)d * 4096 + 2048 + k) = lo;
    }
}

// ---------------- classifier (sums 4 split-K parts) ----------------
__global__ void k_classifier(const float* __restrict__ h, const float* __restrict__ bc,
                             const float* __restrict__ Wc1, const float* __restrict__ bc1,
                             const float* __restrict__ Wc2, const float* __restrict__ bc2,
                             float* __restrict__ out)
{
    int wid = (blockIdx.x * blockDim.x + threadIdx.x) >> 5;
    int lane = threadIdx.x & 31;
    if (wid >= N_) return;
    const float* hr0 = h + (size_t)wid * 64;
    const float* hr1 = hr0 + (size_t)N_ * 64;
    const float* hr2 = hr1 + (size_t)N_ * 64;
    const float* hr3 = hr2 + (size_t)N_ * 64;
    float acc = bc1[lane];
#pragma unroll
    for (int c = 0; c < 64; c++) {
        float hv = eluf(__ldg(hr0 + c) + __ldg(hr1 + c) + __ldg(hr2 + c) + __ldg(hr3 + c)
                        + __ldg(bc + c));
        acc = fmaf(hv, Wc1[c * 32 + lane], acc);
    }
    acc = fmaxf(acc, 0.f);
    float p0 = acc * Wc2[lane * 2];
    float p1 = acc * Wc2[lane * 2 + 1];
#pragma unroll
    for (int o = 16; o >= 1; o >>= 1) {
        p0 += __shfl_xor_sync(0xffffffffu, p0, o);
        p1 += __shfl_xor_sync(0xffffffffu, p1, o);
    }
    if (lane == 0) {
        out[wid * 2 + 0] = p0 + bc2[0];
        out[wid * 2 + 1] = p1 + bc2[1];
    }
}

// ---------------- launch ----------------
extern "C" void kernel_launch(void* const* d_in, const int* in_sizes, int n_in,
                              void* d_out, int out_size)
{
    const float* x    = (const float*)d_in[0];
    const void*  eia  = d_in[1];
    const void*  eib  = d_in[2];
    const float* W1   = (const float*)d_in[3];
    const float* a1s  = (const float*)d_in[4];
    const float* a1d  = (const float*)d_in[5];
    const float* b1   = (const float*)d_in[6];
    const float* W2   = (const float*)d_in[7];
    const float* a2s  = (const float*)d_in[8];
    const float* a2d  = (const float*)d_in[9];
    const float* b2   = (const float*)d_in[10];
    const float* Wc1  = (const float*)d_in[11];
    const float* bc1  = (const float*)d_in[12];
    const float* Wc2  = (const float*)d_in[13];
    const float* bc2  = (const float*)d_in[14];
    float* out = (float*)d_out;

    void* basev = nullptr;
    cudaGetSymbolAddress(&basev, g_scratch);
    unsigned char* base = (unsigned char*)basev;

    int*      p_csr  = (int*)(base + O_CSR);
    int*      p_cnt  = (int*)(base + O_CNT);
    int*      p_off  = (int*)(base + O_OFF);
    int*      p_cur  = (int*)(base + O_CUR);
    uint16_t* p_xb   = (uint16_t*)(base + O_XB);
    float*    p_h1   = (float*)(base + O_H1);
    float*    p_s1s  = (float*)(base + O_S1S);
    float*    p_s1d  = (float*)(base + O_S1D);
    float*    p_h1c  = (float*)(base + O_H1C);
    float*    p_s2s  = (float*)(base + O_S2S);
    float*    p_s2d  = (float*)(base + O_S2D);
    float*    p_ws   = (float*)(base + O_WS);
    float*    p_wd   = (float*)(base + O_WD);
    float*    p_bc   = (float*)(base + O_BC);
    uint16_t* p_wt1  = (uint16_t*)(base + O_WT1);
    uint16_t* p_wt2  = (uint16_t*)(base + O_WT2);
    uint16_t* p_aggb = (uint16_t*)(base + O_AGGB);
    int*      p_src  = (int*)(base + O_SRC);
    int*      p_dst  = (int*)(base + O_DST);
    float*    p_h2p  = (float*)(base + O_H2P);

    cudaFuncSetAttribute(k_mmagemm<4, 512, 512>,
                         cudaFuncAttributeMaxDynamicSharedMemorySize, 73728);
    cudaFuncSetAttribute(k_mmagemm<32, 4096, 4096>,
                         cudaFuncAttributeMaxDynamicSharedMemorySize, 73728);

    // 1-3: prep (zeros cnt), cvt (+histogram), cvtx
    k_prep<<<(240768 + 255) / 256, 256>>>(W2, a2s, a2d, b2, W1, p_wt1, p_wt2,
                                          p_ws, p_wd, p_bc, p_cnt);
    k_cvt<<<dim3((E_ + 255) / 256, 2), 256>>>(eia, eib, p_src, p_dst, p_cnt);
    k_cvtx<<<(N_ * 64 + 255) / 256, 256>>>(x, p_xb);

    // 4: layer-1 GEMM
    k_mmagemm<4, 512, 512><<<dim3(157, 4, 1), 256, 73728>>>(p_xb, p_wt1, p_h1, N_, 256, 0);

    // 5-6: finish CSR
    k_scan<<<2, 1024>>>(p_cnt, p_off, p_cur);
    k_scatter<<<(2 * E_ + 255) / 256, 256>>>(p_src, p_dst, p_cur, p_csr);

    // 7-9: scores -> gat1 (h1c + layer-2 scores) -> gat2
    k_scores1<<<dim3((N_ + 7) / 8, 2), 256>>>(p_h1, a1s, a1d, p_s1s, p_s1d);
    k_gat1<<<(N_ + 3) / 4, 256>>>(p_off, p_cnt, p_csr, p_s1s, p_s1d, p_h1, b1,
                                  p_h1c, p_ws, p_wd, p_s2s, p_s2d);
    k_gat2<<<(N_ + 3) / 4, 256>>>(p_off, p_cnt, p_csr, p_s2s, p_s2d, p_h1c, p_aggb);

    // 10: layer-2 GEMM, split-K=4
    k_mmagemm<32, 4096, 4096><<<dim3(157, 1, 4), 256, 73728>>>(
        p_aggb, p_wt2, p_h2p, N_, 64, (size_t)N_ * 64);

    // 11: classifier
    k_classifier<<<(N_ * 32 + 255) / 256, 256>>>(p_h2p, p_bc, Wc1, bc1, Wc2, bc2, out);
}

// round 14
// speedup vs baseline: 1.1602x; 1.0259x over previous
#include <cuda_runtime.h>
#include <cuda_bf16.h>
#include <cstdint>
#include <cstddef>

#define N_ 20000
#define E_ 640000
#define MB (1048576ull)

// ---------------- scratch layout ----------------
static const size_t O_CSR  = 0;                // int[2E] 5.12MB
static const size_t O_CNT  = 6*MB;
static const size_t O_OFF  = 7*MB;
static const size_t O_CUR  = 8*MB;
static const size_t O_XB   = 9*MB;             // bf16[20000*512] hi|lo, 20.5MB
static const size_t O_H1   = 30*MB;            // fp32[20000*256] 20.5MB
static const size_t O_S1S  = 51*MB;            // fp32[2*N*8]
static const size_t O_S1D  = 53*MB;
static const size_t O_H1C  = 55*MB;            // fp32[N*128] 10.2MB
static const size_t O_S2S  = 66*MB;
static const size_t O_S2D  = 68*MB;
static const size_t O_WS   = 70*MB;            // fp32[2048]
static const size_t O_WD   = 70*MB + 16384;
static const size_t O_BC   = 70*MB + 32768;
static const size_t O_WT1  = 71*MB;            // bf16[256*512]  [whi|wlo]
static const size_t O_WT2  = 72*MB;            // bf16[64*4096]  [whi|wlo]
static const size_t O_AGGB = 73*MB;            // bf16[20000*4096] hi|lo, 164MB
static const size_t O_SRC  = 73*MB;            // int[2E] temp (dead before AGGB)
static const size_t O_DST  = 79*MB;            // int[2E] temp
static const size_t O_H2P  = 238*MB;           // fp32[4 * N*64] split-K parts
static const size_t SCRATCH_BYTES = 262*MB;

__device__ __align__(1024) unsigned char g_scratch[SCRATCH_BYTES];

__device__ __forceinline__ float eluf(float x) { return x > 0.f ? x : expm1f(x); }
__device__ __forceinline__ float lrelu(float x) { return x > 0.f ? x : 0.2f * x; }

__device__ __forceinline__ void hl_split(float x, uint16_t& h, uint16_t& l) {
    __nv_bfloat16 hb = __float2bfloat16(x);
    h = __bfloat16_as_ushort(hb);
    l = __bfloat16_as_ushort(__float2bfloat16(x - __bfloat162float(hb)));
}

__device__ __forceinline__ void cpa16(uint32_t dst, const void* src, int szbytes) {
    asm volatile("cp.async.cg.shared.global [%0], [%1], 16, %2;"
                 :: "r"(dst), "l"(src), "r"(szbytes));
}

__device__ __forceinline__ void ldsm4(uint32_t* r, uint32_t addr) {
    asm volatile("ldmatrix.sync.aligned.m8n8.x4.shared.b16 {%0,%1,%2,%3}, [%4];"
                 : "=r"(r[0]), "=r"(r[1]), "=r"(r[2]), "=r"(r[3]) : "r"(addr));
}

// packed f32x2 helpers (sm_100+ family feature)
__device__ __forceinline__ uint64_t pk2(float x, float y) {
    uint64_t r;
    asm("mov.b64 %0, {%1, %2};" : "=l"(r) : "f"(x), "f"(y));
    return r;
}
__device__ __forceinline__ void upk2(uint64_t v, float& x, float& y) {
    asm("mov.b64 {%0, %1}, %2;" : "=f"(x), "=f"(y) : "l"(v));
}
__device__ __forceinline__ uint64_t fma2(uint64_t a, uint64_t b, uint64_t c) {
    uint64_t d;
    asm("fma.rn.f32x2 %0, %1, %2, %3;" : "=l"(d) : "l"(a), "l"(b), "l"(c));
    return d;
}
__device__ __forceinline__ uint64_t add2(uint64_t a, uint64_t b) {
    uint64_t d;
    asm("add.rn.f32x2 %0, %1, %2;" : "=l"(d) : "l"(a), "l"(b));
    return d;
}

// ================= pipelined mma.sync bf16 GEMM (128x64 tiles) =================
template<int HA, int LDA, int LDB>
__global__ void __launch_bounds__(256) k_mmagemm(
    const uint16_t* __restrict__ A, const uint16_t* __restrict__ B,
    float* __restrict__ C, int nrows, int ldc, size_t zstride)
{
    extern __shared__ uint16_t sh[];
    uint16_t* Asm = sh;                 // [2][128*72]
    uint16_t* Bsm = sh + 2 * 9216;      // [2][2][64*72]
    int tid = threadIdx.x;
    int wm = tid >> 5, lane = tid & 31;
    int g = lane >> 2, t4 = lane & 3;
    int rowBase = blockIdx.x * 128;
    int colBase = blockIdx.y * 64;
    int span = (2 * HA) / gridDim.z;
    int itBeg = blockIdx.z * span, itEnd = itBeg + span;
    C += (size_t)blockIdx.z * zstride;

    float c[8][4];
#pragma unroll
    for (int i = 0; i < 8; i++)
#pragma unroll
        for (int j = 0; j < 4; j++) c[i][j] = 0.f;

    uint32_t aBase = (uint32_t)__cvta_generic_to_shared(Asm);
    uint32_t bBase = (uint32_t)__cvta_generic_to_shared(Bsm);

    auto issue = [&](int it, int buf) {
#pragma unroll
        for (int i = 0; i < 4; i++) {
            int s = i * 256 + tid;
            int row = s >> 3, k8 = s & 7;
            int gr = rowBase + row;
            const uint16_t* src = A + (size_t)gr * LDA + it * 64 + k8 * 8;
            cpa16(aBase + (buf * 9216 + row * 72 + k8 * 8) * 2, src, (gr < nrows) ? 16 : 0);
        }
        bool ph1 = it < HA;
        int b0 = ph1 ? it * 64 : (it - HA) * 64;
#pragma unroll
        for (int i = 0; i < 2; i++) {
            int s = i * 256 + tid;
            int row = s >> 3, k8 = s & 7;
            cpa16(bBase + (buf * 9216 + row * 72 + k8 * 8) * 2,
                  B + (size_t)(colBase + row) * LDB + b0 + k8 * 8, 16);
        }
        if (ph1) {
            int b1 = (HA + it) * 64;
#pragma unroll
            for (int i = 0; i < 2; i++) {
                int s = i * 256 + tid;
                int row = s >> 3, k8 = s & 7;
                cpa16(bBase + (buf * 9216 + 4608 + row * 72 + k8 * 8) * 2,
                      B + (size_t)(colBase + row) * LDB + b1 + k8 * 8, 16);
            }
        }
        asm volatile("cp.async.commit_group;" ::: "memory");
    };

    issue(itBeg, 0);
    for (int it = itBeg; it < itEnd; it++) {
        int buf = (it - itBeg) & 1;
        if (it + 1 < itEnd) {
            issue(it + 1, buf ^ 1);
            asm volatile("cp.async.wait_group 1;" ::: "memory");
        } else {
            asm volatile("cp.async.wait_group 0;" ::: "memory");
        }
        __syncthreads();
        bool ph1 = it < HA;
#pragma unroll
        for (int ks = 0; ks < 4; ks++) {
            int k0 = ks * 16;
            uint32_t ar[4];
            {
                int row = wm * 16 + (lane & 15);
                int col = k0 + 8 * (lane >> 4);
                ldsm4(ar, aBase + (buf * 9216 + row * 72 + col) * 2);
            }
#pragma unroll
            for (int bt = 0; bt < 2; bt++) {
                if (bt == 1 && !ph1) break;
                uint32_t br[16];
#pragma unroll
                for (int j = 0; j < 4; j++) {
                    int n = j * 16 + 8 * (lane >> 4) + (lane & 7);
                    int col = k0 + 8 * ((lane >> 3) & 1);
                    ldsm4(br + 4 * j, bBase + (buf * 9216 + bt * 4608 + n * 72 + col) * 2);
                }
#pragma unroll
                for (int nf = 0; nf < 8; nf++) {
                    uint32_t b0 = br[4 * (nf >> 1) + 2 * (nf & 1)];
                    uint32_t b1 = br[4 * (nf >> 1) + 2 * (nf & 1) + 1];
                    asm volatile(
                        "mma.sync.aligned.m16n8k16.row.col.f32.bf16.bf16.f32 "
                        "{%0,%1,%2,%3}, {%4,%5,%6,%7}, {%8,%9}, {%0,%1,%2,%3};"
                        : "+f"(c[nf][0]), "+f"(c[nf][1]), "+f"(c[nf][2]), "+f"(c[nf][3])
                        : "r"(ar[0]), "r"(ar[1]), "r"(ar[2]), "r"(ar[3]), "r"(b0), "r"(b1));
                }
            }
        }
        __syncthreads();
    }
    int r0 = rowBase + wm * 16 + g;
    int r1 = r0 + 8;
#pragma unroll
    for (int nf = 0; nf < 8; nf++) {
        int col = colBase + nf * 8 + 2 * t4;
        if (r0 < nrows) *(float2*)(C + (size_t)r0 * ldc + col) = make_float2(c[nf][0], c[nf][1]);
        if (r1 < nrows) *(float2*)(C + (size_t)r1 * ldc + col) = make_float2(c[nf][2], c[nf][3]);
    }
}

// ================= prep (also zeroes cnt) =================
__global__ void k_prep(const float* __restrict__ W2, const float* __restrict__ a2s,
                       const float* __restrict__ a2d, const float* __restrict__ b2,
                       const float* __restrict__ W1,
                       uint16_t* __restrict__ Wt1, uint16_t* __restrict__ Wt2,
                       float* __restrict__ ws, float* __restrict__ wd, float* __restrict__ bc,
                       int* __restrict__ cnt)
{
    int i = blockIdx.x * blockDim.x + threadIdx.x;
    if (i < 131072) {
        int n = i & 63, k = i >> 6;
        int t = k >> 10, r = k & 1023, h = r >> 7, cc = r & 127;
        float wv = W2[t * 65536 + cc * 512 + h * 64 + n] * 0.0625f;
        uint16_t hh, ll; hl_split(wv, hh, ll);
        uint16_t* p = Wt2 + (size_t)n * 4096 + k;
        p[0] = hh; p[2048] = ll;
    } else if (i < 196608) {
        int j = i - 131072;
        int np = j & 255, k = j >> 8;
        int t = np >> 7, n = np & 127;
        float wv = W1[t * 32768 + k * 128 + n];
        uint16_t hh, ll; hl_split(wv, hh, ll);
        uint16_t* p = Wt1 + (size_t)np * 512 + k;
        p[0] = hh; p[256] = ll;
    } else if (i < 198656) {
        int j = i - 196608;
        int t = j >> 10, r = j & 1023, h = r >> 7, cc = r & 127;
        const float* wrow = W2 + t * 65536 + cc * 512 + h * 64;
        const float* av = a2s + t * 512 + h * 64;
        float acc = 0.f;
        for (int o = 0; o < 64; o++) acc += wrow[o] * av[o];
        ws[j] = acc;
    } else if (i < 200704) {
        int j = i - 198656;
        int t = j >> 10, r = j & 1023, h = r >> 7, cc = r & 127;
        const float* wrow = W2 + t * 65536 + cc * 512 + h * 64;
        const float* av = a2d + t * 512 + h * 64;
        float acc = 0.f;
        for (int o = 0; o < 64; o++) acc += wrow[o] * av[o];
        wd[j] = acc;
    } else if (i < 200768) {
        int o = i - 200704;
        bc[o] = 0.5f * (b2[o] + b2[64 + o]);
    } else if (i < 240768) {
        cnt[i - 200768] = 0;
    }
}

// ================= graph preprocessing =================
__global__ void k_cvt(const void* pa, const void* pb, int* src, int* dst, int* cnt) {
    int t = blockIdx.y;
    const void* p = t ? pb : pa;
    unsigned ov = ((const unsigned*)p)[1 + 2 * (threadIdx.x & 31)];
    int is64 = __all_sync(0xffffffffu, ov == 0u);
    int i = blockIdx.x * blockDim.x + threadIdx.x;
    if (i >= E_) return;
    int s, d;
    if (is64) {
        const long long* q = (const long long*)p;
        s = (int)q[i]; d = (int)q[E_ + i];
    } else {
        const int* q = (const int*)p;
        s = q[i]; d = q[E_ + i];
    }
    src[t * E_ + i] = s;
    dst[t * E_ + i] = d;
    atomicAdd(&cnt[t * N_ + d], 1);
}

__global__ void k_cvtx(const float* __restrict__ x, uint16_t* __restrict__ xb) {
    int i = blockIdx.x * blockDim.x + threadIdx.x;
    if (i >= N_ * 64) return;
    int row = i >> 6, k4 = (i & 63) << 2;
    float4 v = ((const float4*)x)[i];
    uint16_t h0, l0, h1, l1, h2, l2, h3, l3;
    hl_split(v.x, h0, l0); hl_split(v.y, h1, l1);
    hl_split(v.z, h2, l2); hl_split(v.w, h3, l3);
    uint2 hi, lo;
    hi.x = (uint32_t)h0 | ((uint32_t)h1 << 16);
    hi.y = (uint32_t)h2 | ((uint32_t)h3 << 16);
    lo.x = (uint32_t)l0 | ((uint32_t)l1 << 16);
    lo.y = (uint32_t)l2 | ((uint32_t)l3 << 16);
    *(uint2*)(xb + (size_t)row * 512 + k4) = hi;
    *(uint2*)(xb + (size_t)row * 512 + 256 + k4) = lo;
}

__global__ void k_scan(const int* __restrict__ cnt, int* __restrict__ offs, int* __restrict__ cur)
{
    int t = blockIdx.x;
    const int4* c4 = (const int4*)(cnt + t * N_);
    int4* o4 = (int4*)(offs + t * N_);
    int4* q4 = (int4*)(cur + t * N_);
    __shared__ int wsum[32];
    __shared__ int sbase;
    int tid = threadIdx.x, lane = tid & 31, w = tid >> 5;
    if (tid == 0) sbase = 0;
    __syncthreads();
    const int N4 = N_ / 4;
    for (int i0 = 0; i0 < N4; i0 += 1024) {
        int i = i0 + tid;
        int4 c = make_int4(0, 0, 0, 0);
        if (i < N4) c = c4[i];
        int s = c.x + c.y + c.z + c.w;
        int x = s;
#pragma unroll
        for (int ofs = 1; ofs < 32; ofs <<= 1) {
            int y = __shfl_up_sync(0xffffffffu, x, ofs);
            if (lane >= ofs) x += y;
        }
        if (lane == 31) wsum[w] = x;
        __syncthreads();
        if (w == 0) {
            int v = wsum[lane];
#pragma unroll
            for (int ofs = 1; ofs < 32; ofs <<= 1) {
                int y = __shfl_up_sync(0xffffffffu, v, ofs);
                if (lane >= ofs) v += y;
            }
            wsum[lane] = v;
        }
        __syncthreads();
        int excl = sbase + (w ? wsum[w - 1] : 0) + x - s;
        if (i < N4) {
            int4 r;
            r.x = excl; r.y = excl + c.x; r.z = r.y + c.y; r.w = r.z + c.z;
            o4[i] = r; q4[i] = r;
        }
        __syncthreads();
        if (tid == 0) sbase += wsum[31];
        __syncthreads();
    }
}

__global__ void k_scatter(const int* __restrict__ src, const int* __restrict__ dst,
                          int* __restrict__ cur, int* __restrict__ csr)
{
    int i = blockIdx.x * blockDim.x + threadIdx.x;
    if (i >= 2 * E_) return;
    int t = (i >= E_) ? 1 : 0;
    int e = i - t * E_;
    int s = src[t * E_ + e], d = dst[t * E_ + e];
    int pos = atomicAdd(&cur[t * N_ + d], 1);
    csr[(size_t)t * E_ + pos] = s;
}

// ---------------- layer-1 scores ----------------
__global__ void k_scores1(const float* __restrict__ h1,
                          const float* __restrict__ a_src, const float* __restrict__ a_dst,
                          float* __restrict__ ss, float* __restrict__ sd)
{
    int node = blockIdx.x * 8 + (threadIdx.x >> 5);
    int lane = threadIdx.x & 31;
    int t = blockIdx.y;
    if (node >= N_) return;
    const float* hr = h1 + (size_t)node * 256 + t * 128;
    float4 v = *(const float4*)(hr + lane * 4);
    float4 w = *(const float4*)(a_src + t * 128 + lane * 4);
    float4 u = *(const float4*)(a_dst + t * 128 + lane * 4);
    float ps = v.x * w.x + v.y * w.y + v.z * w.z + v.w * w.w;
    float pd = v.x * u.x + v.y * u.y + v.z * u.z + v.w * u.w;
    ps += __shfl_xor_sync(0xffffffffu, ps, 1);
    ps += __shfl_xor_sync(0xffffffffu, ps, 2);
    pd += __shfl_xor_sync(0xffffffffu, pd, 1);
    pd += __shfl_xor_sync(0xffffffffu, pd, 2);
    if ((lane & 3) == 0) {
        ss[t * N_ * 8 + node * 8 + (lane >> 2)] = ps;
        sd[t * N_ * 8 + node * 8 + (lane >> 2)] = pd;
    }
}

// ---------------- layer-1 GAT: single pass, fused scores2 ----------------
__global__ void __launch_bounds__(256) k_gat1(
    const int* __restrict__ offs, const int* __restrict__ cnt, const int* __restrict__ csr,
    const float* __restrict__ s1s, const float* __restrict__ s1d,
    const float* __restrict__ h1, const float* __restrict__ b1,
    float* __restrict__ h1c,
    const float* __restrict__ ws, const float* __restrict__ wd,
    float* __restrict__ s2s, float* __restrict__ s2d)
{
    __shared__ float sa[8][256];
    __shared__ float4 accs[8][32];
    int w = threadIdx.x >> 5, lane = threadIdx.x & 31;
    int d = blockIdx.x * 4 + (w >> 1);
    int t = w & 1;
    int hd = lane >> 2;
    float4 acc = make_float4(0.f, 0.f, 0.f, 0.f);
    if (d < N_) {
        int beg = offs[t * N_ + d], n = cnt[t * N_ + d];
        const float* ss = s1s + (size_t)t * N_ * 8;
        const float4* sdp = (const float4*)(s1d + ((size_t)t * N_ + d) * 8);
        float4 sd0 = sdp[0], sd1 = sdp[1];
        float sdv[8] = {sd0.x, sd0.y, sd0.z, sd0.w, sd1.x, sd1.y, sd1.z, sd1.w};
        const int* cs = csr + (size_t)t * E_ + beg;
        float zp = 0.f;
        for (int c0 = 0; c0 < n; c0 += 32) {
            int m = n - c0; if (m > 32) m = 32;
            int sL = 0;
            if (lane < m) {
                sL = cs[c0 + lane];
                float4 a0 = *(const float4*)(ss + (size_t)sL * 8);
                float4 a1 = *(const float4*)(ss + (size_t)sL * 8 + 4);
                float4 e0, e1;
                e0.x = __expf(lrelu(a0.x + sdv[0]));
                e0.y = __expf(lrelu(a0.y + sdv[1]));
                e0.z = __expf(lrelu(a0.z + sdv[2]));
                e0.w = __expf(lrelu(a0.w + sdv[3]));
                e1.x = __expf(lrelu(a1.x + sdv[4]));
                e1.y = __expf(lrelu(a1.y + sdv[5]));
                e1.z = __expf(lrelu(a1.z + sdv[6]));
                e1.w = __expf(lrelu(a1.w + sdv[7]));
                *(float4*)&sa[w][lane * 8] = e0;
                *(float4*)&sa[w][lane * 8 + 4] = e1;
            }
            __syncwarp();
#pragma unroll
            for (int j = 0; j < 32; j++) {
                if (j < m) {
                    int sj = __shfl_sync(0xffffffffu, sL, j);
                    float a = sa[w][j * 8 + hd];
                    zp += a;
                    float4 v = *(const float4*)(h1 + (size_t)sj * 256 + t * 128 + lane * 4);
                    acc.x = fmaf(a, v.x, acc.x);
                    acc.y = fmaf(a, v.y, acc.y);
                    acc.z = fmaf(a, v.z, acc.z);
                    acc.w = fmaf(a, v.w, acc.w);
                }
            }
            __syncwarp();
        }
        float inv = (zp > 0.f) ? 1.f / zp : 0.f;
        acc.x *= inv; acc.y *= inv; acc.z *= inv; acc.w *= inv;
    }
    accs[w][lane] = acc;
    __syncthreads();
    if (t == 0 && d < N_) {
        float4 a0 = accs[w][lane], a1 = accs[w + 1][lane];
        float4 bb0 = *(const float4*)(b1 + lane * 4);
        float4 bb1 = *(const float4*)(b1 + 128 + lane * 4);
        float4 r;
        r.x = eluf(0.5f * (a0.x + a1.x + bb0.x + bb1.x));
        r.y = eluf(0.5f * (a0.y + a1.y + bb0.y + bb1.y));
        r.z = eluf(0.5f * (a0.z + a1.z + bb0.z + bb1.z));
        r.w = eluf(0.5f * (a0.w + a1.w + bb0.w + bb1.w));
        *(float4*)(h1c + (size_t)d * 128 + lane * 4) = r;
#pragma unroll
        for (int c = 0; c < 16; c++) {
            float4 wv = *(const float4*)(ws + c * 128 + lane * 4);
            float p = r.x * wv.x + r.y * wv.y + r.z * wv.z + r.w * wv.w;
            p += __shfl_xor_sync(0xffffffffu, p, 16);
            p += __shfl_xor_sync(0xffffffffu, p, 8);
            p += __shfl_xor_sync(0xffffffffu, p, 4);
            p += __shfl_xor_sync(0xffffffffu, p, 2);
            p += __shfl_xor_sync(0xffffffffu, p, 1);
            float4 uv = *(const float4*)(wd + c * 128 + lane * 4);
            float q = r.x * uv.x + r.y * uv.y + r.z * uv.z + r.w * uv.w;
            q += __shfl_xor_sync(0xffffffffu, q, 16);
            q += __shfl_xor_sync(0xffffffffu, q, 8);
            q += __shfl_xor_sync(0xffffffffu, q, 4);
            q += __shfl_xor_sync(0xffffffffu, q, 2);
            q += __shfl_xor_sync(0xffffffffu, q, 1);
            if (lane == 0) {
                s2s[(c >> 3) * N_ * 8 + d * 8 + (c & 7)] = p;
                s2d[(c >> 3) * N_ * 8 + d * 8 + (c & 7)] = q;
            }
        }
    }
}

// ---------------- layer-2 aggregate: single pass, packed f32x2 FMAs ----------------
__global__ void __launch_bounds__(256) k_gat2(
    const int* __restrict__ offs, const int* __restrict__ cnt, const int* __restrict__ csr,
    const float* __restrict__ s2s, const float* __restrict__ s2d,
    const float* __restrict__ h1c, uint16_t* __restrict__ aggb)
{
    __shared__ float sa[8][256];
    int w = threadIdx.x >> 5, lane = threadIdx.x & 31;
    int d = blockIdx.x * 4 + (w >> 1);
    int t = w & 1;
    if (d >= N_) return;
    int beg = offs[t * N_ + d], n = cnt[t * N_ + d];
    const float* ss = s2s + (size_t)t * N_ * 8;
    const float4* sdp = (const float4*)(s2d + ((size_t)t * N_ + d) * 8);
    float4 sd0 = sdp[0], sd1 = sdp[1];
    float sdv[8] = {sd0.x, sd0.y, sd0.z, sd0.w, sd1.x, sd1.y, sd1.z, sd1.w};
    const int* cs = csr + (size_t)t * E_ + beg;
    uint64_t z2[4];
#pragma unroll
    for (int k = 0; k < 4; k++) z2[k] = pk2(0.f, 0.f);
    uint64_t acc2[4][4];   // [component][head-pair]
#pragma unroll
    for (int cc = 0; cc < 4; cc++)
#pragma unroll
        for (int hp = 0; hp < 4; hp++) acc2[cc][hp] = pk2(0.f, 0.f);

    for (int c0 = 0; c0 < n; c0 += 32) {
        int m = n - c0; if (m > 32) m = 32;
        int sL = 0;
        if (lane < m) {
            sL = cs[c0 + lane];
            float4 a0 = *(const float4*)(ss + (size_t)sL * 8);
            float4 a1 = *(const float4*)(ss + (size_t)sL * 8 + 4);
            float4 e0, e1;
            e0.x = __expf(lrelu(a0.x + sdv[0]));
            e0.y = __expf(lrelu(a0.y + sdv[1]));
            e0.z = __expf(lrelu(a0.z + sdv[2]));
            e0.w = __expf(lrelu(a0.w + sdv[3]));
            e1.x = __expf(lrelu(a1.x + sdv[4]));
            e1.y = __expf(lrelu(a1.y + sdv[5]));
            e1.z = __expf(lrelu(a1.z + sdv[6]));
            e1.w = __expf(lrelu(a1.w + sdv[7]));
            *(float4*)&sa[w][lane * 8] = e0;
            *(float4*)&sa[w][lane * 8 + 4] = e1;
        }
        __syncwarp();
#pragma unroll
        for (int j = 0; j < 32; j++) {
            if (j < m) {
                int sj = __shfl_sync(0xffffffffu, sL, j);
                uint64_t a01 = *(const uint64_t*)&sa[w][j * 8];
                uint64_t a23 = *(const uint64_t*)&sa[w][j * 8 + 2];
                uint64_t a45 = *(const uint64_t*)&sa[w][j * 8 + 4];
                uint64_t a67 = *(const uint64_t*)&sa[w][j * 8 + 6];
                z2[0] = add2(z2[0], a01);
                z2[1] = add2(z2[1], a23);
                z2[2] = add2(z2[2], a45);
                z2[3] = add2(z2[3], a67);
                float4 v = *(const float4*)(h1c + (size_t)sj * 128 + lane * 4);
                uint64_t vb[4];
                vb[0] = pk2(v.x, v.x); vb[1] = pk2(v.y, v.y);
                vb[2] = pk2(v.z, v.z); vb[3] = pk2(v.w, v.w);
#pragma unroll
                for (int cc = 0; cc < 4; cc++) {
                    acc2[cc][0] = fma2(a01, vb[cc], acc2[cc][0]);
                    acc2[cc][1] = fma2(a23, vb[cc], acc2[cc][1]);
                    acc2[cc][2] = fma2(a45, vb[cc], acc2[cc][2]);
                    acc2[cc][3] = fma2(a67, vb[cc], acc2[cc][3]);
                }
            }
        }
        __syncwarp();
    }
    float z8[8];
#pragma unroll
    for (int hp = 0; hp < 4; hp++) upk2(z2[hp], z8[2 * hp], z8[2 * hp + 1]);
#pragma unroll
    for (int h = 0; h < 8; h++) {
        float inv = (z8[h] > 0.f) ? 1.f / z8[h] : 0.f;
        float ax, ay, az, aw, dummy;
        int hp = h >> 1;
        if ((h & 1) == 0) {
            upk2(acc2[0][hp], ax, dummy);
            upk2(acc2[1][hp], ay, dummy);
            upk2(acc2[2][hp], az, dummy);
            upk2(acc2[3][hp], aw, dummy);
        } else {
            upk2(acc2[0][hp], dummy, ax);
            upk2(acc2[1][hp], dummy, ay);
            upk2(acc2[2][hp], dummy, az);
            upk2(acc2[3][hp], dummy, aw);
        }
        ax *= inv; ay *= inv; az *= inv; aw *= inv;
        uint16_t h0, l0, h1v, l1, h2, l2, h3, l3;
        hl_split(ax, h0, l0); hl_split(ay, h1v, l1);
        hl_split(az, h2, l2); hl_split(aw, h3, l3);
        uint2 hi, lo;
        hi.x = (uint32_t)h0 | ((uint32_t)h1v << 16);
        hi.y = (uint32_t)h2 | ((uint32_t)h3 << 16);
        lo.x = (uint32_t)l0 | ((uint32_t)l1 << 16);
        lo.y = (uint32_t)l2 | ((uint32_t)l3 << 16);
        int k = t * 1024 + h * 128 + lane * 4;
        *(uint2*)(aggb + (size_t)d * 4096 + k) = hi;
        *(uint2*)(aggb + (size_t)d * 4096 + 2048 + k) = lo;
    }
}

// ---------------- classifier (sums 4 split-K parts, bias + ELU fused) ----------------
__global__ void k_classifier(const float* __restrict__ h, const float* __restrict__ bc,
                             const float* __restrict__ Wc1, const float* __restrict__ bc1,
                             const float* __restrict__ Wc2, const float* __restrict__ bc2,
                             float* __restrict__ out)
{
    int wid = (blockIdx.x * blockDim.x + threadIdx.x) >> 5;
    int lane = threadIdx.x & 31;
    if (wid >= N_) return;
    const float* hr0 = h + (size_t)wid * 64;
    const float* hr1 = hr0 + (size_t)N_ * 64;
    const float* hr2 = hr1 + (size_t)N_ * 64;
    const float* hr3 = hr2 + (size_t)N_ * 64;
    float acc = bc1[lane];
#pragma unroll
    for (int c = 0; c < 64; c++) {
        float hv = eluf(__ldg(hr0 + c) + __ldg(hr1 + c) + __ldg(hr2 + c) + __ldg(hr3 + c)
                        + __ldg(bc + c));
        acc = fmaf(hv, Wc1[c * 32 + lane], acc);
    }
    acc = fmaxf(acc, 0.f);
    float p0 = acc * Wc2[lane * 2];
    float p1 = acc * Wc2[lane * 2 + 1];
#pragma unroll
    for (int o = 16; o >= 1; o >>= 1) {
        p0 += __shfl_xor_sync(0xffffffffu, p0, o);
        p1 += __shfl_xor_sync(0xffffffffu, p1, o);
    }
    if (lane == 0) {
        out[wid * 2 + 0] = p0 + bc2[0];
        out[wid * 2 + 1] = p1 + bc2[1];
    }
}

// ---------------- launch ----------------
extern "C" void kernel_launch(void* const* d_in, const int* in_sizes, int n_in,
                              void* d_out, int out_size)
{
    const float* x    = (const float*)d_in[0];
    const void*  eia  = d_in[1];
    const void*  eib  = d_in[2];
    const float* W1   = (const float*)d_in[3];
    const float* a1s  = (const float*)d_in[4];
    const float* a1d  = (const float*)d_in[5];
    const float* b1   = (const float*)d_in[6];
    const float* W2   = (const float*)d_in[7];
    const float* a2s  = (const float*)d_in[8];
    const float* a2d  = (const float*)d_in[9];
    const float* b2   = (const float*)d_in[10];
    const float* Wc1  = (const float*)d_in[11];
    const float* bc1  = (const float*)d_in[12];
    const float* Wc2  = (const float*)d_in[13];
    const float* bc2  = (const float*)d_in[14];
    float* out = (float*)d_out;

    void* basev = nullptr;
    cudaGetSymbolAddress(&basev, g_scratch);
    unsigned char* base = (unsigned char*)basev;

    int*      p_csr  = (int*)(base + O_CSR);
    int*      p_cnt  = (int*)(base + O_CNT);
    int*      p_off  = (int*)(base + O_OFF);
    int*      p_cur  = (int*)(base + O_CUR);
    uint16_t* p_xb   = (uint16_t*)(base + O_XB);
    float*    p_h1   = (float*)(base + O_H1);
    float*    p_s1s  = (float*)(base + O_S1S);
    float*    p_s1d  = (float*)(base + O_S1D);
    float*    p_h1c  = (float*)(base + O_H1C);
    float*    p_s2s  = (float*)(base + O_S2S);
    float*    p_s2d  = (float*)(base + O_S2D);
    float*    p_ws   = (float*)(base + O_WS);
    float*    p_wd   = (float*)(base + O_WD);
    float*    p_bc   = (float*)(base + O_BC);
    uint16_t* p_wt1  = (uint16_t*)(base + O_WT1);
    uint16_t* p_wt2  = (uint16_t*)(base + O_WT2);
    uint16_t* p_aggb = (uint16_t*)(base + O_AGGB);
    int*      p_src  = (int*)(base + O_SRC);
    int*      p_dst  = (int*)(base + O_DST);
    float*    p_h2p  = (float*)(base + O_H2P);

    cudaFuncSetAttribute(k_mmagemm<4, 512, 512>,
                         cudaFuncAttributeMaxDynamicSharedMemorySize, 73728);
    cudaFuncSetAttribute(k_mmagemm<32, 4096, 4096>,
                         cudaFuncAttributeMaxDynamicSharedMemorySize, 73728);

    // 1-3: prep (zeros cnt), cvt (+histogram), cvtx
    k_prep<<<(240768 + 255) / 256, 256>>>(W2, a2s, a2d, b2, W1, p_wt1, p_wt2,
                                          p_ws, p_wd, p_bc, p_cnt);
    k_cvt<<<dim3((E_ + 255) / 256, 2), 256>>>(eia, eib, p_src, p_dst, p_cnt);
    k_cvtx<<<(N_ * 64 + 255) / 256, 256>>>(x, p_xb);

    // 4: layer-1 GEMM
    k_mmagemm<4, 512, 512><<<dim3(157, 4, 1), 256, 73728>>>(p_xb, p_wt1, p_h1, N_, 256, 0);

    // 5-6: finish CSR
    k_scan<<<2, 1024>>>(p_cnt, p_off, p_cur);
    k_scatter<<<(2 * E_ + 255) / 256, 256>>>(p_src, p_dst, p_cur, p_csr);

    // 7-9: scores -> gat1 (h1c + layer-2 scores) -> gat2
    k_scores1<<<dim3((N_ + 7) / 8, 2), 256>>>(p_h1, a1s, a1d, p_s1s, p_s1d);
    k_gat1<<<(N_ + 3) / 4, 256>>>(p_off, p_cnt, p_csr, p_s1s, p_s1d, p_h1, b1,
                                  p_h1c, p_ws, p_wd, p_s2s, p_s2d);
    k_gat2<<<(N_ + 3) / 4, 256>>>(p_off, p_cnt, p_csr, p_s2s, p_s2d, p_h1c, p_aggb);

    // 10: layer-2 GEMM, split-K=4
    k_mmagemm<32, 4096, 4096><<<dim3(157, 1, 4), 256, 73728>>>(
        p_aggb, p_wt2, p_h2p, N_, 64, (size_t)N_ * 64);

    // 11: classifier
    k_classifier<<<(N_ * 32 + 255) / 256, 256>>>(p_h2p, p_bc, Wc1, bc1, Wc2, bc2, out);
}

// round 15
// speedup vs baseline: 1.1610x; 1.0007x over previous
#include <cuda_runtime.h>
#include <cuda_bf16.h>
#include <cstdint>
#include <cstddef>

#define N_ 20000
#define E_ 640000
#define MB (1048576ull)

// ---------------- scratch layout ----------------
static const size_t O_CSR  = 0;                // int[2E] 5.12MB
static const size_t O_CNT  = 6*MB;
static const size_t O_OFF  = 7*MB;
static const size_t O_CUR  = 8*MB;
static const size_t O_XB   = 9*MB;             // bf16[20000*512] hi|lo, 20.5MB
static const size_t O_H1   = 30*MB;            // fp32[20000*256] 20.5MB
static const size_t O_S1S  = 51*MB;            // fp32[2*N*8]
static const size_t O_S1D  = 53*MB;
static const size_t O_H1C  = 55*MB;            // fp32[N*128] 10.2MB
static const size_t O_S2S  = 66*MB;
static const size_t O_S2D  = 68*MB;
static const size_t O_WS   = 70*MB;            // fp32[2048]
static const size_t O_WD   = 70*MB + 16384;
static const size_t O_BC   = 70*MB + 32768;
static const size_t O_WT1  = 71*MB;            // bf16[256*512]  [whi|wlo]
static const size_t O_WT2  = 72*MB;            // bf16[64*4096]  [whi|wlo]
static const size_t O_AGGB = 73*MB;            // bf16[20000*4096] hi|lo, 164MB
static const size_t O_SRC  = 73*MB;            // int[2E] temp (dead before AGGB)
static const size_t O_DST  = 79*MB;            // int[2E] temp
static const size_t O_H2P  = 238*MB;           // fp32[4 * N*64] split-K parts
static const size_t SCRATCH_BYTES = 262*MB;

__device__ __align__(1024) unsigned char g_scratch[SCRATCH_BYTES];

__device__ __forceinline__ float eluf(float x) { return x > 0.f ? x : expm1f(x); }
__device__ __forceinline__ float lrelu(float x) { return x > 0.f ? x : 0.2f * x; }

__device__ __forceinline__ void hl_split(float x, uint16_t& h, uint16_t& l) {
    __nv_bfloat16 hb = __float2bfloat16(x);
    h = __bfloat16_as_ushort(hb);
    l = __bfloat16_as_ushort(__float2bfloat16(x - __bfloat162float(hb)));
}

__device__ __forceinline__ void cpa16(uint32_t dst, const void* src, int szbytes) {
    asm volatile("cp.async.cg.shared.global [%0], [%1], 16, %2;"
                 :: "r"(dst), "l"(src), "r"(szbytes));
}

__device__ __forceinline__ void ldsm4(uint32_t* r, uint32_t addr) {
    asm volatile("ldmatrix.sync.aligned.m8n8.x4.shared.b16 {%0,%1,%2,%3}, [%4];"
                 : "=r"(r[0]), "=r"(r[1]), "=r"(r[2]), "=r"(r[3]) : "r"(addr));
}

// packed f32x2 helpers (sm_100+ family feature)
__device__ __forceinline__ uint64_t pk2(float x, float y) {
    uint64_t r;
    asm("mov.b64 %0, {%1, %2};" : "=l"(r) : "f"(x), "f"(y));
    return r;
}
__device__ __forceinline__ void upk2(uint64_t v, float& x, float& y) {
    asm("mov.b64 {%0, %1}, %2;" : "=f"(x), "=f"(y) : "l"(v));
}
__device__ __forceinline__ uint64_t fma2(uint64_t a, uint64_t b, uint64_t c) {
    uint64_t d;
    asm("fma.rn.f32x2 %0, %1, %2, %3;" : "=l"(d) : "l"(a), "l"(b), "l"(c));
    return d;
}
__device__ __forceinline__ uint64_t add2(uint64_t a, uint64_t b) {
    uint64_t d;
    asm("add.rn.f32x2 %0, %1, %2;" : "=l"(d) : "l"(a), "l"(b));
    return d;
}

// ================= pipelined mma.sync bf16 GEMM (128x64 tiles) =================
// FUSE=1 (gemm1): epilogue also computes per-head attention scores.
// Block (bx, by): rows [bx*128,..), cols [by*64,..) of the 256-wide output.
// by encodes (t = by>>1, head-group hb = (by&1)*4); each head's dot = 16 cols,
// fully inside this block's slice -> block-local score computation, no atomics.
template<int HA, int LDA, int LDB, int FUSE>
__global__ void __launch_bounds__(256) k_mmagemm(
    const uint16_t* __restrict__ A, const uint16_t* __restrict__ B,
    float* __restrict__ C, int nrows, int ldc, size_t zstride,
    const float* __restrict__ a_src, const float* __restrict__ a_dst,
    float* __restrict__ ssO, float* __restrict__ sdO)
{
    extern __shared__ uint16_t sh[];
    uint16_t* Asm = sh;                 // [2][128*72]
    uint16_t* Bsm = sh + 2 * 9216;      // [2][2][64*72]
    int tid = threadIdx.x;
    int wm = tid >> 5, lane = tid & 31;
    int g = lane >> 2, t4 = lane & 3;
    int rowBase = blockIdx.x * 128;
    int colBase = blockIdx.y * 64;
    int span = (2 * HA) / gridDim.z;
    int itBeg = blockIdx.z * span, itEnd = itBeg + span;
    C += (size_t)blockIdx.z * zstride;

    float c[8][4];
#pragma unroll
    for (int i = 0; i < 8; i++)
#pragma unroll
        for (int j = 0; j < 4; j++) c[i][j] = 0.f;

    uint32_t aBase = (uint32_t)__cvta_generic_to_shared(Asm);
    uint32_t bBase = (uint32_t)__cvta_generic_to_shared(Bsm);

    auto issue = [&](int it, int buf) {
#pragma unroll
        for (int i = 0; i < 4; i++) {
            int s = i * 256 + tid;
            int row = s >> 3, k8 = s & 7;
            int gr = rowBase + row;
            const uint16_t* src = A + (size_t)gr * LDA + it * 64 + k8 * 8;
            cpa16(aBase + (buf * 9216 + row * 72 + k8 * 8) * 2, src, (gr < nrows) ? 16 : 0);
        }
        bool ph1 = it < HA;
        int b0 = ph1 ? it * 64 : (it - HA) * 64;
#pragma unroll
        for (int i = 0; i < 2; i++) {
            int s = i * 256 + tid;
            int row = s >> 3, k8 = s & 7;
            cpa16(bBase + (buf * 9216 + row * 72 + k8 * 8) * 2,
                  B + (size_t)(colBase + row) * LDB + b0 + k8 * 8, 16);
        }
        if (ph1) {
            int b1 = (HA + it) * 64;
#pragma unroll
            for (int i = 0; i < 2; i++) {
                int s = i * 256 + tid;
                int row = s >> 3, k8 = s & 7;
                cpa16(bBase + (buf * 9216 + 4608 + row * 72 + k8 * 8) * 2,
                      B + (size_t)(colBase + row) * LDB + b1 + k8 * 8, 16);
            }
        }
        asm volatile("cp.async.commit_group;" ::: "memory");
    };

    issue(itBeg, 0);
    for (int it = itBeg; it < itEnd; it++) {
        int buf = (it - itBeg) & 1;
        if (it + 1 < itEnd) {
            issue(it + 1, buf ^ 1);
            asm volatile("cp.async.wait_group 1;" ::: "memory");
        } else {
            asm volatile("cp.async.wait_group 0;" ::: "memory");
        }
        __syncthreads();
        bool ph1 = it < HA;
#pragma unroll
        for (int ks = 0; ks < 4; ks++) {
            int k0 = ks * 16;
            uint32_t ar[4];
            {
                int row = wm * 16 + (lane & 15);
                int col = k0 + 8 * (lane >> 4);
                ldsm4(ar, aBase + (buf * 9216 + row * 72 + col) * 2);
            }
#pragma unroll
            for (int bt = 0; bt < 2; bt++) {
                if (bt == 1 && !ph1) break;
                uint32_t br[16];
#pragma unroll
                for (int j = 0; j < 4; j++) {
                    int n = j * 16 + 8 * (lane >> 4) + (lane & 7);
                    int col = k0 + 8 * ((lane >> 3) & 1);
                    ldsm4(br + 4 * j, bBase + (buf * 9216 + bt * 4608 + n * 72 + col) * 2);
                }
#pragma unroll
                for (int nf = 0; nf < 8; nf++) {
                    uint32_t b0 = br[4 * (nf >> 1) + 2 * (nf & 1)];
                    uint32_t b1 = br[4 * (nf >> 1) + 2 * (nf & 1) + 1];
                    asm volatile(
                        "mma.sync.aligned.m16n8k16.row.col.f32.bf16.bf16.f32 "
                        "{%0,%1,%2,%3}, {%4,%5,%6,%7}, {%8,%9}, {%0,%1,%2,%3};"
                        : "+f"(c[nf][0]), "+f"(c[nf][1]), "+f"(c[nf][2]), "+f"(c[nf][3])
                        : "r"(ar[0]), "r"(ar[1]), "r"(ar[2]), "r"(ar[3]), "r"(b0), "r"(b1));
                }
            }
        }
        __syncthreads();
    }
    int r0 = rowBase + wm * 16 + g;
    int r1 = r0 + 8;
#pragma unroll
    for (int nf = 0; nf < 8; nf++) {
        int col = colBase + nf * 8 + 2 * t4;
        if (r0 < nrows) *(float2*)(C + (size_t)r0 * ldc + col) = make_float2(c[nf][0], c[nf][1]);
        if (r1 < nrows) *(float2*)(C + (size_t)r1 * ldc + col) = make_float2(c[nf][2], c[nf][3]);
    }
    if (FUSE) {
        // fused attention scores: this block covers heads hb..hb+3 of type t
        int tt = blockIdx.y >> 1;
        int hb = (blockIdx.y & 1) * 4;
        float ps0[4], pd0[4], ps1[4], pd1[4];
#pragma unroll
        for (int hl = 0; hl < 4; hl++) { ps0[hl] = pd0[hl] = ps1[hl] = pd1[hl] = 0.f; }
#pragma unroll
        for (int nf = 0; nf < 8; nf++) {
            int cc = tt * 128 + (blockIdx.y & 1) * 64 + nf * 8 + 2 * t4;
            float as0 = __ldg(a_src + cc), as1 = __ldg(a_src + cc + 1);
            float ad0 = __ldg(a_dst + cc), ad1 = __ldg(a_dst + cc + 1);
            int hl = nf >> 1;
            ps0[hl] += c[nf][0] * as0 + c[nf][1] * as1;
            pd0[hl] += c[nf][0] * ad0 + c[nf][1] * ad1;
            ps1[hl] += c[nf][2] * as0 + c[nf][3] * as1;
            pd1[hl] += c[nf][2] * ad0 + c[nf][3] * ad1;
        }
#pragma unroll
        for (int hl = 0; hl < 4; hl++) {
            ps0[hl] += __shfl_xor_sync(0xffffffffu, ps0[hl], 1);
            ps0[hl] += __shfl_xor_sync(0xffffffffu, ps0[hl], 2);
            pd0[hl] += __shfl_xor_sync(0xffffffffu, pd0[hl], 1);
            pd0[hl] += __shfl_xor_sync(0xffffffffu, pd0[hl], 2);
            ps1[hl] += __shfl_xor_sync(0xffffffffu, ps1[hl], 1);
            ps1[hl] += __shfl_xor_sync(0xffffffffu, ps1[hl], 2);
            pd1[hl] += __shfl_xor_sync(0xffffffffu, pd1[hl], 1);
            pd1[hl] += __shfl_xor_sync(0xffffffffu, pd1[hl], 2);
        }
        if (t4 == 0) {
            float* ssb = ssO + (size_t)tt * N_ * 8;
            float* sdb = sdO + (size_t)tt * N_ * 8;
#pragma unroll
            for (int hl = 0; hl < 4; hl++) {
                if (r0 < nrows) {
                    ssb[r0 * 8 + hb + hl] = ps0[hl];
                    sdb[r0 * 8 + hb + hl] = pd0[hl];
                }
                if (r1 < nrows) {
                    ssb[r1 * 8 + hb + hl] = ps1[hl];
                    sdb[r1 * 8 + hb + hl] = pd1[hl];
                }
            }
        }
    }
}

// ================= prep (also zeroes cnt) =================
__global__ void k_prep(const float* __restrict__ W2, const float* __restrict__ a2s,
                       const float* __restrict__ a2d, const float* __restrict__ b2,
                       const float* __restrict__ W1,
                       uint16_t* __restrict__ Wt1, uint16_t* __restrict__ Wt2,
                       float* __restrict__ ws, float* __restrict__ wd, float* __restrict__ bc,
                       int* __restrict__ cnt)
{
    int i = blockIdx.x * blockDim.x + threadIdx.x;
    if (i < 131072) {
        int n = i & 63, k = i >> 6;
        int t = k >> 10, r = k & 1023, h = r >> 7, cc = r & 127;
        float wv = W2[t * 65536 + cc * 512 + h * 64 + n] * 0.0625f;
        uint16_t hh, ll; hl_split(wv, hh, ll);
        uint16_t* p = Wt2 + (size_t)n * 4096 + k;
        p[0] = hh; p[2048] = ll;
    } else if (i < 196608) {
        int j = i - 131072;
        int np = j & 255, k = j >> 8;
        int t = np >> 7, n = np & 127;
        float wv = W1[t * 32768 + k * 128 + n];
        uint16_t hh, ll; hl_split(wv, hh, ll);
        uint16_t* p = Wt1 + (size_t)np * 512 + k;
        p[0] = hh; p[256] = ll;
    } else if (i < 198656) {
        int j = i - 196608;
        int t = j >> 10, r = j & 1023, h = r >> 7, cc = r & 127;
        const float* wrow = W2 + t * 65536 + cc * 512 + h * 64;
        const float* av = a2s + t * 512 + h * 64;
        float acc = 0.f;
        for (int o = 0; o < 64; o++) acc += wrow[o] * av[o];
        ws[j] = acc;
    } else if (i < 200704) {
        int j = i - 198656;
        int t = j >> 10, r = j & 1023, h = r >> 7, cc = r & 127;
        const float* wrow = W2 + t * 65536 + cc * 512 + h * 64;
        const float* av = a2d + t * 512 + h * 64;
        float acc = 0.f;
        for (int o = 0; o < 64; o++) acc += wrow[o] * av[o];
        wd[j] = acc;
    } else if (i < 200768) {
        int o = i - 200704;
        bc[o] = 0.5f * (b2[o] + b2[64 + o]);
    } else if (i < 240768) {
        cnt[i - 200768] = 0;
    }
}

// ================= graph preprocessing =================
__global__ void k_cvt(const void* pa, const void* pb, int* src, int* dst, int* cnt) {
    int t = blockIdx.y;
    const void* p = t ? pb : pa;
    unsigned ov = ((const unsigned*)p)[1 + 2 * (threadIdx.x & 31)];
    int is64 = __all_sync(0xffffffffu, ov == 0u);
    int i = blockIdx.x * blockDim.x + threadIdx.x;
    if (i >= E_) return;
    int s, d;
    if (is64) {
        const long long* q = (const long long*)p;
        s = (int)q[i]; d = (int)q[E_ + i];
    } else {
        const int* q = (const int*)p;
        s = q[i]; d = q[E_ + i];
    }
    src[t * E_ + i] = s;
    dst[t * E_ + i] = d;
    atomicAdd(&cnt[t * N_ + d], 1);
}

__global__ void k_cvtx(const float* __restrict__ x, uint16_t* __restrict__ xb) {
    int i = blockIdx.x * blockDim.x + threadIdx.x;
    if (i >= N_ * 64) return;
    int row = i >> 6, k4 = (i & 63) << 2;
    float4 v = ((const float4*)x)[i];
    uint16_t h0, l0, h1, l1, h2, l2, h3, l3;
    hl_split(v.x, h0, l0); hl_split(v.y, h1, l1);
    hl_split(v.z, h2, l2); hl_split(v.w, h3, l3);
    uint2 hi, lo;
    hi.x = (uint32_t)h0 | ((uint32_t)h1 << 16);
    hi.y = (uint32_t)h2 | ((uint32_t)h3 << 16);
    lo.x = (uint32_t)l0 | ((uint32_t)l1 << 16);
    lo.y = (uint32_t)l2 | ((uint32_t)l3 << 16);
    *(uint2*)(xb + (size_t)row * 512 + k4) = hi;
    *(uint2*)(xb + (size_t)row * 512 + 256 + k4) = lo;
}

__global__ void k_scan(const int* __restrict__ cnt, int* __restrict__ offs, int* __restrict__ cur)
{
    int t = blockIdx.x;
    const int4* c4 = (const int4*)(cnt + t * N_);
    int4* o4 = (int4*)(offs + t * N_);
    int4* q4 = (int4*)(cur + t * N_);
    __shared__ int wsum[32];
    __shared__ int sbase;
    int tid = threadIdx.x, lane = tid & 31, w = tid >> 5;
    if (tid == 0) sbase = 0;
    __syncthreads();
    const int N4 = N_ / 4;
    for (int i0 = 0; i0 < N4; i0 += 1024) {
        int i = i0 + tid;
        int4 c = make_int4(0, 0, 0, 0);
        if (i < N4) c = c4[i];
        int s = c.x + c.y + c.z + c.w;
        int x = s;
#pragma unroll
        for (int ofs = 1; ofs < 32; ofs <<= 1) {
            int y = __shfl_up_sync(0xffffffffu, x, ofs);
            if (lane >= ofs) x += y;
        }
        if (lane == 31) wsum[w] = x;
        __syncthreads();
        if (w == 0) {
            int v = wsum[lane];
#pragma unroll
            for (int ofs = 1; ofs < 32; ofs <<= 1) {
                int y = __shfl_up_sync(0xffffffffu, v, ofs);
                if (lane >= ofs) v += y;
            }
            wsum[lane] = v;
        }
        __syncthreads();
        int excl = sbase + (w ? wsum[w - 1] : 0) + x - s;
        if (i < N4) {
            int4 r;
            r.x = excl; r.y = excl + c.x; r.z = r.y + c.y; r.w = r.z + c.z;
            o4[i] = r; q4[i] = r;
        }
        __syncthreads();
        if (tid == 0) sbase += wsum[31];
        __syncthreads();
    }
}

__global__ void k_scatter(const int* __restrict__ src, const int* __restrict__ dst,
                          int* __restrict__ cur, int* __restrict__ csr)
{
    int i = blockIdx.x * blockDim.x + threadIdx.x;
    if (i >= 2 * E_) return;
    int t = (i >= E_) ? 1 : 0;
    int e = i - t * E_;
    int s = src[t * E_ + e], d = dst[t * E_ + e];
    int pos = atomicAdd(&cur[t * N_ + d], 1);
    csr[(size_t)t * E_ + pos] = s;
}

// ---------------- layer-1 GAT: single pass, fused scores2 ----------------
__global__ void __launch_bounds__(256) k_gat1(
    const int* __restrict__ offs, const int* __restrict__ cnt, const int* __restrict__ csr,
    const float* __restrict__ s1s, const float* __restrict__ s1d,
    const float* __restrict__ h1, const float* __restrict__ b1,
    float* __restrict__ h1c,
    const float* __restrict__ ws, const float* __restrict__ wd,
    float* __restrict__ s2s, float* __restrict__ s2d)
{
    __shared__ float sa[8][256];
    __shared__ float4 accs[8][32];
    int w = threadIdx.x >> 5, lane = threadIdx.x & 31;
    int d = blockIdx.x * 4 + (w >> 1);
    int t = w & 1;
    int hd = lane >> 2;
    float4 acc = make_float4(0.f, 0.f, 0.f, 0.f);
    if (d < N_) {
        int beg = offs[t * N_ + d], n = cnt[t * N_ + d];
        const float* ss = s1s + (size_t)t * N_ * 8;
        const float4* sdp = (const float4*)(s1d + ((size_t)t * N_ + d) * 8);
        float4 sd0 = sdp[0], sd1 = sdp[1];
        float sdv[8] = {sd0.x, sd0.y, sd0.z, sd0.w, sd1.x, sd1.y, sd1.z, sd1.w};
        const int* cs = csr + (size_t)t * E_ + beg;
        float zp = 0.f;
        for (int c0 = 0; c0 < n; c0 += 32) {
            int m = n - c0; if (m > 32) m = 32;
            int sL = 0;
            if (lane < m) {
                sL = cs[c0 + lane];
                float4 a0 = *(const float4*)(ss + (size_t)sL * 8);
                float4 a1 = *(const float4*)(ss + (size_t)sL * 8 + 4);
                float4 e0, e1;
                e0.x = __expf(lrelu(a0.x + sdv[0]));
                e0.y = __expf(lrelu(a0.y + sdv[1]));
                e0.z = __expf(lrelu(a0.z + sdv[2]));
                e0.w = __expf(lrelu(a0.w + sdv[3]));
                e1.x = __expf(lrelu(a1.x + sdv[4]));
                e1.y = __expf(lrelu(a1.y + sdv[5]));
                e1.z = __expf(lrelu(a1.z + sdv[6]));
                e1.w = __expf(lrelu(a1.w + sdv[7]));
                *(float4*)&sa[w][lane * 8] = e0;
                *(float4*)&sa[w][lane * 8 + 4] = e1;
            }
            __syncwarp();
#pragma unroll
            for (int j = 0; j < 32; j++) {
                if (j < m) {
                    int sj = __shfl_sync(0xffffffffu, sL, j);
                    float a = sa[w][j * 8 + hd];
                    zp += a;
                    float4 v = *(const float4*)(h1 + (size_t)sj * 256 + t * 128 + lane * 4);
                    acc.x = fmaf(a, v.x, acc.x);
                    acc.y = fmaf(a, v.y, acc.y);
                    acc.z = fmaf(a, v.z, acc.z);
                    acc.w = fmaf(a, v.w, acc.w);
                }
            }
            __syncwarp();
        }
        float inv = (zp > 0.f) ? 1.f / zp : 0.f;
        acc.x *= inv; acc.y *= inv; acc.z *= inv; acc.w *= inv;
    }
    accs[w][lane] = acc;
    __syncthreads();
    if (t == 0 && d < N_) {
        float4 a0 = accs[w][lane], a1 = accs[w + 1][lane];
        float4 bb0 = *(const float4*)(b1 + lane * 4);
        float4 bb1 = *(const float4*)(b1 + 128 + lane * 4);
        float4 r;
        r.x = eluf(0.5f * (a0.x + a1.x + bb0.x + bb1.x));
        r.y = eluf(0.5f * (a0.y + a1.y + bb0.y + bb1.y));
        r.z = eluf(0.5f * (a0.z + a1.z + bb0.z + bb1.z));
        r.w = eluf(0.5f * (a0.w + a1.w + bb0.w + bb1.w));
        *(float4*)(h1c + (size_t)d * 128 + lane * 4) = r;
#pragma unroll
        for (int c = 0; c < 16; c++) {
            float4 wv = *(const float4*)(ws + c * 128 + lane * 4);
            float p = r.x * wv.x + r.y * wv.y + r.z * wv.z + r.w * wv.w;
            p += __shfl_xor_sync(0xffffffffu, p, 16);
            p += __shfl_xor_sync(0xffffffffu, p, 8);
            p += __shfl_xor_sync(0xffffffffu, p, 4);
            p += __shfl_xor_sync(0xffffffffu, p, 2);
            p += __shfl_xor_sync(0xffffffffu, p, 1);
            float4 uv = *(const float4*)(wd + c * 128 + lane * 4);
            float q = r.x * uv.x + r.y * uv.y + r.z * uv.z + r.w * uv.w;
            q += __shfl_xor_sync(0xffffffffu, q, 16);
            q += __shfl_xor_sync(0xffffffffu, q, 8);
            q += __shfl_xor_sync(0xffffffffu, q, 4);
            q += __shfl_xor_sync(0xffffffffu, q, 2);
            q += __shfl_xor_sync(0xffffffffu, q, 1);
            if (lane == 0) {
                s2s[(c >> 3) * N_ * 8 + d * 8 + (c & 7)] = p;
                s2d[(c >> 3) * N_ * 8 + d * 8 + (c & 7)] = q;
            }
        }
    }
}

// ---------------- layer-2 aggregate: single pass, packed f32x2 FMAs ----------------
__global__ void __launch_bounds__(256) k_gat2(
    const int* __restrict__ offs, const int* __restrict__ cnt, const int* __restrict__ csr,
    const float* __restrict__ s2s, const float* __restrict__ s2d,
    const float* __restrict__ h1c, uint16_t* __restrict__ aggb)
{
    __shared__ float sa[8][256];
    int w = threadIdx.x >> 5, lane = threadIdx.x & 31;
    int d = blockIdx.x * 4 + (w >> 1);
    int t = w & 1;
    if (d >= N_) return;
    int beg = offs[t * N_ + d], n = cnt[t * N_ + d];
    const float* ss = s2s + (size_t)t * N_ * 8;
    const float4* sdp = (const float4*)(s2d + ((size_t)t * N_ + d) * 8);
    float4 sd0 = sdp[0], sd1 = sdp[1];
    float sdv[8] = {sd0.x, sd0.y, sd0.z, sd0.w, sd1.x, sd1.y, sd1.z, sd1.w};
    const int* cs = csr + (size_t)t * E_ + beg;
    uint64_t z2[4];
#pragma unroll
    for (int k = 0; k < 4; k++) z2[k] = pk2(0.f, 0.f);
    uint64_t acc2[4][4];   // [component][head-pair]
#pragma unroll
    for (int cc = 0; cc < 4; cc++)
#pragma unroll
        for (int hp = 0; hp < 4; hp++) acc2[cc][hp] = pk2(0.f, 0.f);

    for (int c0 = 0; c0 < n; c0 += 32) {
        int m = n - c0; if (m > 32) m = 32;
        int sL = 0;
        if (lane < m) {
            sL = cs[c0 + lane];
            float4 a0 = *(const float4*)(ss + (size_t)sL * 8);
            float4 a1 = *(const float4*)(ss + (size_t)sL * 8 + 4);
            float4 e0, e1;
            e0.x = __expf(lrelu(a0.x + sdv[0]));
            e0.y = __expf(lrelu(a0.y + sdv[1]));
            e0.z = __expf(lrelu(a0.z + sdv[2]));
            e0.w = __expf(lrelu(a0.w + sdv[3]));
            e1.x = __expf(lrelu(a1.x + sdv[4]));
            e1.y = __expf(lrelu(a1.y + sdv[5]));
            e1.z = __expf(lrelu(a1.z + sdv[6]));
            e1.w = __expf(lrelu(a1.w + sdv[7]));
            *(float4*)&sa[w][lane * 8] = e0;
            *(float4*)&sa[w][lane * 8 + 4] = e1;
        }
        __syncwarp();
#pragma unroll
        for (int j = 0; j < 32; j++) {
            if (j < m) {
                int sj = __shfl_sync(0xffffffffu, sL, j);
                uint64_t a01 = *(const uint64_t*)&sa[w][j * 8];
                uint64_t a23 = *(const uint64_t*)&sa[w][j * 8 + 2];
                uint64_t a45 = *(const uint64_t*)&sa[w][j * 8 + 4];
                uint64_t a67 = *(const uint64_t*)&sa[w][j * 8 + 6];
                z2[0] = add2(z2[0], a01);
                z2[1] = add2(z2[1], a23);
                z2[2] = add2(z2[2], a45);
                z2[3] = add2(z2[3], a67);
                float4 v = *(const float4*)(h1c + (size_t)sj * 128 + lane * 4);
                uint64_t vb[4];
                vb[0] = pk2(v.x, v.x); vb[1] = pk2(v.y, v.y);
                vb[2] = pk2(v.z, v.z); vb[3] = pk2(v.w, v.w);
#pragma unroll
                for (int cc = 0; cc < 4; cc++) {
                    acc2[cc][0] = fma2(a01, vb[cc], acc2[cc][0]);
                    acc2[cc][1] = fma2(a23, vb[cc], acc2[cc][1]);
                    acc2[cc][2] = fma2(a45, vb[cc], acc2[cc][2]);
                    acc2[cc][3] = fma2(a67, vb[cc], acc2[cc][3]);
                }
            }
        }
        __syncwarp();
    }
    float z8[8];
#pragma unroll
    for (int hp = 0; hp < 4; hp++) upk2(z2[hp], z8[2 * hp], z8[2 * hp + 1]);
#pragma unroll
    for (int h = 0; h < 8; h++) {
        float inv = (z8[h] > 0.f) ? 1.f / z8[h] : 0.f;
        float ax, ay, az, aw, dummy;
        int hp = h >> 1;
        if ((h & 1) == 0) {
            upk2(acc2[0][hp], ax, dummy);
            upk2(acc2[1][hp], ay, dummy);
            upk2(acc2[2][hp], az, dummy);
            upk2(acc2[3][hp], aw, dummy);
        } else {
            upk2(acc2[0][hp], dummy, ax);
            upk2(acc2[1][hp], dummy, ay);
            upk2(acc2[2][hp], dummy, az);
            upk2(acc2[3][hp], dummy, aw);
        }
        ax *= inv; ay *= inv; az *= inv; aw *= inv;
        uint16_t h0, l0, h1v, l1, h2, l2, h3, l3;
        hl_split(ax, h0, l0); hl_split(ay, h1v, l1);
        hl_split(az, h2, l2); hl_split(aw, h3, l3);
        uint2 hi, lo;
        hi.x = (uint32_t)h0 | ((uint32_t)h1v << 16);
        hi.y = (uint32_t)h2 | ((uint32_t)h3 << 16);
        lo.x = (uint32_t)l0 | ((uint32_t)l1 << 16);
        lo.y = (uint32_t)l2 | ((uint32_t)l3 << 16);
        int k = t * 1024 + h * 128 + lane * 4;
        *(uint2*)(aggb + (size_t)d * 4096 + k) = hi;
        *(uint2*)(aggb + (size_t)d * 4096 + 2048 + k) = lo;
    }
}

// ---------------- classifier (sums 4 split-K parts, bias + ELU fused) ----------------
__global__ void k_classifier(const float* __restrict__ h, const float* __restrict__ bc,
                             const float* __restrict__ Wc1, const float* __restrict__ bc1,
                             const float* __restrict__ Wc2, const float* __restrict__ bc2,
                             float* __restrict__ out)
{
    int wid = (blockIdx.x * blockDim.x + threadIdx.x) >> 5;
    int lane = threadIdx.x & 31;
    if (wid >= N_) return;
    const float* hr0 = h + (size_t)wid * 64;
    const float* hr1 = hr0 + (size_t)N_ * 64;
    const float* hr2 = hr1 + (size_t)N_ * 64;
    const float* hr3 = hr2 + (size_t)N_ * 64;
    float acc = bc1[lane];
#pragma unroll
    for (int c = 0; c < 64; c++) {
        float hv = eluf(__ldg(hr0 + c) + __ldg(hr1 + c) + __ldg(hr2 + c) + __ldg(hr3 + c)
                        + __ldg(bc + c));
        acc = fmaf(hv, Wc1[c * 32 + lane], acc);
    }
    acc = fmaxf(acc, 0.f);
    float p0 = acc * Wc2[lane * 2];
    float p1 = acc * Wc2[lane * 2 + 1];
#pragma unroll
    for (int o = 16; o >= 1; o >>= 1) {
        p0 += __shfl_xor_sync(0xffffffffu, p0, o);
        p1 += __shfl_xor_sync(0xffffffffu, p1, o);
    }
    if (lane == 0) {
        out[wid * 2 + 0] = p0 + bc2[0];
        out[wid * 2 + 1] = p1 + bc2[1];
    }
}

// ---------------- launch ----------------
extern "C" void kernel_launch(void* const* d_in, const int* in_sizes, int n_in,
                              void* d_out, int out_size)
{
    const float* x    = (const float*)d_in[0];
    const void*  eia  = d_in[1];
    const void*  eib  = d_in[2];
    const float* W1   = (const float*)d_in[3];
    const float* a1s  = (const float*)d_in[4];
    const float* a1d  = (const float*)d_in[5];
    const float* b1   = (const float*)d_in[6];
    const float* W2   = (const float*)d_in[7];
    const float* a2s  = (const float*)d_in[8];
    const float* a2d  = (const float*)d_in[9];
    const float* b2   = (const float*)d_in[10];
    const float* Wc1  = (const float*)d_in[11];
    const float* bc1  = (const float*)d_in[12];
    const float* Wc2  = (const float*)d_in[13];
    const float* bc2  = (const float*)d_in[14];
    float* out = (float*)d_out;

    void* basev = nullptr;
    cudaGetSymbolAddress(&basev, g_scratch);
    unsigned char* base = (unsigned char*)basev;

    int*      p_csr  = (int*)(base + O_CSR);
    int*      p_cnt  = (int*)(base + O_CNT);
    int*      p_off  = (int*)(base + O_OFF);
    int*      p_cur  = (int*)(base + O_CUR);
    uint16_t* p_xb   = (uint16_t*)(base + O_XB);
    float*    p_h1   = (float*)(base + O_H1);
    float*    p_s1s  = (float*)(base + O_S1S);
    float*    p_s1d  = (float*)(base + O_S1D);
    float*    p_h1c  = (float*)(base + O_H1C);
    float*    p_s2s  = (float*)(base + O_S2S);
    float*    p_s2d  = (float*)(base + O_S2D);
    float*    p_ws   = (float*)(base + O_WS);
    float*    p_wd   = (float*)(base + O_WD);
    float*    p_bc   = (float*)(base + O_BC);
    uint16_t* p_wt1  = (uint16_t*)(base + O_WT1);
    uint16_t* p_wt2  = (uint16_t*)(base + O_WT2);
    uint16_t* p_aggb = (uint16_t*)(base + O_AGGB);
    int*      p_src  = (int*)(base + O_SRC);
    int*      p_dst  = (int*)(base + O_DST);
    float*    p_h2p  = (float*)(base + O_H2P);

    cudaFuncSetAttribute(k_mmagemm<4, 512, 512, 1>,
                         cudaFuncAttributeMaxDynamicSharedMemorySize, 73728);
    cudaFuncSetAttribute(k_mmagemm<32, 4096, 4096, 0>,
                         cudaFuncAttributeMaxDynamicSharedMemorySize, 73728);

    // 1-3: prep (zeros cnt), cvt (+histogram), cvtx
    k_prep<<<(240768 + 255) / 256, 256>>>(W2, a2s, a2d, b2, W1, p_wt1, p_wt2,
                                          p_ws, p_wd, p_bc, p_cnt);
    k_cvt<<<dim3((E_ + 255) / 256, 2), 256>>>(eia, eib, p_src, p_dst, p_cnt);
    k_cvtx<<<(N_ * 64 + 255) / 256, 256>>>(x, p_xb);

    // 4: layer-1 GEMM with fused attention scores (k_scores1 deleted)
    k_mmagemm<4, 512, 512, 1><<<dim3(157, 4, 1), 256, 73728>>>(
        p_xb, p_wt1, p_h1, N_, 256, 0, a1s, a1d, p_s1s, p_s1d);

    // 5-6: finish CSR
    k_scan<<<2, 1024>>>(p_cnt, p_off, p_cur);
    k_scatter<<<(2 * E_ + 255) / 256, 256>>>(p_src, p_dst, p_cur, p_csr);

    // 7-8: gat1 (h1c + layer-2 scores) -> gat2
    k_gat1<<<(N_ + 3) / 4, 256>>>(p_off, p_cnt, p_csr, p_s1s, p_s1d, p_h1, b1,
                                  p_h1c, p_ws, p_wd, p_s2s, p_s2d);
    k_gat2<<<(N_ + 3) / 4, 256>>>(p_off, p_cnt, p_csr, p_s2s, p_s2d, p_h1c, p_aggb);

    // 9: layer-2 GEMM, split-K=4
    k_mmagemm<32, 4096, 4096, 0><<<dim3(157, 1, 4), 256, 73728>>>(
        p_aggb, p_wt2, p_h2p, N_, 64, (size_t)N_ * 64,
        nullptr, nullptr, nullptr, nullptr);

    // 10: classifier
    k_classifier<<<(N_ * 32 + 255) / 256, 256>>>(p_h2p, p_bc, Wc1, bc1, Wc2, bc2, out);
}

// round 16
// speedup vs baseline: 1.1738x; 1.0110x over previous
#include <cuda_runtime.h>
#include <cuda_bf16.h>
#include <cstdint>
#include <cstddef>

#define N_ 20000
#define E_ 640000
#define MB (1048576ull)

// ---------------- scratch layout ----------------
static const size_t O_CSR  = 0;                // int[2E] 5.12MB
static const size_t O_CNT  = 6*MB;
static const size_t O_OFF  = 7*MB;
static const size_t O_CUR  = 8*MB;
static const size_t O_XB   = 9*MB;             // bf16[20000*512] hi|lo, 20.5MB
static const size_t O_H1   = 30*MB;            // fp32[20000*256] 20.5MB
static const size_t O_S1S  = 51*MB;            // fp32[2*N*8]
static const size_t O_S1D  = 53*MB;
static const size_t O_H1C  = 55*MB;            // fp32[N*128] 10.2MB
static const size_t O_S2S  = 66*MB;
static const size_t O_S2D  = 68*MB;
static const size_t O_WS   = 70*MB;            // fp32[2048]
static const size_t O_WD   = 70*MB + 16384;
static const size_t O_BC   = 70*MB + 32768;
static const size_t O_WT1  = 71*MB;            // bf16[256*512]  [whi|wlo]
static const size_t O_WT2  = 72*MB;            // bf16[64*4096]  [whi|wlo]
static const size_t O_AGGB = 73*MB;            // bf16[20000*4096] hi|lo, 164MB
static const size_t O_SRC  = 73*MB;            // int[2E] temp (dead before AGGB)
static const size_t O_DST  = 79*MB;            // int[2E] temp
static const size_t O_H2P  = 238*MB;           // fp32[4 * N*64] split-K parts
static const size_t SCRATCH_BYTES = 262*MB;

__device__ __align__(1024) unsigned char g_scratch[SCRATCH_BYTES];

__device__ __forceinline__ float eluf(float x) { return x > 0.f ? x : expm1f(x); }
__device__ __forceinline__ float lrelu(float x) { return x > 0.f ? x : 0.2f * x; }

__device__ __forceinline__ void hl_split(float x, uint16_t& h, uint16_t& l) {
    __nv_bfloat16 hb = __float2bfloat16(x);
    h = __bfloat16_as_ushort(hb);
    l = __bfloat16_as_ushort(__float2bfloat16(x - __bfloat162float(hb)));
}

__device__ __forceinline__ void cpa16(uint32_t dst, const void* src, int szbytes) {
    asm volatile("cp.async.cg.shared.global [%0], [%1], 16, %2;"
                 :: "r"(dst), "l"(src), "r"(szbytes));
}

__device__ __forceinline__ void ldsm4(uint32_t* r, uint32_t addr) {
    asm volatile("ldmatrix.sync.aligned.m8n8.x4.shared.b16 {%0,%1,%2,%3}, [%4];"
                 : "=r"(r[0]), "=r"(r[1]), "=r"(r[2]), "=r"(r[3]) : "r"(addr));
}

// packed f32x2 helpers (sm_100+ family feature)
__device__ __forceinline__ uint64_t pk2(float x, float y) {
    uint64_t r;
    asm("mov.b64 %0, {%1, %2};" : "=l"(r) : "f"(x), "f"(y));
    return r;
}
__device__ __forceinline__ void upk2(uint64_t v, float& x, float& y) {
    asm("mov.b64 {%0, %1}, %2;" : "=f"(x), "=f"(y) : "l"(v));
}
__device__ __forceinline__ uint64_t fma2(uint64_t a, uint64_t b, uint64_t c) {
    uint64_t d;
    asm("fma.rn.f32x2 %0, %1, %2, %3;" : "=l"(d) : "l"(a), "l"(b), "l"(c));
    return d;
}
__device__ __forceinline__ uint64_t add2(uint64_t a, uint64_t b) {
    uint64_t d;
    asm("add.rn.f32x2 %0, %1, %2;" : "=l"(d) : "l"(a), "l"(b));
    return d;
}

// ================= pipelined mma.sync bf16 GEMM (128x64 tiles) =================
// FUSE=1 (gemm1): epilogue also computes per-head attention scores.
template<int HA, int LDA, int LDB, int FUSE>
__global__ void __launch_bounds__(256) k_mmagemm(
    const uint16_t* __restrict__ A, const uint16_t* __restrict__ B,
    float* __restrict__ C, int nrows, int ldc, size_t zstride,
    const float* __restrict__ a_src, const float* __restrict__ a_dst,
    float* __restrict__ ssO, float* __restrict__ sdO)
{
    extern __shared__ uint16_t sh[];
    uint16_t* Asm = sh;                 // [2][128*72]
    uint16_t* Bsm = sh + 2 * 9216;      // [2][2][64*72]
    int tid = threadIdx.x;
    int wm = tid >> 5, lane = tid & 31;
    int g = lane >> 2, t4 = lane & 3;
    int rowBase = blockIdx.x * 128;
    int colBase = blockIdx.y * 64;
    int span = (2 * HA) / gridDim.z;
    int itBeg = blockIdx.z * span, itEnd = itBeg + span;
    C += (size_t)blockIdx.z * zstride;

    float c[8][4];
#pragma unroll
    for (int i = 0; i < 8; i++)
#pragma unroll
        for (int j = 0; j < 4; j++) c[i][j] = 0.f;

    uint32_t aBase = (uint32_t)__cvta_generic_to_shared(Asm);
    uint32_t bBase = (uint32_t)__cvta_generic_to_shared(Bsm);

    auto issue = [&](int it, int buf) {
#pragma unroll
        for (int i = 0; i < 4; i++) {
            int s = i * 256 + tid;
            int row = s >> 3, k8 = s & 7;
            int gr = rowBase + row;
            const uint16_t* src = A + (size_t)gr * LDA + it * 64 + k8 * 8;
            cpa16(aBase + (buf * 9216 + row * 72 + k8 * 8) * 2, src, (gr < nrows) ? 16 : 0);
        }
        bool ph1 = it < HA;
        int b0 = ph1 ? it * 64 : (it - HA) * 64;
#pragma unroll
        for (int i = 0; i < 2; i++) {
            int s = i * 256 + tid;
            int row = s >> 3, k8 = s & 7;
            cpa16(bBase + (buf * 9216 + row * 72 + k8 * 8) * 2,
                  B + (size_t)(colBase + row) * LDB + b0 + k8 * 8, 16);
        }
        if (ph1) {
            int b1 = (HA + it) * 64;
#pragma unroll
            for (int i = 0; i < 2; i++) {
                int s = i * 256 + tid;
                int row = s >> 3, k8 = s & 7;
                cpa16(bBase + (buf * 9216 + 4608 + row * 72 + k8 * 8) * 2,
                      B + (size_t)(colBase + row) * LDB + b1 + k8 * 8, 16);
            }
        }
        asm volatile("cp.async.commit_group;" ::: "memory");
    };

    issue(itBeg, 0);
    for (int it = itBeg; it < itEnd; it++) {
        int buf = (it - itBeg) & 1;
        if (it + 1 < itEnd) {
            issue(it + 1, buf ^ 1);
            asm volatile("cp.async.wait_group 1;" ::: "memory");
        } else {
            asm volatile("cp.async.wait_group 0;" ::: "memory");
        }
        __syncthreads();
        bool ph1 = it < HA;
#pragma unroll
        for (int ks = 0; ks < 4; ks++) {
            int k0 = ks * 16;
            uint32_t ar[4];
            {
                int row = wm * 16 + (lane & 15);
                int col = k0 + 8 * (lane >> 4);
                ldsm4(ar, aBase + (buf * 9216 + row * 72 + col) * 2);
            }
#pragma unroll
            for (int bt = 0; bt < 2; bt++) {
                if (bt == 1 && !ph1) break;
                uint32_t br[16];
#pragma unroll
                for (int j = 0; j < 4; j++) {
                    int n = j * 16 + 8 * (lane >> 4) + (lane & 7);
                    int col = k0 + 8 * ((lane >> 3) & 1);
                    ldsm4(br + 4 * j, bBase + (buf * 9216 + bt * 4608 + n * 72 + col) * 2);
                }
#pragma unroll
                for (int nf = 0; nf < 8; nf++) {
                    uint32_t b0 = br[4 * (nf >> 1) + 2 * (nf & 1)];
                    uint32_t b1 = br[4 * (nf >> 1) + 2 * (nf & 1) + 1];
                    asm volatile(
                        "mma.sync.aligned.m16n8k16.row.col.f32.bf16.bf16.f32 "
                        "{%0,%1,%2,%3}, {%4,%5,%6,%7}, {%8,%9}, {%0,%1,%2,%3};"
                        : "+f"(c[nf][0]), "+f"(c[nf][1]), "+f"(c[nf][2]), "+f"(c[nf][3])
                        : "r"(ar[0]), "r"(ar[1]), "r"(ar[2]), "r"(ar[3]), "r"(b0), "r"(b1));
                }
            }
        }
        __syncthreads();
    }
    int r0 = rowBase + wm * 16 + g;
    int r1 = r0 + 8;
#pragma unroll
    for (int nf = 0; nf < 8; nf++) {
        int col = colBase + nf * 8 + 2 * t4;
        if (r0 < nrows) *(float2*)(C + (size_t)r0 * ldc + col) = make_float2(c[nf][0], c[nf][1]);
        if (r1 < nrows) *(float2*)(C + (size_t)r1 * ldc + col) = make_float2(c[nf][2], c[nf][3]);
    }
    if (FUSE) {
        int tt = blockIdx.y >> 1;
        int hb = (blockIdx.y & 1) * 4;
        float ps0[4], pd0[4], ps1[4], pd1[4];
#pragma unroll
        for (int hl = 0; hl < 4; hl++) { ps0[hl] = pd0[hl] = ps1[hl] = pd1[hl] = 0.f; }
#pragma unroll
        for (int nf = 0; nf < 8; nf++) {
            int cc = tt * 128 + (blockIdx.y & 1) * 64 + nf * 8 + 2 * t4;
            float as0 = __ldg(a_src + cc), as1 = __ldg(a_src + cc + 1);
            float ad0 = __ldg(a_dst + cc), ad1 = __ldg(a_dst + cc + 1);
            int hl = nf >> 1;
            ps0[hl] += c[nf][0] * as0 + c[nf][1] * as1;
            pd0[hl] += c[nf][0] * ad0 + c[nf][1] * ad1;
            ps1[hl] += c[nf][2] * as0 + c[nf][3] * as1;
            pd1[hl] += c[nf][2] * ad0 + c[nf][3] * ad1;
        }
#pragma unroll
        for (int hl = 0; hl < 4; hl++) {
            ps0[hl] += __shfl_xor_sync(0xffffffffu, ps0[hl], 1);
            ps0[hl] += __shfl_xor_sync(0xffffffffu, ps0[hl], 2);
            pd0[hl] += __shfl_xor_sync(0xffffffffu, pd0[hl], 1);
            pd0[hl] += __shfl_xor_sync(0xffffffffu, pd0[hl], 2);
            ps1[hl] += __shfl_xor_sync(0xffffffffu, ps1[hl], 1);
            ps1[hl] += __shfl_xor_sync(0xffffffffu, ps1[hl], 2);
            pd1[hl] += __shfl_xor_sync(0xffffffffu, pd1[hl], 1);
            pd1[hl] += __shfl_xor_sync(0xffffffffu, pd1[hl], 2);
        }
        if (t4 == 0) {
            float* ssb = ssO + (size_t)tt * N_ * 8;
            float* sdb = sdO + (size_t)tt * N_ * 8;
#pragma unroll
            for (int hl = 0; hl < 4; hl++) {
                if (r0 < nrows) {
                    ssb[r0 * 8 + hb + hl] = ps0[hl];
                    sdb[r0 * 8 + hb + hl] = pd0[hl];
                }
                if (r1 < nrows) {
                    ssb[r1 * 8 + hb + hl] = ps1[hl];
                    sdb[r1 * 8 + hb + hl] = pd1[hl];
                }
            }
        }
    }
}

// ================= prep (weights, zeroes cnt, and x->bf16 hi/lo) =================
__global__ void k_prep(const float* __restrict__ W2, const float* __restrict__ a2s,
                       const float* __restrict__ a2d, const float* __restrict__ b2,
                       const float* __restrict__ W1, const float* __restrict__ x,
                       uint16_t* __restrict__ Wt1, uint16_t* __restrict__ Wt2,
                       float* __restrict__ ws, float* __restrict__ wd, float* __restrict__ bc,
                       int* __restrict__ cnt, uint16_t* __restrict__ xb)
{
    int i = blockIdx.x * blockDim.x + threadIdx.x;
    if (i < 131072) {
        int n = i & 63, k = i >> 6;
        int t = k >> 10, r = k & 1023, h = r >> 7, cc = r & 127;
        float wv = W2[t * 65536 + cc * 512 + h * 64 + n] * 0.0625f;
        uint16_t hh, ll; hl_split(wv, hh, ll);
        uint16_t* p = Wt2 + (size_t)n * 4096 + k;
        p[0] = hh; p[2048] = ll;
    } else if (i < 196608) {
        int j = i - 131072;
        int np = j & 255, k = j >> 8;
        int t = np >> 7, n = np & 127;
        float wv = W1[t * 32768 + k * 128 + n];
        uint16_t hh, ll; hl_split(wv, hh, ll);
        uint16_t* p = Wt1 + (size_t)np * 512 + k;
        p[0] = hh; p[256] = ll;
    } else if (i < 198656) {
        int j = i - 196608;
        int t = j >> 10, r = j & 1023, h = r >> 7, cc = r & 127;
        const float* wrow = W2 + t * 65536 + cc * 512 + h * 64;
        const float* av = a2s + t * 512 + h * 64;
        float acc = 0.f;
        for (int o = 0; o < 64; o++) acc += wrow[o] * av[o];
        ws[j] = acc;
    } else if (i < 200704) {
        int j = i - 198656;
        int t = j >> 10, r = j & 1023, h = r >> 7, cc = r & 127;
        const float* wrow = W2 + t * 65536 + cc * 512 + h * 64;
        const float* av = a2d + t * 512 + h * 64;
        float acc = 0.f;
        for (int o = 0; o < 64; o++) acc += wrow[o] * av[o];
        wd[j] = acc;
    } else if (i < 200768) {
        int o = i - 200704;
        bc[o] = 0.5f * (b2[o] + b2[64 + o]);
    } else if (i < 240768) {
        cnt[i - 200768] = 0;
    } else if (i < 240768 + N_ * 64) {
        int j = i - 240768;                 // float4 index over x
        int row = j >> 6, k4 = (j & 63) << 2;
        float4 v = ((const float4*)x)[j];
        uint16_t h0, l0, h1, l1, h2, l2, h3, l3;
        hl_split(v.x, h0, l0); hl_split(v.y, h1, l1);
        hl_split(v.z, h2, l2); hl_split(v.w, h3, l3);
        uint2 hi, lo;
        hi.x = (uint32_t)h0 | ((uint32_t)h1 << 16);
        hi.y = (uint32_t)h2 | ((uint32_t)h3 << 16);
        lo.x = (uint32_t)l0 | ((uint32_t)l1 << 16);
        lo.y = (uint32_t)l2 | ((uint32_t)l3 << 16);
        *(uint2*)(xb + (size_t)row * 512 + k4) = hi;
        *(uint2*)(xb + (size_t)row * 512 + 256 + k4) = lo;
    }
}

// ================= graph preprocessing =================
__global__ void k_cvt(const void* pa, const void* pb, int* src, int* dst, int* cnt) {
    int t = blockIdx.y;
    const void* p = t ? pb : pa;
    unsigned ov = ((const unsigned*)p)[1 + 2 * (threadIdx.x & 31)];
    int is64 = __all_sync(0xffffffffu, ov == 0u);
    int i = blockIdx.x * blockDim.x + threadIdx.x;
    if (i >= E_) return;
    int s, d;
    if (is64) {
        const long long* q = (const long long*)p;
        s = (int)q[i]; d = (int)q[E_ + i];
    } else {
        const int* q = (const int*)p;
        s = q[i]; d = q[E_ + i];
    }
    src[t * E_ + i] = s;
    dst[t * E_ + i] = d;
    atomicAdd(&cnt[t * N_ + d], 1);
}

__global__ void k_scan(const int* __restrict__ cnt, int* __restrict__ offs, int* __restrict__ cur)
{
    int t = blockIdx.x;
    const int4* c4 = (const int4*)(cnt + t * N_);
    int4* o4 = (int4*)(offs + t * N_);
    int4* q4 = (int4*)(cur + t * N_);
    __shared__ int wsum[32];
    __shared__ int sbase;
    int tid = threadIdx.x, lane = tid & 31, w = tid >> 5;
    if (tid == 0) sbase = 0;
    __syncthreads();
    const int N4 = N_ / 4;
    for (int i0 = 0; i0 < N4; i0 += 1024) {
        int i = i0 + tid;
        int4 c = make_int4(0, 0, 0, 0);
        if (i < N4) c = c4[i];
        int s = c.x + c.y + c.z + c.w;
        int x = s;
#pragma unroll
        for (int ofs = 1; ofs < 32; ofs <<= 1) {
            int y = __shfl_up_sync(0xffffffffu, x, ofs);
            if (lane >= ofs) x += y;
        }
        if (lane == 31) wsum[w] = x;
        __syncthreads();
        if (w == 0) {
            int v = wsum[lane];
#pragma unroll
            for (int ofs = 1; ofs < 32; ofs <<= 1) {
                int y = __shfl_up_sync(0xffffffffu, v, ofs);
                if (lane >= ofs) v += y;
            }
            wsum[lane] = v;
        }
        __syncthreads();
        int excl = sbase + (w ? wsum[w - 1] : 0) + x - s;
        if (i < N4) {
            int4 r;
            r.x = excl; r.y = excl + c.x; r.z = r.y + c.y; r.w = r.z + c.z;
            o4[i] = r; q4[i] = r;
        }
        __syncthreads();
        if (tid == 0) sbase += wsum[31];
        __syncthreads();
    }
}

__global__ void k_scatter(const int* __restrict__ src, const int* __restrict__ dst,
                          int* __restrict__ cur, int* __restrict__ csr)
{
    int i = blockIdx.x * blockDim.x + threadIdx.x;
    if (i >= 2 * E_) return;
    int t = (i >= E_) ? 1 : 0;
    int e = i - t * E_;
    int s = src[t * E_ + e], d = dst[t * E_ + e];
    int pos = atomicAdd(&cur[t * N_ + d], 1);
    csr[(size_t)t * E_ + pos] = s;
}

// ---------------- layer-1 GAT: single pass, fused scores2 ----------------
__global__ void __launch_bounds__(256) k_gat1(
    const int* __restrict__ offs, const int* __restrict__ cnt, const int* __restrict__ csr,
    const float* __restrict__ s1s, const float* __restrict__ s1d,
    const float* __restrict__ h1, const float* __restrict__ b1,
    float* __restrict__ h1c,
    const float* __restrict__ ws, const float* __restrict__ wd,
    float* __restrict__ s2s, float* __restrict__ s2d)
{
    __shared__ float sa[8][256];
    __shared__ float4 accs[8][32];
    int w = threadIdx.x >> 5, lane = threadIdx.x & 31;
    int d = blockIdx.x * 4 + (w >> 1);
    int t = w & 1;
    int hd = lane >> 2;
    float4 acc = make_float4(0.f, 0.f, 0.f, 0.f);
    if (d < N_) {
        int beg = offs[t * N_ + d], n = cnt[t * N_ + d];
        const float* ss = s1s + (size_t)t * N_ * 8;
        const float4* sdp = (const float4*)(s1d + ((size_t)t * N_ + d) * 8);
        float4 sd0 = sdp[0], sd1 = sdp[1];
        float sdv[8] = {sd0.x, sd0.y, sd0.z, sd0.w, sd1.x, sd1.y, sd1.z, sd1.w};
        const int* cs = csr + (size_t)t * E_ + beg;
        float zp = 0.f;
        for (int c0 = 0; c0 < n; c0 += 32) {
            int m = n - c0; if (m > 32) m = 32;
            int sL = 0;
            if (lane < m) {
                sL = cs[c0 + lane];
                float4 a0 = *(const float4*)(ss + (size_t)sL * 8);
                float4 a1 = *(const float4*)(ss + (size_t)sL * 8 + 4);
                float4 e0, e1;
                e0.x = __expf(lrelu(a0.x + sdv[0]));
                e0.y = __expf(lrelu(a0.y + sdv[1]));
                e0.z = __expf(lrelu(a0.z + sdv[2]));
                e0.w = __expf(lrelu(a0.w + sdv[3]));
                e1.x = __expf(lrelu(a1.x + sdv[4]));
                e1.y = __expf(lrelu(a1.y + sdv[5]));
                e1.z = __expf(lrelu(a1.z + sdv[6]));
                e1.w = __expf(lrelu(a1.w + sdv[7]));
                *(float4*)&sa[w][lane * 8] = e0;
                *(float4*)&sa[w][lane * 8 + 4] = e1;
            }
            __syncwarp();
#pragma unroll
            for (int j = 0; j < 32; j++) {
                if (j < m) {
                    int sj = __shfl_sync(0xffffffffu, sL, j);
                    float a = sa[w][j * 8 + hd];
                    zp += a;
                    float4 v = *(const float4*)(h1 + (size_t)sj * 256 + t * 128 + lane * 4);
                    acc.x = fmaf(a, v.x, acc.x);
                    acc.y = fmaf(a, v.y, acc.y);
                    acc.z = fmaf(a, v.z, acc.z);
                    acc.w = fmaf(a, v.w, acc.w);
                }
            }
            __syncwarp();
        }
        float inv = (zp > 0.f) ? 1.f / zp : 0.f;
        acc.x *= inv; acc.y *= inv; acc.z *= inv; acc.w *= inv;
    }
    accs[w][lane] = acc;
    __syncthreads();
    if (t == 0 && d < N_) {
        float4 a0 = accs[w][lane], a1 = accs[w + 1][lane];
        float4 bb0 = *(const float4*)(b1 + lane * 4);
        float4 bb1 = *(const float4*)(b1 + 128 + lane * 4);
        float4 r;
        r.x = eluf(0.5f * (a0.x + a1.x + bb0.x + bb1.x));
        r.y = eluf(0.5f * (a0.y + a1.y + bb0.y + bb1.y));
        r.z = eluf(0.5f * (a0.z + a1.z + bb0.z + bb1.z));
        r.w = eluf(0.5f * (a0.w + a1.w + bb0.w + bb1.w));
        *(float4*)(h1c + (size_t)d * 128 + lane * 4) = r;
#pragma unroll
        for (int c = 0; c < 16; c++) {
            float4 wv = *(const float4*)(ws + c * 128 + lane * 4);
            float p = r.x * wv.x + r.y * wv.y + r.z * wv.z + r.w * wv.w;
            p += __shfl_xor_sync(0xffffffffu, p, 16);
            p += __shfl_xor_sync(0xffffffffu, p, 8);
            p += __shfl_xor_sync(0xffffffffu, p, 4);
            p += __shfl_xor_sync(0xffffffffu, p, 2);
            p += __shfl_xor_sync(0xffffffffu, p, 1);
            float4 uv = *(const float4*)(wd + c * 128 + lane * 4);
            float q = r.x * uv.x + r.y * uv.y + r.z * uv.z + r.w * uv.w;
            q += __shfl_xor_sync(0xffffffffu, q, 16);
            q += __shfl_xor_sync(0xffffffffu, q, 8);
            q += __shfl_xor_sync(0xffffffffu, q, 4);
            q += __shfl_xor_sync(0xffffffffu, q, 2);
            q += __shfl_xor_sync(0xffffffffu, q, 1);
            if (lane == 0) {
                s2s[(c >> 3) * N_ * 8 + d * 8 + (c & 7)] = p;
                s2d[(c >> 3) * N_ * 8 + d * 8 + (c & 7)] = q;
            }
        }
    }
}

// ---------------- layer-2 aggregate: single pass, packed f32x2 FMAs ----------------
__global__ void __launch_bounds__(256) k_gat2(
    const int* __restrict__ offs, const int* __restrict__ cnt, const int* __restrict__ csr,
    const float* __restrict__ s2s, const float* __restrict__ s2d,
    const float* __restrict__ h1c, uint16_t* __restrict__ aggb)
{
    __shared__ float sa[8][256];
    int w = threadIdx.x >> 5, lane = threadIdx.x & 31;
    int d = blockIdx.x * 4 + (w >> 1);
    int t = w & 1;
    if (d >= N_) return;
    int beg = offs[t * N_ + d], n = cnt[t * N_ + d];
    const float* ss = s2s + (size_t)t * N_ * 8;
    const float4* sdp = (const float4*)(s2d + ((size_t)t * N_ + d) * 8);
    float4 sd0 = sdp[0], sd1 = sdp[1];
    float sdv[8] = {sd0.x, sd0.y, sd0.z, sd0.w, sd1.x, sd1.y, sd1.z, sd1.w};
    const int* cs = csr + (size_t)t * E_ + beg;
    uint64_t z2[4];
#pragma unroll
    for (int k = 0; k < 4; k++) z2[k] = pk2(0.f, 0.f);
    uint64_t acc2[4][4];   // [component][head-pair]
#pragma unroll
    for (int cc = 0; cc < 4; cc++)
#pragma unroll
        for (int hp = 0; hp < 4; hp++) acc2[cc][hp] = pk2(0.f, 0.f);

    for (int c0 = 0; c0 < n; c0 += 32) {
        int m = n - c0; if (m > 32) m = 32;
        int sL = 0;
        if (lane < m) {
            sL = cs[c0 + lane];
            float4 a0 = *(const float4*)(ss + (size_t)sL * 8);
            float4 a1 = *(const float4*)(ss + (size_t)sL * 8 + 4);
            float4 e0, e1;
            e0.x = __expf(lrelu(a0.x + sdv[0]));
            e0.y = __expf(lrelu(a0.y + sdv[1]));
            e0.z = __expf(lrelu(a0.z + sdv[2]));
            e0.w = __expf(lrelu(a0.w + sdv[3]));
            e1.x = __expf(lrelu(a1.x + sdv[4]));
            e1.y = __expf(lrelu(a1.y + sdv[5]));
            e1.z = __expf(lrelu(a1.z + sdv[6]));
            e1.w = __expf(lrelu(a1.w + sdv[7]));
            *(float4*)&sa[w][lane * 8] = e0;
            *(float4*)&sa[w][lane * 8 + 4] = e1;
        }
        __syncwarp();
#pragma unroll
        for (int j = 0; j < 32; j++) {
            if (j < m) {
                int sj = __shfl_sync(0xffffffffu, sL, j);
                uint64_t a01 = *(const uint64_t*)&sa[w][j * 8];
                uint64_t a23 = *(const uint64_t*)&sa[w][j * 8 + 2];
                uint64_t a45 = *(const uint64_t*)&sa[w][j * 8 + 4];
                uint64_t a67 = *(const uint64_t*)&sa[w][j * 8 + 6];
                z2[0] = add2(z2[0], a01);
                z2[1] = add2(z2[1], a23);
                z2[2] = add2(z2[2], a45);
                z2[3] = add2(z2[3], a67);
                float4 v = *(const float4*)(h1c + (size_t)sj * 128 + lane * 4);
                uint64_t vb[4];
                vb[0] = pk2(v.x, v.x); vb[1] = pk2(v.y, v.y);
                vb[2] = pk2(v.z, v.z); vb[3] = pk2(v.w, v.w);
#pragma unroll
                for (int cc = 0; cc < 4; cc++) {
                    acc2[cc][0] = fma2(a01, vb[cc], acc2[cc][0]);
                    acc2[cc][1] = fma2(a23, vb[cc], acc2[cc][1]);
                    acc2[cc][2] = fma2(a45, vb[cc], acc2[cc][2]);
                    acc2[cc][3] = fma2(a67, vb[cc], acc2[cc][3]);
                }
            }
        }
        __syncwarp();
    }
    float z8[8];
#pragma unroll
    for (int hp = 0; hp < 4; hp++) upk2(z2[hp], z8[2 * hp], z8[2 * hp + 1]);
#pragma unroll
    for (int h = 0; h < 8; h++) {
        float inv = (z8[h] > 0.f) ? 1.f / z8[h] : 0.f;
        float ax, ay, az, aw, dummy;
        int hp = h >> 1;
        if ((h & 1) == 0) {
            upk2(acc2[0][hp], ax, dummy);
            upk2(acc2[1][hp], ay, dummy);
            upk2(acc2[2][hp], az, dummy);
            upk2(acc2[3][hp], aw, dummy);
        } else {
            upk2(acc2[0][hp], dummy, ax);
            upk2(acc2[1][hp], dummy, ay);
            upk2(acc2[2][hp], dummy, az);
            upk2(acc2[3][hp], dummy, aw);
        }
        ax *= inv; ay *= inv; az *= inv; aw *= inv;
        uint16_t h0, l0, h1v, l1, h2, l2, h3, l3;
        hl_split(ax, h0, l0); hl_split(ay, h1v, l1);
        hl_split(az, h2, l2); hl_split(aw, h3, l3);
        uint2 hi, lo;
        hi.x = (uint32_t)h0 | ((uint32_t)h1v << 16);
        hi.y = (uint32_t)h2 | ((uint32_t)h3 << 16);
        lo.x = (uint32_t)l0 | ((uint32_t)l1 << 16);
        lo.y = (uint32_t)l2 | ((uint32_t)l3 << 16);
        int k = t * 1024 + h * 128 + lane * 4;
        *(uint2*)(aggb + (size_t)d * 4096 + k) = hi;
        *(uint2*)(aggb + (size_t)d * 4096 + 2048 + k) = lo;
    }
}

// ---------------- classifier (sums 4 split-K parts, bias + ELU fused) ----------------
__global__ void k_classifier(const float* __restrict__ h, const float* __restrict__ bc,
                             const float* __restrict__ Wc1, const float* __restrict__ bc1,
                             const float* __restrict__ Wc2, const float* __restrict__ bc2,
                             float* __restrict__ out)
{
    int wid = (blockIdx.x * blockDim.x + threadIdx.x) >> 5;
    int lane = threadIdx.x & 31;
    if (wid >= N_) return;
    const float* hr0 = h + (size_t)wid * 64;
    const float* hr1 = hr0 + (size_t)N_ * 64;
    const float* hr2 = hr1 + (size_t)N_ * 64;
    const float* hr3 = hr2 + (size_t)N_ * 64;
    float acc = bc1[lane];
#pragma unroll
    for (int c = 0; c < 64; c++) {
        float hv = eluf(__ldg(hr0 + c) + __ldg(hr1 + c) + __ldg(hr2 + c) + __ldg(hr3 + c)
                        + __ldg(bc + c));
        acc = fmaf(hv, Wc1[c * 32 + lane], acc);
    }
    acc = fmaxf(acc, 0.f);
    float p0 = acc * Wc2[lane * 2];
    float p1 = acc * Wc2[lane * 2 + 1];
#pragma unroll
    for (int o = 16; o >= 1; o >>= 1) {
        p0 += __shfl_xor_sync(0xffffffffu, p0, o);
        p1 += __shfl_xor_sync(0xffffffffu, p1, o);
    }
    if (lane == 0) {
        out[wid * 2 + 0] = p0 + bc2[0];
        out[wid * 2 + 1] = p1 + bc2[1];
    }
}

// ---------------- launch ----------------
extern "C" void kernel_launch(void* const* d_in, const int* in_sizes, int n_in,
                              void* d_out, int out_size)
{
    const float* x    = (const float*)d_in[0];
    const void*  eia  = d_in[1];
    const void*  eib  = d_in[2];
    const float* W1   = (const float*)d_in[3];
    const float* a1s  = (const float*)d_in[4];
    const float* a1d  = (const float*)d_in[5];
    const float* b1   = (const float*)d_in[6];
    const float* W2   = (const float*)d_in[7];
    const float* a2s  = (const float*)d_in[8];
    const float* a2d  = (const float*)d_in[9];
    const float* b2   = (const float*)d_in[10];
    const float* Wc1  = (const float*)d_in[11];
    const float* bc1  = (const float*)d_in[12];
    const float* Wc2  = (const float*)d_in[13];
    const float* bc2  = (const float*)d_in[14];
    float* out = (float*)d_out;

    void* basev = nullptr;
    cudaGetSymbolAddress(&basev, g_scratch);
    unsigned char* base = (unsigned char*)basev;

    int*      p_csr  = (int*)(base + O_CSR);
    int*      p_cnt  = (int*)(base + O_CNT);
    int*      p_off  = (int*)(base + O_OFF);
    int*      p_cur  = (int*)(base + O_CUR);
    uint16_t* p_xb   = (uint16_t*)(base + O_XB);
    float*    p_h1   = (float*)(base + O_H1);
    float*    p_s1s  = (float*)(base + O_S1S);
    float*    p_s1d  = (float*)(base + O_S1D);
    float*    p_h1c  = (float*)(base + O_H1C);
    float*    p_s2s  = (float*)(base + O_S2S);
    float*    p_s2d  = (float*)(base + O_S2D);
    float*    p_ws   = (float*)(base + O_WS);
    float*    p_wd   = (float*)(base + O_WD);
    float*    p_bc   = (float*)(base + O_BC);
    uint16_t* p_wt1  = (uint16_t*)(base + O_WT1);
    uint16_t* p_wt2  = (uint16_t*)(base + O_WT2);
    uint16_t* p_aggb = (uint16_t*)(base + O_AGGB);
    int*      p_src  = (int*)(base + O_SRC);
    int*      p_dst  = (int*)(base + O_DST);
    float*    p_h2p  = (float*)(base + O_H2P);

    cudaFuncSetAttribute(k_mmagemm<4, 512, 512, 1>,
                         cudaFuncAttributeMaxDynamicSharedMemorySize, 73728);
    cudaFuncSetAttribute(k_mmagemm<32, 4096, 4096, 0>,
                         cudaFuncAttributeMaxDynamicSharedMemorySize, 73728);

    // 1-2: prep (weights + cnt zero + x->bf16), cvt (+histogram)
    const int PREP_N = 240768 + N_ * 64;
    k_prep<<<(PREP_N + 255) / 256, 256>>>(W2, a2s, a2d, b2, W1, x, p_wt1, p_wt2,
                                          p_ws, p_wd, p_bc, p_cnt, p_xb);
    k_cvt<<<dim3((E_ + 255) / 256, 2), 256>>>(eia, eib, p_src, p_dst, p_cnt);

    // 3: layer-1 GEMM with fused attention scores
    k_mmagemm<4, 512, 512, 1><<<dim3(157, 4, 1), 256, 73728>>>(
        p_xb, p_wt1, p_h1, N_, 256, 0, a1s, a1d, p_s1s, p_s1d);

    // 4-5: finish CSR
    k_scan<<<2, 1024>>>(p_cnt, p_off, p_cur);
    k_scatter<<<(2 * E_ + 255) / 256, 256>>>(p_src, p_dst, p_cur, p_csr);

    // 6-7: gat1 (h1c + layer-2 scores) -> gat2
    k_gat1<<<(N_ + 3) / 4, 256>>>(p_off, p_cnt, p_csr, p_s1s, p_s1d, p_h1, b1,
                                  p_h1c, p_ws, p_wd, p_s2s, p_s2d);
    k_gat2<<<(N_ + 3) / 4, 256>>>(p_off, p_cnt, p_csr, p_s2s, p_s2d, p_h1c, p_aggb);

    // 8: layer-2 GEMM, split-K=4
    k_mmagemm<32, 4096, 4096, 0><<<dim3(157, 1, 4), 256, 73728>>>(
        p_aggb, p_wt2, p_h2p, N_, 64, (size_t)N_ * 64,
        nullptr, nullptr, nullptr, nullptr);

    // 9: classifier
    k_classifier<<<(N_ * 32 + 255) / 256, 256>>>(p_h2p, p_bc, Wc1, bc1, Wc2, bc2, out);
}

// round 17
// speedup vs baseline: 1.2012x; 1.0233x over previous
#include <cuda_runtime.h>
#include <cuda_bf16.h>
#include <cstdint>
#include <cstddef>

#define N_ 20000
#define E_ 640000
#define MB (1048576ull)

// ---------------- scratch layout ----------------
static const size_t O_CSR  = 0;                // int[2E] 5.12MB
static const size_t O_CNT  = 6*MB;
static const size_t O_OFF  = 7*MB;
static const size_t O_CUR  = 8*MB;
static const size_t O_XB   = 9*MB;             // bf16[20000*512] hi|lo, 20.5MB
static const size_t O_H1   = 30*MB;            // fp32[20000*256] 20.5MB
static const size_t O_S1S  = 51*MB;            // fp32[2*N*8]
static const size_t O_S1D  = 53*MB;
static const size_t O_H1C  = 55*MB;            // fp32[N*128] 10.2MB
static const size_t O_S2S  = 66*MB;
static const size_t O_S2D  = 68*MB;
static const size_t O_WS   = 70*MB;            // fp32[2048]
static const size_t O_WD   = 70*MB + 16384;
static const size_t O_BC   = 70*MB + 32768;
static const size_t O_WT1  = 71*MB;            // bf16[256*512]  [whi|wlo]
static const size_t O_WT2  = 72*MB;            // bf16[64*4096]  [whi|wlo]
static const size_t O_AGGB = 73*MB;            // bf16[20000*4096] hi|lo, 164MB
static const size_t O_SRC  = 73*MB;            // int[2E] temp (dead before AGGB)
static const size_t O_DST  = 79*MB;            // int[2E] temp
static const size_t O_H2P  = 238*MB;           // fp32[4 * N*64] split-K parts
static const size_t SCRATCH_BYTES = 262*MB;

__device__ __align__(1024) unsigned char g_scratch[SCRATCH_BYTES];

__device__ __forceinline__ float eluf(float x) { return x > 0.f ? x : expm1f(x); }
__device__ __forceinline__ float lrelu(float x) { return x > 0.f ? x : 0.2f * x; }

__device__ __forceinline__ void hl_split(float x, uint16_t& h, uint16_t& l) {
    __nv_bfloat16 hb = __float2bfloat16(x);
    h = __bfloat16_as_ushort(hb);
    l = __bfloat16_as_ushort(__float2bfloat16(x - __bfloat162float(hb)));
}

__device__ __forceinline__ void cpa16(uint32_t dst, const void* src, int szbytes) {
    asm volatile("cp.async.cg.shared.global [%0], [%1], 16, %2;"
                 :: "r"(dst), "l"(src), "r"(szbytes));
}

__device__ __forceinline__ void ldsm4(uint32_t* r, uint32_t addr) {
    asm volatile("ldmatrix.sync.aligned.m8n8.x4.shared.b16 {%0,%1,%2,%3}, [%4];"
                 : "=r"(r[0]), "=r"(r[1]), "=r"(r[2]), "=r"(r[3]) : "r"(addr));
}

// packed f32x2 helpers (sm_100+ family feature)
__device__ __forceinline__ uint64_t pk2(float x, float y) {
    uint64_t r;
    asm("mov.b64 %0, {%1, %2};" : "=l"(r) : "f"(x), "f"(y));
    return r;
}
__device__ __forceinline__ void upk2(uint64_t v, float& x, float& y) {
    asm("mov.b64 {%0, %1}, %2;" : "=f"(x), "=f"(y) : "l"(v));
}
__device__ __forceinline__ uint64_t fma2(uint64_t a, uint64_t b, uint64_t c) {
    uint64_t d;
    asm("fma.rn.f32x2 %0, %1, %2, %3;" : "=l"(d) : "l"(a), "l"(b), "l"(c));
    return d;
}
__device__ __forceinline__ uint64_t add2(uint64_t a, uint64_t b) {
    uint64_t d;
    asm("add.rn.f32x2 %0, %1, %2;" : "=l"(d) : "l"(a), "l"(b));
    return d;
}

// ================= pipelined mma.sync bf16 GEMM (128x64 tiles) =================
// FUSE=1 (gemm1): epilogue also computes per-head attention scores.
template<int HA, int LDA, int LDB, int FUSE>
__global__ void __launch_bounds__(256) k_mmagemm(
    const uint16_t* __restrict__ A, const uint16_t* __restrict__ B,
    float* __restrict__ C, int nrows, int ldc, size_t zstride,
    const float* __restrict__ a_src, const float* __restrict__ a_dst,
    float* __restrict__ ssO, float* __restrict__ sdO)
{
    extern __shared__ uint16_t sh[];
    uint16_t* Asm = sh;                 // [2][128*72]
    uint16_t* Bsm = sh + 2 * 9216;      // [2][2][64*72]
    int tid = threadIdx.x;
    int wm = tid >> 5, lane = tid & 31;
    int g = lane >> 2, t4 = lane & 3;
    int rowBase = blockIdx.x * 128;
    int colBase = blockIdx.y * 64;
    int span = (2 * HA) / gridDim.z;
    int itBeg = blockIdx.z * span, itEnd = itBeg + span;
    C += (size_t)blockIdx.z * zstride;

    float c[8][4];
#pragma unroll
    for (int i = 0; i < 8; i++)
#pragma unroll
        for (int j = 0; j < 4; j++) c[i][j] = 0.f;

    uint32_t aBase = (uint32_t)__cvta_generic_to_shared(Asm);
    uint32_t bBase = (uint32_t)__cvta_generic_to_shared(Bsm);

    auto issue = [&](int it, int buf) {
#pragma unroll
        for (int i = 0; i < 4; i++) {
            int s = i * 256 + tid;
            int row = s >> 3, k8 = s & 7;
            int gr = rowBase + row;
            const uint16_t* src = A + (size_t)gr * LDA + it * 64 + k8 * 8;
            cpa16(aBase + (buf * 9216 + row * 72 + k8 * 8) * 2, src, (gr < nrows) ? 16 : 0);
        }
        bool ph1 = it < HA;
        int b0 = ph1 ? it * 64 : (it - HA) * 64;
#pragma unroll
        for (int i = 0; i < 2; i++) {
            int s = i * 256 + tid;
            int row = s >> 3, k8 = s & 7;
            cpa16(bBase + (buf * 9216 + row * 72 + k8 * 8) * 2,
                  B + (size_t)(colBase + row) * LDB + b0 + k8 * 8, 16);
        }
        if (ph1) {
            int b1 = (HA + it) * 64;
#pragma unroll
            for (int i = 0; i < 2; i++) {
                int s = i * 256 + tid;
                int row = s >> 3, k8 = s & 7;
                cpa16(bBase + (buf * 9216 + 4608 + row * 72 + k8 * 8) * 2,
                      B + (size_t)(colBase + row) * LDB + b1 + k8 * 8, 16);
            }
        }
        asm volatile("cp.async.commit_group;" ::: "memory");
    };

    issue(itBeg, 0);
    for (int it = itBeg; it < itEnd; it++) {
        int buf = (it - itBeg) & 1;
        if (it + 1 < itEnd) {
            issue(it + 1, buf ^ 1);
            asm volatile("cp.async.wait_group 1;" ::: "memory");
        } else {
            asm volatile("cp.async.wait_group 0;" ::: "memory");
        }
        __syncthreads();
        bool ph1 = it < HA;
#pragma unroll
        for (int ks = 0; ks < 4; ks++) {
            int k0 = ks * 16;
            uint32_t ar[4];
            {
                int row = wm * 16 + (lane & 15);
                int col = k0 + 8 * (lane >> 4);
                ldsm4(ar, aBase + (buf * 9216 + row * 72 + col) * 2);
            }
#pragma unroll
            for (int bt = 0; bt < 2; bt++) {
                if (bt == 1 && !ph1) break;
                uint32_t br[16];
#pragma unroll
                for (int j = 0; j < 4; j++) {
                    int n = j * 16 + 8 * (lane >> 4) + (lane & 7);
                    int col = k0 + 8 * ((lane >> 3) & 1);
                    ldsm4(br + 4 * j, bBase + (buf * 9216 + bt * 4608 + n * 72 + col) * 2);
                }
#pragma unroll
                for (int nf = 0; nf < 8; nf++) {
                    uint32_t b0 = br[4 * (nf >> 1) + 2 * (nf & 1)];
                    uint32_t b1 = br[4 * (nf >> 1) + 2 * (nf & 1) + 1];
                    asm volatile(
                        "mma.sync.aligned.m16n8k16.row.col.f32.bf16.bf16.f32 "
                        "{%0,%1,%2,%3}, {%4,%5,%6,%7}, {%8,%9}, {%0,%1,%2,%3};"
                        : "+f"(c[nf][0]), "+f"(c[nf][1]), "+f"(c[nf][2]), "+f"(c[nf][3])
                        : "r"(ar[0]), "r"(ar[1]), "r"(ar[2]), "r"(ar[3]), "r"(b0), "r"(b1));
                }
            }
        }
        __syncthreads();
    }
    int r0 = rowBase + wm * 16 + g;
    int r1 = r0 + 8;
#pragma unroll
    for (int nf = 0; nf < 8; nf++) {
        int col = colBase + nf * 8 + 2 * t4;
        if (r0 < nrows) *(float2*)(C + (size_t)r0 * ldc + col) = make_float2(c[nf][0], c[nf][1]);
        if (r1 < nrows) *(float2*)(C + (size_t)r1 * ldc + col) = make_float2(c[nf][2], c[nf][3]);
    }
    if (FUSE) {
        int tt = blockIdx.y >> 1;
        int hb = (blockIdx.y & 1) * 4;
        float ps0[4], pd0[4], ps1[4], pd1[4];
#pragma unroll
        for (int hl = 0; hl < 4; hl++) { ps0[hl] = pd0[hl] = ps1[hl] = pd1[hl] = 0.f; }
#pragma unroll
        for (int nf = 0; nf < 8; nf++) {
            int cc = tt * 128 + (blockIdx.y & 1) * 64 + nf * 8 + 2 * t4;
            float as0 = __ldg(a_src + cc), as1 = __ldg(a_src + cc + 1);
            float ad0 = __ldg(a_dst + cc), ad1 = __ldg(a_dst + cc + 1);
            int hl = nf >> 1;
            ps0[hl] += c[nf][0] * as0 + c[nf][1] * as1;
            pd0[hl] += c[nf][0] * ad0 + c[nf][1] * ad1;
            ps1[hl] += c[nf][2] * as0 + c[nf][3] * as1;
            pd1[hl] += c[nf][2] * ad0 + c[nf][3] * ad1;
        }
#pragma unroll
        for (int hl = 0; hl < 4; hl++) {
            ps0[hl] += __shfl_xor_sync(0xffffffffu, ps0[hl], 1);
            ps0[hl] += __shfl_xor_sync(0xffffffffu, ps0[hl], 2);
            pd0[hl] += __shfl_xor_sync(0xffffffffu, pd0[hl], 1);
            pd0[hl] += __shfl_xor_sync(0xffffffffu, pd0[hl], 2);
            ps1[hl] += __shfl_xor_sync(0xffffffffu, ps1[hl], 1);
            ps1[hl] += __shfl_xor_sync(0xffffffffu, ps1[hl], 2);
            pd1[hl] += __shfl_xor_sync(0xffffffffu, pd1[hl], 1);
            pd1[hl] += __shfl_xor_sync(0xffffffffu, pd1[hl], 2);
        }
        if (t4 == 0) {
            float* ssb = ssO + (size_t)tt * N_ * 8;
            float* sdb = sdO + (size_t)tt * N_ * 8;
#pragma unroll
            for (int hl = 0; hl < 4; hl++) {
                if (r0 < nrows) {
                    ssb[r0 * 8 + hb + hl] = ps0[hl];
                    sdb[r0 * 8 + hb + hl] = pd0[hl];
                }
                if (r1 < nrows) {
                    ssb[r1 * 8 + hb + hl] = ps1[hl];
                    sdb[r1 * 8 + hb + hl] = pd1[hl];
                }
            }
        }
    }
}

// ================= prep (weights, zeroes cnt, and x->bf16 hi/lo) =================
__global__ void k_prep(const float* __restrict__ W2, const float* __restrict__ a2s,
                       const float* __restrict__ a2d, const float* __restrict__ b2,
                       const float* __restrict__ W1, const float* __restrict__ x,
                       uint16_t* __restrict__ Wt1, uint16_t* __restrict__ Wt2,
                       float* __restrict__ ws, float* __restrict__ wd, float* __restrict__ bc,
                       int* __restrict__ cnt, uint16_t* __restrict__ xb)
{
    int i = blockIdx.x * blockDim.x + threadIdx.x;
    if (i < 131072) {
        int n = i & 63, k = i >> 6;
        int t = k >> 10, r = k & 1023, h = r >> 7, cc = r & 127;
        float wv = W2[t * 65536 + cc * 512 + h * 64 + n] * 0.0625f;
        uint16_t hh, ll; hl_split(wv, hh, ll);
        uint16_t* p = Wt2 + (size_t)n * 4096 + k;
        p[0] = hh; p[2048] = ll;
    } else if (i < 196608) {
        int j = i - 131072;
        int np = j & 255, k = j >> 8;
        int t = np >> 7, n = np & 127;
        float wv = W1[t * 32768 + k * 128 + n];
        uint16_t hh, ll; hl_split(wv, hh, ll);
        uint16_t* p = Wt1 + (size_t)np * 512 + k;
        p[0] = hh; p[256] = ll;
    } else if (i < 198656) {
        int j = i - 196608;
        int t = j >> 10, r = j & 1023, h = r >> 7, cc = r & 127;
        const float* wrow = W2 + t * 65536 + cc * 512 + h * 64;
        const float* av = a2s + t * 512 + h * 64;
        float acc = 0.f;
        for (int o = 0; o < 64; o++) acc += wrow[o] * av[o];
        ws[j] = acc;
    } else if (i < 200704) {
        int j = i - 198656;
        int t = j >> 10, r = j & 1023, h = r >> 7, cc = r & 127;
        const float* wrow = W2 + t * 65536 + cc * 512 + h * 64;
        const float* av = a2d + t * 512 + h * 64;
        float acc = 0.f;
        for (int o = 0; o < 64; o++) acc += wrow[o] * av[o];
        wd[j] = acc;
    } else if (i < 200768) {
        int o = i - 200704;
        bc[o] = 0.5f * (b2[o] + b2[64 + o]);
    } else if (i < 240768) {
        cnt[i - 200768] = 0;
    } else if (i < 240768 + N_ * 64) {
        int j = i - 240768;                 // float4 index over x
        int row = j >> 6, k4 = (j & 63) << 2;
        float4 v = ((const float4*)x)[j];
        uint16_t h0, l0, h1, l1, h2, l2, h3, l3;
        hl_split(v.x, h0, l0); hl_split(v.y, h1, l1);
        hl_split(v.z, h2, l2); hl_split(v.w, h3, l3);
        uint2 hi, lo;
        hi.x = (uint32_t)h0 | ((uint32_t)h1 << 16);
        hi.y = (uint32_t)h2 | ((uint32_t)h3 << 16);
        lo.x = (uint32_t)l0 | ((uint32_t)l1 << 16);
        lo.y = (uint32_t)l2 | ((uint32_t)l3 << 16);
        *(uint2*)(xb + (size_t)row * 512 + k4) = hi;
        *(uint2*)(xb + (size_t)row * 512 + 256 + k4) = lo;
    }
}

// ================= graph preprocessing =================
__global__ void k_cvt(const void* pa, const void* pb, int* src, int* dst, int* cnt) {
    int t = blockIdx.y;
    const void* p = t ? pb : pa;
    unsigned ov = ((const unsigned*)p)[1 + 2 * (threadIdx.x & 31)];
    int is64 = __all_sync(0xffffffffu, ov == 0u);
    int i = blockIdx.x * blockDim.x + threadIdx.x;
    if (i >= E_) return;
    int s, d;
    if (is64) {
        const long long* q = (const long long*)p;
        s = (int)q[i]; d = (int)q[E_ + i];
    } else {
        const int* q = (const int*)p;
        s = q[i]; d = q[E_ + i];
    }
    src[t * E_ + i] = s;
    dst[t * E_ + i] = d;
    atomicAdd(&cnt[t * N_ + d], 1);
}

__global__ void k_scan(const int* __restrict__ cnt, int* __restrict__ offs, int* __restrict__ cur)
{
    int t = blockIdx.x;
    const int4* c4 = (const int4*)(cnt + t * N_);
    int4* o4 = (int4*)(offs + t * N_);
    int4* q4 = (int4*)(cur + t * N_);
    __shared__ int wsum[32];
    __shared__ int sbase;
    int tid = threadIdx.x, lane = tid & 31, w = tid >> 5;
    if (tid == 0) sbase = 0;
    __syncthreads();
    const int N4 = N_ / 4;
    for (int i0 = 0; i0 < N4; i0 += 1024) {
        int i = i0 + tid;
        int4 c = make_int4(0, 0, 0, 0);
        if (i < N4) c = c4[i];
        int s = c.x + c.y + c.z + c.w;
        int x = s;
#pragma unroll
        for (int ofs = 1; ofs < 32; ofs <<= 1) {
            int y = __shfl_up_sync(0xffffffffu, x, ofs);
            if (lane >= ofs) x += y;
        }
        if (lane == 31) wsum[w] = x;
        __syncthreads();
        if (w == 0) {
            int v = wsum[lane];
#pragma unroll
            for (int ofs = 1; ofs < 32; ofs <<= 1) {
                int y = __shfl_up_sync(0xffffffffu, v, ofs);
                if (lane >= ofs) v += y;
            }
            wsum[lane] = v;
        }
        __syncthreads();
        int excl = sbase + (w ? wsum[w - 1] : 0) + x - s;
        if (i < N4) {
            int4 r;
            r.x = excl; r.y = excl + c.x; r.z = r.y + c.y; r.w = r.z + c.z;
            o4[i] = r; q4[i] = r;
        }
        __syncthreads();
        if (tid == 0) sbase += wsum[31];
        __syncthreads();
    }
}

__global__ void k_scatter(const int* __restrict__ src, const int* __restrict__ dst,
                          int* __restrict__ cur, int* __restrict__ csr)
{
    int i = blockIdx.x * blockDim.x + threadIdx.x;
    if (i >= 2 * E_) return;
    int t = (i >= E_) ? 1 : 0;
    int e = i - t * E_;
    int s = src[t * E_ + e], d = dst[t * E_ + e];
    int pos = atomicAdd(&cur[t * N_ + d], 1);
    csr[(size_t)t * E_ + pos] = s;
}

// ---------------- layer-1 GAT: single pass, fused scores2 ----------------
__global__ void __launch_bounds__(256) k_gat1(
    const int* __restrict__ offs, const int* __restrict__ cnt, const int* __restrict__ csr,
    const float* __restrict__ s1s, const float* __restrict__ s1d,
    const float* __restrict__ h1, const float* __restrict__ b1,
    float* __restrict__ h1c,
    const float* __restrict__ ws, const float* __restrict__ wd,
    float* __restrict__ s2s, float* __restrict__ s2d)
{
    __shared__ float sa[8][256];
    __shared__ float4 accs[8][32];
    int w = threadIdx.x >> 5, lane = threadIdx.x & 31;
    int d = blockIdx.x * 4 + (w >> 1);
    int t = w & 1;
    int hd = lane >> 2;
    float4 acc = make_float4(0.f, 0.f, 0.f, 0.f);
    if (d < N_) {
        int beg = offs[t * N_ + d], n = cnt[t * N_ + d];
        const float* ss = s1s + (size_t)t * N_ * 8;
        const float4* sdp = (const float4*)(s1d + ((size_t)t * N_ + d) * 8);
        float4 sd0 = sdp[0], sd1 = sdp[1];
        float sdv[8] = {sd0.x, sd0.y, sd0.z, sd0.w, sd1.x, sd1.y, sd1.z, sd1.w};
        const int* cs = csr + (size_t)t * E_ + beg;
        float zp = 0.f;
        for (int c0 = 0; c0 < n; c0 += 32) {
            int m = n - c0; if (m > 32) m = 32;
            int sL = 0;
            if (lane < m) {
                sL = cs[c0 + lane];
                float4 a0 = *(const float4*)(ss + (size_t)sL * 8);
                float4 a1 = *(const float4*)(ss + (size_t)sL * 8 + 4);
                float4 e0, e1;
                e0.x = __expf(lrelu(a0.x + sdv[0]));
                e0.y = __expf(lrelu(a0.y + sdv[1]));
                e0.z = __expf(lrelu(a0.z + sdv[2]));
                e0.w = __expf(lrelu(a0.w + sdv[3]));
                e1.x = __expf(lrelu(a1.x + sdv[4]));
                e1.y = __expf(lrelu(a1.y + sdv[5]));
                e1.z = __expf(lrelu(a1.z + sdv[6]));
                e1.w = __expf(lrelu(a1.w + sdv[7]));
                *(float4*)&sa[w][lane * 8] = e0;
                *(float4*)&sa[w][lane * 8 + 4] = e1;
            }
            __syncwarp();
#pragma unroll
            for (int j = 0; j < 32; j++) {
                if (j < m) {
                    int sj = __shfl_sync(0xffffffffu, sL, j);
                    float a = sa[w][j * 8 + hd];
                    zp += a;
                    float4 v = *(const float4*)(h1 + (size_t)sj * 256 + t * 128 + lane * 4);
                    acc.x = fmaf(a, v.x, acc.x);
                    acc.y = fmaf(a, v.y, acc.y);
                    acc.z = fmaf(a, v.z, acc.z);
                    acc.w = fmaf(a, v.w, acc.w);
                }
            }
            __syncwarp();
        }
        float inv = (zp > 0.f) ? 1.f / zp : 0.f;
        acc.x *= inv; acc.y *= inv; acc.z *= inv; acc.w *= inv;
    }
    accs[w][lane] = acc;
    __syncthreads();
    if (t == 0 && d < N_) {
        float4 a0 = accs[w][lane], a1 = accs[w + 1][lane];
        float4 bb0 = *(const float4*)(b1 + lane * 4);
        float4 bb1 = *(const float4*)(b1 + 128 + lane * 4);
        float4 r;
        r.x = eluf(0.5f * (a0.x + a1.x + bb0.x + bb1.x));
        r.y = eluf(0.5f * (a0.y + a1.y + bb0.y + bb1.y));
        r.z = eluf(0.5f * (a0.z + a1.z + bb0.z + bb1.z));
        r.w = eluf(0.5f * (a0.w + a1.w + bb0.w + bb1.w));
        *(float4*)(h1c + (size_t)d * 128 + lane * 4) = r;
#pragma unroll
        for (int c = 0; c < 16; c++) {
            float4 wv = *(const float4*)(ws + c * 128 + lane * 4);
            float p = r.x * wv.x + r.y * wv.y + r.z * wv.z + r.w * wv.w;
            p += __shfl_xor_sync(0xffffffffu, p, 16);
            p += __shfl_xor_sync(0xffffffffu, p, 8);
            p += __shfl_xor_sync(0xffffffffu, p, 4);
            p += __shfl_xor_sync(0xffffffffu, p, 2);
            p += __shfl_xor_sync(0xffffffffu, p, 1);
            float4 uv = *(const float4*)(wd + c * 128 + lane * 4);
            float q = r.x * uv.x + r.y * uv.y + r.z * uv.z + r.w * uv.w;
            q += __shfl_xor_sync(0xffffffffu, q, 16);
            q += __shfl_xor_sync(0xffffffffu, q, 8);
            q += __shfl_xor_sync(0xffffffffu, q, 4);
            q += __shfl_xor_sync(0xffffffffu, q, 2);
            q += __shfl_xor_sync(0xffffffffu, q, 1);
            if (lane == 0) {
                s2s[(c >> 3) * N_ * 8 + d * 8 + (c & 7)] = p;
                s2d[(c >> 3) * N_ * 8 + d * 8 + (c & 7)] = q;
            }
        }
    }
}

// ---------------- layer-2 aggregate: single pass, packed f32x2 FMAs ----------------
__global__ void __launch_bounds__(256) k_gat2(
    const int* __restrict__ offs, const int* __restrict__ cnt, const int* __restrict__ csr,
    const float* __restrict__ s2s, const float* __restrict__ s2d,
    const float* __restrict__ h1c, uint16_t* __restrict__ aggb)
{
    __shared__ float sa[8][256];
    int w = threadIdx.x >> 5, lane = threadIdx.x & 31;
    int d = blockIdx.x * 4 + (w >> 1);
    int t = w & 1;
    if (d >= N_) return;
    int beg = offs[t * N_ + d], n = cnt[t * N_ + d];
    const float* ss = s2s + (size_t)t * N_ * 8;
    const float4* sdp = (const float4*)(s2d + ((size_t)t * N_ + d) * 8);
    float4 sd0 = sdp[0], sd1 = sdp[1];
    float sdv[8] = {sd0.x, sd0.y, sd0.z, sd0.w, sd1.x, sd1.y, sd1.z, sd1.w};
    const int* cs = csr + (size_t)t * E_ + beg;
    uint64_t z2[4];
#pragma unroll
    for (int k = 0; k < 4; k++) z2[k] = pk2(0.f, 0.f);
    uint64_t acc2[4][4];   // [component][head-pair]
#pragma unroll
    for (int cc = 0; cc < 4; cc++)
#pragma unroll
        for (int hp = 0; hp < 4; hp++) acc2[cc][hp] = pk2(0.f, 0.f);

    for (int c0 = 0; c0 < n; c0 += 32) {
        int m = n - c0; if (m > 32) m = 32;
        int sL = 0;
        if (lane < m) {
            sL = cs[c0 + lane];
            float4 a0 = *(const float4*)(ss + (size_t)sL * 8);
            float4 a1 = *(const float4*)(ss + (size_t)sL * 8 + 4);
            float4 e0, e1;
            e0.x = __expf(lrelu(a0.x + sdv[0]));
            e0.y = __expf(lrelu(a0.y + sdv[1]));
            e0.z = __expf(lrelu(a0.z + sdv[2]));
            e0.w = __expf(lrelu(a0.w + sdv[3]));
            e1.x = __expf(lrelu(a1.x + sdv[4]));
            e1.y = __expf(lrelu(a1.y + sdv[5]));
            e1.z = __expf(lrelu(a1.z + sdv[6]));
            e1.w = __expf(lrelu(a1.w + sdv[7]));
            *(float4*)&sa[w][lane * 8] = e0;
            *(float4*)&sa[w][lane * 8 + 4] = e1;
        }
        __syncwarp();
#pragma unroll
        for (int j = 0; j < 32; j++) {
            if (j < m) {
                int sj = __shfl_sync(0xffffffffu, sL, j);
                uint64_t a01 = *(const uint64_t*)&sa[w][j * 8];
                uint64_t a23 = *(const uint64_t*)&sa[w][j * 8 + 2];
                uint64_t a45 = *(const uint64_t*)&sa[w][j * 8 + 4];
                uint64_t a67 = *(const uint64_t*)&sa[w][j * 8 + 6];
                z2[0] = add2(z2[0], a01);
                z2[1] = add2(z2[1], a23);
                z2[2] = add2(z2[2], a45);
                z2[3] = add2(z2[3], a67);
                float4 v = *(const float4*)(h1c + (size_t)sj * 128 + lane * 4);
                uint64_t vb[4];
                vb[0] = pk2(v.x, v.x); vb[1] = pk2(v.y, v.y);
                vb[2] = pk2(v.z, v.z); vb[3] = pk2(v.w, v.w);
#pragma unroll
                for (int cc = 0; cc < 4; cc++) {
                    acc2[cc][0] = fma2(a01, vb[cc], acc2[cc][0]);
                    acc2[cc][1] = fma2(a23, vb[cc], acc2[cc][1]);
                    acc2[cc][2] = fma2(a45, vb[cc], acc2[cc][2]);
                    acc2[cc][3] = fma2(a67, vb[cc], acc2[cc][3]);
                }
            }
        }
        __syncwarp();
    }
    float z8[8];
#pragma unroll
    for (int hp = 0; hp < 4; hp++) upk2(z2[hp], z8[2 * hp], z8[2 * hp + 1]);
#pragma unroll
    for (int h = 0; h < 8; h++) {
        float inv = (z8[h] > 0.f) ? 1.f / z8[h] : 0.f;
        float ax, ay, az, aw, dummy;
        int hp = h >> 1;
        if ((h & 1) == 0) {
            upk2(acc2[0][hp], ax, dummy);
            upk2(acc2[1][hp], ay, dummy);
            upk2(acc2[2][hp], az, dummy);
            upk2(acc2[3][hp], aw, dummy);
        } else {
            upk2(acc2[0][hp], dummy, ax);
            upk2(acc2[1][hp], dummy, ay);
            upk2(acc2[2][hp], dummy, az);
            upk2(acc2[3][hp], dummy, aw);
        }
        ax *= inv; ay *= inv; az *= inv; aw *= inv;
        uint16_t h0, l0, h1v, l1, h2, l2, h3, l3;
        hl_split(ax, h0, l0); hl_split(ay, h1v, l1);
        hl_split(az, h2, l2); hl_split(aw, h3, l3);
        uint2 hi, lo;
        hi.x = (uint32_t)h0 | ((uint32_t)h1v << 16);
        hi.y = (uint32_t)h2 | ((uint32_t)h3 << 16);
        lo.x = (uint32_t)l0 | ((uint32_t)l1 << 16);
        lo.y = (uint32_t)l2 | ((uint32_t)l3 << 16);
        int k = t * 1024 + h * 128 + lane * 4;
        *(uint2*)(aggb + (size_t)d * 4096 + k) = hi;
        *(uint2*)(aggb + (size_t)d * 4096 + 2048 + k) = lo;
    }
}

// ---------------- classifier (sums 4 split-K parts, bias + ELU fused) ----------------
__global__ void k_classifier(const float* __restrict__ h, const float* __restrict__ bc,
                             const float* __restrict__ Wc1, const float* __restrict__ bc1,
                             const float* __restrict__ Wc2, const float* __restrict__ bc2,
                             float* __restrict__ out)
{
    int wid = (blockIdx.x * blockDim.x + threadIdx.x) >> 5;
    int lane = threadIdx.x & 31;
    if (wid >= N_) return;
    const float* hr0 = h + (size_t)wid * 64;
    const float* hr1 = hr0 + (size_t)N_ * 64;
    const float* hr2 = hr1 + (size_t)N_ * 64;
    const float* hr3 = hr2 + (size_t)N_ * 64;
    float acc = bc1[lane];
#pragma unroll
    for (int c = 0; c < 64; c++) {
        float hv = eluf(__ldg(hr0 + c) + __ldg(hr1 + c) + __ldg(hr2 + c) + __ldg(hr3 + c)
                        + __ldg(bc + c));
        acc = fmaf(hv, Wc1[c * 32 + lane], acc);
    }
    acc = fmaxf(acc, 0.f);
    float p0 = acc * Wc2[lane * 2];
    float p1 = acc * Wc2[lane * 2 + 1];
#pragma unroll
    for (int o = 16; o >= 1; o >>= 1) {
        p0 += __shfl_xor_sync(0xffffffffu, p0, o);
        p1 += __shfl_xor_sync(0xffffffffu, p1, o);
    }
    if (lane == 0) {
        out[wid * 2 + 0] = p0 + bc2[0];
        out[wid * 2 + 1] = p1 + bc2[1];
    }
}

// ---------------- launch ----------------
extern "C" void kernel_launch(void* const* d_in, const int* in_sizes, int n_in,
                              void* d_out, int out_size)
{
    const float* x    = (const float*)d_in[0];
    const void*  eia  = d_in[1];
    const void*  eib  = d_in[2];
    const float* W1   = (const float*)d_in[3];
    const float* a1s  = (const float*)d_in[4];
    const float* a1d  = (const float*)d_in[5];
    const float* b1   = (const float*)d_in[6];
    const float* W2   = (const float*)d_in[7];
    const float* a2s  = (const float*)d_in[8];
    const float* a2d  = (const float*)d_in[9];
    const float* b2   = (const float*)d_in[10];
    const float* Wc1  = (const float*)d_in[11];
    const float* bc1  = (const float*)d_in[12];
    const float* Wc2  = (const float*)d_in[13];
    const float* bc2  = (const float*)d_in[14];
    float* out = (float*)d_out;

    void* basev = nullptr;
    cudaGetSymbolAddress(&basev, g_scratch);
    unsigned char* base = (unsigned char*)basev;

    int*      p_csr  = (int*)(base + O_CSR);
    int*      p_cnt  = (int*)(base + O_CNT);
    int*      p_off  = (int*)(base + O_OFF);
    int*      p_cur  = (int*)(base + O_CUR);
    uint16_t* p_xb   = (uint16_t*)(base + O_XB);
    float*    p_h1   = (float*)(base + O_H1);
    float*    p_s1s  = (float*)(base + O_S1S);
    float*    p_s1d  = (float*)(base + O_S1D);
    float*    p_h1c  = (float*)(base + O_H1C);
    float*    p_s2s  = (float*)(base + O_S2S);
    float*    p_s2d  = (float*)(base + O_S2D);
    float*    p_ws   = (float*)(base + O_WS);
    float*    p_wd   = (float*)(base + O_WD);
    float*    p_bc   = (float*)(base + O_BC);
    uint16_t* p_wt1  = (uint16_t*)(base + O_WT1);
    uint16_t* p_wt2  = (uint16_t*)(base + O_WT2);
    uint16_t* p_aggb = (uint16_t*)(base + O_AGGB);
    int*      p_src  = (int*)(base + O_SRC);
    int*      p_dst  = (int*)(base + O_DST);
    float*    p_h2p  = (float*)(base + O_H2P);

    cudaFuncSetAttribute(k_mmagemm<4, 512, 512, 1>,
                         cudaFuncAttributeMaxDynamicSharedMemorySize, 73728);
    cudaFuncSetAttribute(k_mmagemm<32, 4096, 4096, 0>,
                         cudaFuncAttributeMaxDynamicSharedMemorySize, 73728);

    // side stream + fork/join events (created per call; capture-safe, no device allocs)
    cudaStream_t s2;
    cudaStreamCreateWithFlags(&s2, cudaStreamNonBlocking);
    cudaEvent_t e1, e2;
    cudaEventCreateWithFlags(&e1, cudaEventDisableTiming);
    cudaEventCreateWithFlags(&e2, cudaEventDisableTiming);

    // 1: prep (weights + cnt zero + x->bf16) on main stream
    const int PREP_N = 240768 + N_ * 64;
    k_prep<<<(PREP_N + 255) / 256, 256>>>(W2, a2s, a2d, b2, W1, x, p_wt1, p_wt2,
                                          p_ws, p_wd, p_bc, p_cnt, p_xb);

    // fork: CSR-build chain on s2 (depends only on prep's cnt zeroing)
    cudaEventRecord(e1, 0);
    cudaStreamWaitEvent(s2, e1, 0);
    k_cvt<<<dim3((E_ + 255) / 256, 2), 256, 0, s2>>>(eia, eib, p_src, p_dst, p_cnt);
    k_scan<<<2, 1024, 0, s2>>>(p_cnt, p_off, p_cur);
    k_scatter<<<(2 * E_ + 255) / 256, 256, 0, s2>>>(p_src, p_dst, p_cur, p_csr);
    cudaEventRecord(e2, s2);

    // main stream: layer-1 GEMM with fused attention scores (overlaps CSR chain)
    k_mmagemm<4, 512, 512, 1><<<dim3(157, 4, 1), 256, 73728>>>(
        p_xb, p_wt1, p_h1, N_, 256, 0, a1s, a1d, p_s1s, p_s1d);

    // join before gat1 (needs csr + scores)
    cudaStreamWaitEvent(0, e2, 0);

    // gat1 (h1c + layer-2 scores) -> gat2
    k_gat1<<<(N_ + 3) / 4, 256>>>(p_off, p_cnt, p_csr, p_s1s, p_s1d, p_h1, b1,
                                  p_h1c, p_ws, p_wd, p_s2s, p_s2d);
    k_gat2<<<(N_ + 3) / 4, 256>>>(p_off, p_cnt, p_csr, p_s2s, p_s2d, p_h1c, p_aggb);

    // layer-2 GEMM, split-K=4
    k_mmagemm<32, 4096, 4096, 0><<<dim3(157, 1, 4), 256, 73728>>>(
        p_aggb, p_wt2, p_h2p, N_, 64, (size_t)N_ * 64,
        nullptr, nullptr, nullptr, nullptr);

    // classifier
    k_classifier<<<(N_ * 32 + 255) / 256, 256>>>(p_h2p, p_bc, Wc1, bc1, Wc2, bc2, out);
}